// round 5
// baseline (speedup 1.0000x reference)
#include <cuda_runtime.h>
#include <cuda_bf16.h>
#include <math_constants.h>
#include <stdint.h>

#define NROWS 16384
#define DIMS  256
#define NEMB  8192

// Output layout (float32, reference return order, flattened+concatenated)
#define OFF_Q    0
#define OFF_DIFF 4194304
#define OFF_IND  4194305
#define OFF_EMB  4210689
#define OFF_NCS  6307841
#define OFF_AVG  6316033

// Scratch (no cudaMalloc allowed)
__device__ float          g_enorm[NEMB];
__device__ int            g_arg4[4 * NROWS];       // top-4 candidates per row
__device__ int            g_count[NEMB];
__device__ float          g_n;
__device__ __nv_bfloat16  g_zhi[NROWS * DIMS];     // [row][k] bf16
__device__ __nv_bfloat16  g_ehi[NEMB * DIMS];      // [code][k] bf16 (transposed)
__device__ float          g_eT[NEMB * DIMS];       // [code][k] fp32 (transposed)

// ---------------------------------------------------------------------------
// PTX helpers — baseline sm_80+ features only (target is compute_103, no 'a').
// ---------------------------------------------------------------------------
__device__ __forceinline__ uint32_t smem_u32(const void* p) {
    uint32_t a;
    asm("{ .reg .u64 t; cvta.to.shared.u64 t, %1; cvt.u32.u64 %0, t; }" : "=r"(a) : "l"(p));
    return a;
}
__device__ __forceinline__ void cp_async16(uint32_t s, const void* g) {
    asm volatile("cp.async.ca.shared.global [%0], [%1], 16;" :: "r"(s), "l"(g));
}
#define CP_COMMIT() asm volatile("cp.async.commit_group;")
#define CP_WAIT0()  asm volatile("cp.async.wait_group 0;")
#define CP_WAIT1()  asm volatile("cp.async.wait_group 1;")

__device__ __forceinline__ void ldsm_x4(uint32_t* r, uint32_t a) {
    asm volatile("ldmatrix.sync.aligned.m8n8.x4.shared.b16 {%0,%1,%2,%3}, [%4];"
                 : "=r"(r[0]), "=r"(r[1]), "=r"(r[2]), "=r"(r[3]) : "r"(a));
}
__device__ __forceinline__ void ldsm_x2(uint32_t* r, uint32_t a) {
    asm volatile("ldmatrix.sync.aligned.m8n8.x2.shared.b16 {%0,%1}, [%2];"
                 : "=r"(r[0]), "=r"(r[1]) : "r"(a));
}
__device__ __forceinline__ void mma16816(float* d, const uint32_t* a, const uint32_t* b) {
    asm volatile("mma.sync.aligned.m16n8k16.row.col.f32.bf16.bf16.f32 "
                 "{%0,%1,%2,%3}, {%4,%5,%6,%7}, {%8,%9}, {%0,%1,%2,%3};"
                 : "+f"(d[0]), "+f"(d[1]), "+f"(d[2]), "+f"(d[3])
                 : "r"(a[0]), "r"(a[1]), "r"(a[2]), "r"(a[3]), "r"(b[0]), "r"(b[1]));
}

// sorted top-4 insert (ascending); common case = 1 compare
__device__ __forceinline__ void t4_insert(float (&v)[4], int (&j)[4], float d, int c) {
    if (d < v[3]) {
        if (d < v[1]) {
            v[3] = v[2]; j[3] = j[2]; v[2] = v[1]; j[2] = j[1];
            if (d < v[0]) { v[1] = v[0]; j[1] = j[0]; v[0] = d; j[0] = c; }
            else          { v[1] = d; j[1] = c; }
        } else {
            if (d < v[2]) { v[3] = v[2]; j[3] = j[2]; v[2] = d; j[2] = c; }
            else          { v[3] = d; j[3] = c; }
        }
    }
}

// merge sorted-4 'w' into sorted-4 'v' keeping smallest 4 (end-of-kernel only)
__device__ __forceinline__ void t4_merge(float (&v)[4], int (&j)[4],
                                         const float (&w)[4], const int (&iw)[4]) {
    float rv[4]; int rj[4];
    int a = 0, b = 0;
#pragma unroll
    for (int o = 0; o < 4; o++) {
        bool t = (w[b] < v[a]);
        rv[o] = t ? w[b] : v[a];
        rj[o] = t ? iw[b] : j[a];
        if (t) b = (b < 3) ? b + 1 : 3; else a = (a < 3) ? a + 1 : 3;
    }
#pragma unroll
    for (int o = 0; o < 4; o++) { v[o] = rv[o]; j[o] = rj[o]; }
}

// ---------------------------------------------------------------------------
// A: init — zero counters/enorm/diff/n; seed new_embedding_avg with 0.99*avg
// ---------------------------------------------------------------------------
__global__ void k_init(const float* __restrict__ eavg, float* __restrict__ out) {
    int i = blockIdx.x * blockDim.x + threadIdx.x;
    if (i < DIMS * NEMB) out[OFF_AVG + i] = 0.99f * eavg[i];
    if (i < NEMB) { g_count[i] = 0; g_enorm[i] = 0.0f; }
    if (i == 0) { g_n = 0.0f; out[OFF_DIFF] = 0.0f; }
}

// ---------------------------------------------------------------------------
// B: convert z to bf16 ([row][k] layout)
// ---------------------------------------------------------------------------
__global__ void k_conv_z(const float* __restrict__ z) {
    int i = blockIdx.x * blockDim.x + threadIdx.x;
    g_zhi[i] = __float2bfloat16(z[i]);
}

// ---------------------------------------------------------------------------
// B2: fused E prep: transpose to [j][k] (fp32 + bf16) and accumulate enorm.
//     32x32 tiles; block (32,8). Requires g_enorm pre-zeroed (k_init).
// ---------------------------------------------------------------------------
__global__ void k_prep_e(const float* __restrict__ E) {
    __shared__ float t[32][33];
    int j0 = blockIdx.x * 32, k0 = blockIdx.y * 32;
    int tx = threadIdx.x, ty = threadIdx.y;
#pragma unroll
    for (int s = 0; s < 32; s += 8)
        t[ty + s][tx] = E[(size_t)(k0 + ty + s) * NEMB + j0 + tx];
    __syncthreads();
#pragma unroll
    for (int s = 0; s < 32; s += 8) {
        float x = t[tx][ty + s];                  // j = j0+ty+s, k = k0+tx
        size_t o = (size_t)(j0 + ty + s) * DIMS + k0 + tx;
        g_eT[o]  = x;
        g_ehi[o] = __float2bfloat16(x);
        float p = x * x;
#pragma unroll
        for (int w = 16; w; w >>= 1) p += __shfl_xor_sync(0xffffffffu, p, w);
        if (tx == 0) atomicAdd(&g_enorm[j0 + ty + s], p);
    }
}

// ---------------------------------------------------------------------------
// C: single-bf16 mma.sync GEMM + fused per-lane top-4 argmin.
//    CTA: 128 rows, 8 warps (2m x 4n), warp tile 64x32.
//    A (K=256) resident in smem; B double-buffered, 64-k chunks.
//    16B-chunk XOR swizzle: chunk c of row r stored at c ^ (r&7).
// ---------------------------------------------------------------------------
#define SM_A     0          // 4 planes of 16 KB: [kc]
#define SM_B     65536      // 2 planes: [buf]
#define SM_RED   65536      // reused for final top-4 merge (16 KB)
#define SMEM_TOTAL 98304

__global__ __launch_bounds__(256) void k_argmin_mma() {
    extern __shared__ char smem[];
    const uint32_t sb = smem_u32(smem);
    const int tid = threadIdx.x, wid = tid >> 5, l = tid & 31;
    const int wm = wid >> 2, wn = wid & 3;
    const int row0 = blockIdx.x * 128;

    // stage resident A (4 k-chunks): 4096 x 16B (group 0)
    {
#pragma unroll
        for (int t = 0; t < 16; t++) {
            int i = tid + t * 256;
            int kc = i >> 10, r = (i >> 3) & 127, c = i & 7;
            const __nv_bfloat16* g = g_zhi + (size_t)(row0 + r) * DIMS + kc * 64 + c * 8;
            cp_async16(sb + SM_A + kc * 16384 + r * 128 + ((c ^ (r & 7)) << 4), g);
        }
        CP_COMMIT();
    }

    auto stageB = [&](int q) {
        const int jt = q >> 2, kc = q & 3, buf = q & 1;
#pragma unroll
        for (int t = 0; t < 4; t++) {
            int i = tid + t * 256;
            int r = (i >> 3) & 127, c = i & 7;
            const __nv_bfloat16* g = g_ehi + (size_t)(jt * 128 + r) * DIMS + kc * 64 + c * 8;
            cp_async16(sb + SM_B + buf * 16384 + r * 128 + ((c ^ (r & 7)) << 4), g);
        }
        CP_COMMIT();
    };
    stageB(0);

    const int arow_base = wm * 64 + (l & 15);   // + mt*16
    const int ach = l >> 4;
    const int brow_base = wn * 32 + (l & 7);    // + nt*8
    const int bch = (l >> 3) & 1;

    float acc[4][4][4];
    float sv[8][4]; int sj[8][4];               // per-lane top-4 per row-slot
#pragma unroll
    for (int s = 0; s < 8; s++)
#pragma unroll
        for (int e = 0; e < 4; e++) { sv[s][e] = CUDART_INF_F; sj[s][e] = 0; }

    for (int q = 0; q < 256; q++) {
        const int jt = q >> 2, kc = q & 3, buf = q & 1;
        if (q + 1 < 256) { stageB(q + 1); CP_WAIT1(); } else { CP_WAIT0(); }
        __syncthreads();

        if (kc == 0) {
#pragma unroll
            for (int mt = 0; mt < 4; mt++)
#pragma unroll
                for (int nt = 0; nt < 4; nt++)
#pragma unroll
                    for (int e = 0; e < 4; e++) acc[mt][nt][e] = 0.0f;
        }

#pragma unroll
        for (int ks = 0; ks < 4; ks++) {
            const int kb = ks * 2;
            uint32_t bfr[4][2];
#pragma unroll
            for (int nt = 0; nt < 4; nt++) {
                int row = brow_base + nt * 8;
                ldsm_x2(bfr[nt], sb + SM_B + buf * 16384 + row * 128
                                 + (((kb + bch) ^ (row & 7)) << 4));
            }
#pragma unroll
            for (int mt = 0; mt < 4; mt++) {
                int row = arow_base + mt * 16;
                uint32_t afr[4];
                ldsm_x4(afr, sb + SM_A + kc * 16384 + row * 128
                             + (((kb + ach) ^ (row & 7)) << 4));
#pragma unroll
                for (int nt = 0; nt < 4; nt++)
                    mma16816(acc[mt][nt], afr, bfr[nt]);
            }
        }
        __syncthreads();

        if (kc == 3) {
#pragma unroll
            for (int nt = 0; nt < 4; nt++) {
                int cbase = jt * 128 + wn * 32 + nt * 8 + 2 * (l & 3);
                float2 en = __ldg((const float2*)&g_enorm[cbase]);
#pragma unroll
                for (int mt = 0; mt < 4; mt++) {
                    float d0 = fmaf(-2.0f, acc[mt][nt][0], en.x);
                    float d1 = fmaf(-2.0f, acc[mt][nt][1], en.y);
                    float d2 = fmaf(-2.0f, acc[mt][nt][2], en.x);
                    float d3 = fmaf(-2.0f, acc[mt][nt][3], en.y);
                    t4_insert(sv[mt * 2],     sj[mt * 2],     d0, cbase);
                    t4_insert(sv[mt * 2],     sj[mt * 2],     d1, cbase + 1);
                    t4_insert(sv[mt * 2 + 1], sj[mt * 2 + 1], d2, cbase);
                    t4_insert(sv[mt * 2 + 1], sj[mt * 2 + 1], d3, cbase + 1);
                }
            }
        }
    }

    // cross-lane merge (4 lanes per row), stash per-warp top-4 in smem
    __syncthreads();
#pragma unroll
    for (int mt = 0; mt < 4; mt++) {
#pragma unroll
        for (int h = 0; h < 2; h++) {
            int s = mt * 2 + h;
#pragma unroll
            for (int o = 1; o <= 2; o <<= 1) {
                float wv[4]; int wj[4];
#pragma unroll
                for (int e = 0; e < 4; e++) {
                    wv[e] = __shfl_xor_sync(0xffffffffu, sv[s][e], o);
                    wj[e] = __shfl_xor_sync(0xffffffffu, sj[s][e], o);
                }
                t4_merge(sv[s], sj[s], wv, wj);
            }
            if ((l & 3) == 0) {
                int rl = wm * 64 + mt * 16 + h * 8 + (l >> 2);
                float4* dst = (float4*)(smem + SM_RED) + (rl * 4 + wn) * 2;
                dst[0] = make_float4(sv[s][0], sv[s][1], sv[s][2], sv[s][3]);
                dst[1] = make_float4(__int_as_float(sj[s][0]), __int_as_float(sj[s][1]),
                                     __int_as_float(sj[s][2]), __int_as_float(sj[s][3]));
            }
        }
    }
    __syncthreads();

    // merge the 4 n-warps per row; write final top-4
    if (tid < 128) {
        const float4* src = (const float4*)(smem + SM_RED) + tid * 8;
        float v[4]; int j[4];
        float4 a = src[0], b = src[1];
        v[0] = a.x; v[1] = a.y; v[2] = a.z; v[3] = a.w;
        j[0] = __float_as_int(b.x); j[1] = __float_as_int(b.y);
        j[2] = __float_as_int(b.z); j[3] = __float_as_int(b.w);
#pragma unroll
        for (int w = 1; w < 4; w++) {
            float4 c = src[w * 2], d = src[w * 2 + 1];
            float wv[4] = {c.x, c.y, c.z, c.w};
            int   wj[4] = {__float_as_int(d.x), __float_as_int(d.y),
                           __float_as_int(d.z), __float_as_int(d.w)};
            t4_merge(v, j, wv, wj);
        }
        int row = row0 + tid;
        *(int4*)&g_arg4[4 * row] = make_int4(j[0], j[1], j[2], j[3]);
    }
}

// ---------------------------------------------------------------------------
// D: exact fp32 rescore of top-4 (coalesced via g_eT), then gather quantize,
//    diff, segment sums. One warp per row.
// ---------------------------------------------------------------------------
__global__ __launch_bounds__(256) void k_gather(
    const float* __restrict__ z, float* __restrict__ out)
{
    __shared__ float warpsum[8];
    const int warp = threadIdx.x >> 5, lane = threadIdx.x & 31;
    const int r = blockIdx.x * 8 + warp;
    const int4 cand = *(const int4*)&g_arg4[4 * r];
    const int cj[4] = {cand.x, cand.y, cand.z, cand.w};

    float zv[8];
#pragma unroll
    for (int it = 0; it < 8; it++) zv[it] = z[(size_t)r * DIMS + lane + it * 32];

    float dot[4] = {0.0f, 0.0f, 0.0f, 0.0f};
#pragma unroll
    for (int c = 0; c < 4; c++) {
        const float* e = g_eT + (size_t)cj[c] * DIMS;
#pragma unroll
        for (int it = 0; it < 8; it++)
            dot[c] = fmaf(zv[it], e[lane + it * 32], dot[c]);
    }
#pragma unroll
    for (int c = 0; c < 4; c++)
#pragma unroll
        for (int o = 16; o; o >>= 1) dot[c] += __shfl_xor_sync(0xffffffffu, dot[c], o);

    int bj = cj[0];
    float bd = fmaf(-2.0f, dot[0], g_enorm[cj[0]]);
#pragma unroll
    for (int c = 1; c < 4; c++) {
        float d = fmaf(-2.0f, dot[c], g_enorm[cj[c]]);
        if (d < bd || (d == bd && cj[c] < bj)) { bd = d; bj = cj[c]; }
    }

    const float* eb = g_eT + (size_t)bj * DIMS;
    float ss = 0.0f;
#pragma unroll
    for (int it = 0; it < 8; it++) {
        int d = lane + it * 32;
        float e = eb[d];
        float qd = e - zv[it];
        out[OFF_Q + (size_t)r * DIMS + d] = zv[it] + qd;
        ss = fmaf(qd, qd, ss);
        atomicAdd(&out[OFF_AVG + (size_t)d * NEMB + bj], 0.01f * zv[it]);
    }
    if (lane == 0) {
        atomicAdd(&g_count[bj], 1);
        out[OFF_IND + r] = (float)bj;
    }
#pragma unroll
    for (int o = 16; o; o >>= 1) ss += __shfl_down_sync(0xffffffffu, ss, o);
    if (lane == 0) warpsum[warp] = ss;
    __syncthreads();
    if (threadIdx.x == 0) {
        float t = 0.0f;
#pragma unroll
        for (int w = 0; w < 8; w++) t += warpsum[w];
        atomicAdd(&out[OFF_DIFF], t);
    }
}

// ---------------------------------------------------------------------------
// E: new_cluster_size + global n reduction
// ---------------------------------------------------------------------------
__global__ void k_ncs(const float* __restrict__ cs, float* __restrict__ out) {
    __shared__ float sh[256];
    int j = blockIdx.x * 256 + threadIdx.x;
    float v = cs[j] * 0.99f + 0.01f * (float)g_count[j];
    out[OFF_NCS + j] = v;
    sh[threadIdx.x] = v;
    __syncthreads();
    for (int s = 128; s; s >>= 1) {
        if (threadIdx.x < s) sh[threadIdx.x] += sh[threadIdx.x + s];
        __syncthreads();
    }
    if (threadIdx.x == 0) atomicAdd(&g_n, sh[0]);
}

// ---------------------------------------------------------------------------
// F: new_embedding = avg / smoothed; finalize diff mean
// ---------------------------------------------------------------------------
__global__ void k_final(float* __restrict__ out) {
    int i = blockIdx.x * blockDim.x + threadIdx.x;
    if (i == 0) out[OFF_DIFF] *= (1.0f / 4194304.0f);
    if (i >= DIMS * NEMB) return;
    float n = g_n;
    int j = i & (NEMB - 1);
    float ncs = out[OFF_NCS + j];
    float smoothed = (ncs + 1e-5f) / (n + (float)NEMB * 1e-5f) * n;
    out[OFF_EMB + i] = out[OFF_AVG + i] / smoothed;
}

// ---------------------------------------------------------------------------
extern "C" void kernel_launch(void* const* d_in, const int* in_sizes, int n_in,
                              void* d_out, int out_size) {
    const float* z    = (const float*)d_in[0];   // [16,32,32,256]
    const float* E    = (const float*)d_in[1];   // [256, 8192]
    const float* cs   = (const float*)d_in[2];   // [8192]
    const float* eavg = (const float*)d_in[3];   // [256, 8192]
    float* out = (float*)d_out;

    static int cfg_done = 0;
    if (!cfg_done) {
        cudaFuncSetAttribute(k_argmin_mma,
                             cudaFuncAttributeMaxDynamicSharedMemorySize, SMEM_TOTAL);
        cfg_done = 1;
    }

    k_init   <<<(DIMS * NEMB + 255) / 256, 256>>>(eavg, out);
    k_conv_z <<<NROWS * DIMS / 256, 256>>>(z);
    {
        dim3 g(NEMB / 32, DIMS / 32), b(32, 8);
        k_prep_e<<<g, b>>>(E);
    }
    k_argmin_mma<<<NROWS / 128, 256, SMEM_TOTAL>>>();
    k_gather <<<NROWS / 8, 256>>>(z, out);
    k_ncs    <<<NEMB / 256, 256>>>(cs, out);
    k_final  <<<(DIMS * NEMB + 255) / 256, 256>>>(out);
}

// round 6
// speedup vs baseline: 1.7977x; 1.7977x over previous
#include <cuda_runtime.h>
#include <cuda_bf16.h>
#include <math_constants.h>
#include <stdint.h>

#define NROWS 16384
#define DIMS  256
#define NEMB  8192

// Output layout (float32, reference return order, flattened+concatenated)
#define OFF_Q    0
#define OFF_DIFF 4194304
#define OFF_IND  4194305
#define OFF_EMB  4210689
#define OFF_NCS  6307841
#define OFF_AVG  6316033

// Scratch (no cudaMalloc allowed)
__device__ float          g_enorm[NEMB];
__device__ int            g_arg4[4 * NROWS];       // top-4 candidates per row
__device__ int            g_count[NEMB];
__device__ float          g_n;
__device__ __nv_bfloat16  g_zhi[NROWS * DIMS];     // [row][k] bf16
__device__ __nv_bfloat16  g_ehi[NEMB * DIMS];      // [code][k] bf16 (transposed)
__device__ float          g_eT[NEMB * DIMS];       // [code][k] fp32 (transposed)

// ---------------------------------------------------------------------------
// PTX helpers — baseline sm_80+ features only (target is compute_103, no 'a').
// ---------------------------------------------------------------------------
__device__ __forceinline__ uint32_t smem_u32(const void* p) {
    uint32_t a;
    asm("{ .reg .u64 t; cvta.to.shared.u64 t, %1; cvt.u32.u64 %0, t; }" : "=r"(a) : "l"(p));
    return a;
}
__device__ __forceinline__ void cp_async16(uint32_t s, const void* g) {
    asm volatile("cp.async.ca.shared.global [%0], [%1], 16;" :: "r"(s), "l"(g));
}
#define CP_COMMIT() asm volatile("cp.async.commit_group;")
#define CP_WAIT0()  asm volatile("cp.async.wait_group 0;")
#define CP_WAIT1()  asm volatile("cp.async.wait_group 1;")

__device__ __forceinline__ void ldsm_x4(uint32_t* r, uint32_t a) {
    asm volatile("ldmatrix.sync.aligned.m8n8.x4.shared.b16 {%0,%1,%2,%3}, [%4];"
                 : "=r"(r[0]), "=r"(r[1]), "=r"(r[2]), "=r"(r[3]) : "r"(a));
}
__device__ __forceinline__ void ldsm_x2(uint32_t* r, uint32_t a) {
    asm volatile("ldmatrix.sync.aligned.m8n8.x2.shared.b16 {%0,%1}, [%2];"
                 : "=r"(r[0]), "=r"(r[1]) : "r"(a));
}
__device__ __forceinline__ void mma16816(float* d, const uint32_t* a, const uint32_t* b) {
    asm volatile("mma.sync.aligned.m16n8k16.row.col.f32.bf16.bf16.f32 "
                 "{%0,%1,%2,%3}, {%4,%5,%6,%7}, {%8,%9}, {%0,%1,%2,%3};"
                 : "+f"(d[0]), "+f"(d[1]), "+f"(d[2]), "+f"(d[3])
                 : "r"(a[0]), "r"(a[1]), "r"(a[2]), "r"(a[3]), "r"(b[0]), "r"(b[1]));
}

// sorted top-4 insert (ascending); common case = 1 compare
__device__ __forceinline__ void t4_insert(float (&v)[4], int (&j)[4], float d, int c) {
    if (d < v[3]) {
        if (d < v[1]) {
            v[3] = v[2]; j[3] = j[2]; v[2] = v[1]; j[2] = j[1];
            if (d < v[0]) { v[1] = v[0]; j[1] = j[0]; v[0] = d; j[0] = c; }
            else          { v[1] = d; j[1] = c; }
        } else {
            if (d < v[2]) { v[3] = v[2]; j[3] = j[2]; v[2] = d; j[2] = c; }
            else          { v[3] = d; j[3] = c; }
        }
    }
}

// merge sorted-4 'w' into sorted-4 'v' keeping smallest 4 (end-of-kernel only)
__device__ __forceinline__ void t4_merge(float (&v)[4], int (&j)[4],
                                         const float (&w)[4], const int (&iw)[4]) {
    float rv[4]; int rj[4];
    int a = 0, b = 0;
#pragma unroll
    for (int o = 0; o < 4; o++) {
        bool t = (w[b] < v[a]);
        rv[o] = t ? w[b] : v[a];
        rj[o] = t ? iw[b] : j[a];
        if (t) b = (b < 3) ? b + 1 : 3; else a = (a < 3) ? a + 1 : 3;
    }
#pragma unroll
    for (int o = 0; o < 4; o++) { v[o] = rv[o]; j[o] = rj[o]; }
}

// ---------------------------------------------------------------------------
// A: init — zero counters/enorm/diff/n; seed new_embedding_avg with 0.99*avg
// ---------------------------------------------------------------------------
__global__ void k_init(const float* __restrict__ eavg, float* __restrict__ out) {
    int i = blockIdx.x * blockDim.x + threadIdx.x;
    if (i < DIMS * NEMB) out[OFF_AVG + i] = 0.99f * eavg[i];
    if (i < NEMB) { g_count[i] = 0; g_enorm[i] = 0.0f; }
    if (i == 0) { g_n = 0.0f; out[OFF_DIFF] = 0.0f; }
}

// ---------------------------------------------------------------------------
// B: convert z to bf16 ([row][k] layout)
// ---------------------------------------------------------------------------
__global__ void k_conv_z(const float* __restrict__ z) {
    int i = blockIdx.x * blockDim.x + threadIdx.x;
    g_zhi[i] = __float2bfloat16(z[i]);
}

// ---------------------------------------------------------------------------
// B2: fused E prep: transpose to [j][k] (fp32 + bf16) and accumulate enorm.
//     32x32 tiles; block (32,8). Requires g_enorm pre-zeroed (k_init).
// ---------------------------------------------------------------------------
__global__ void k_prep_e(const float* __restrict__ E) {
    __shared__ float t[32][33];
    int j0 = blockIdx.x * 32, k0 = blockIdx.y * 32;
    int tx = threadIdx.x, ty = threadIdx.y;
#pragma unroll
    for (int s = 0; s < 32; s += 8)
        t[ty + s][tx] = E[(size_t)(k0 + ty + s) * NEMB + j0 + tx];
    __syncthreads();
#pragma unroll
    for (int s = 0; s < 32; s += 8) {
        float x = t[tx][ty + s];                  // j = j0+ty+s, k = k0+tx
        size_t o = (size_t)(j0 + ty + s) * DIMS + k0 + tx;
        g_eT[o]  = x;
        g_ehi[o] = __float2bfloat16(x);
        float p = x * x;
#pragma unroll
        for (int w = 16; w; w >>= 1) p += __shfl_xor_sync(0xffffffffu, p, w);
        if (tx == 0) atomicAdd(&g_enorm[j0 + ty + s], p);
    }
}

// ---------------------------------------------------------------------------
// C: single-bf16 mma.sync GEMM + fused per-lane top-4 argmin.
//    CTA: 128 rows, 8 warps (2m x 4n), warp tile 64x32.
//    A (K=256) resident in smem; B double-buffered, 64-k chunks.
//    16B-chunk XOR swizzle: chunk c of row r stored at c ^ (r&7).
//    __launch_bounds__(256, 1): allow full register budget (R5 spilled at 128-reg
//    2-CTA target -> LDL/STL in the inner MMA loop -> 2.8ms).
// ---------------------------------------------------------------------------
#define SM_A     0          // 4 planes of 16 KB: [kc]
#define SM_B     65536      // 2 planes: [buf]
#define SM_RED   65536      // reused for final top-4 merge (16 KB)
#define SMEM_TOTAL 98304

__global__ __launch_bounds__(256, 1) void k_argmin_mma() {
    extern __shared__ char smem[];
    const uint32_t sb = smem_u32(smem);
    const int tid = threadIdx.x, wid = tid >> 5, l = tid & 31;
    const int wm = wid >> 2, wn = wid & 3;
    const int row0 = blockIdx.x * 128;

    // stage resident A (4 k-chunks): 4096 x 16B (group 0)
    {
#pragma unroll
        for (int t = 0; t < 16; t++) {
            int i = tid + t * 256;
            int kc = i >> 10, r = (i >> 3) & 127, c = i & 7;
            const __nv_bfloat16* g = g_zhi + (size_t)(row0 + r) * DIMS + kc * 64 + c * 8;
            cp_async16(sb + SM_A + kc * 16384 + r * 128 + ((c ^ (r & 7)) << 4), g);
        }
        CP_COMMIT();
    }

    auto stageB = [&](int q) {
        const int jt = q >> 2, kc = q & 3, buf = q & 1;
#pragma unroll
        for (int t = 0; t < 4; t++) {
            int i = tid + t * 256;
            int r = (i >> 3) & 127, c = i & 7;
            const __nv_bfloat16* g = g_ehi + (size_t)(jt * 128 + r) * DIMS + kc * 64 + c * 8;
            cp_async16(sb + SM_B + buf * 16384 + r * 128 + ((c ^ (r & 7)) << 4), g);
        }
        CP_COMMIT();
    };
    stageB(0);

    const int arow_base = wm * 64 + (l & 15);   // + mt*16
    const int ach = l >> 4;
    const int brow_base = wn * 32 + (l & 7);    // + nt*8
    const int bch = (l >> 3) & 1;

    float acc[4][4][4];
    float sv[8][4]; int sj[8][4];               // per-lane top-4 per row-slot
#pragma unroll
    for (int s = 0; s < 8; s++)
#pragma unroll
        for (int e = 0; e < 4; e++) { sv[s][e] = CUDART_INF_F; sj[s][e] = 0; }

    for (int q = 0; q < 256; q++) {
        const int jt = q >> 2, kc = q & 3, buf = q & 1;
        if (q + 1 < 256) { stageB(q + 1); CP_WAIT1(); } else { CP_WAIT0(); }
        __syncthreads();

        if (kc == 0) {
#pragma unroll
            for (int mt = 0; mt < 4; mt++)
#pragma unroll
                for (int nt = 0; nt < 4; nt++)
#pragma unroll
                    for (int e = 0; e < 4; e++) acc[mt][nt][e] = 0.0f;
        }

#pragma unroll
        for (int ks = 0; ks < 4; ks++) {
            const int kb = ks * 2;
            uint32_t bfr[4][2];
#pragma unroll
            for (int nt = 0; nt < 4; nt++) {
                int row = brow_base + nt * 8;
                ldsm_x2(bfr[nt], sb + SM_B + buf * 16384 + row * 128
                                 + (((kb + bch) ^ (row & 7)) << 4));
            }
#pragma unroll
            for (int mt = 0; mt < 4; mt++) {
                int row = arow_base + mt * 16;
                uint32_t afr[4];
                ldsm_x4(afr, sb + SM_A + kc * 16384 + row * 128
                             + (((kb + ach) ^ (row & 7)) << 4));
#pragma unroll
                for (int nt = 0; nt < 4; nt++)
                    mma16816(acc[mt][nt], afr, bfr[nt]);
            }
        }
        __syncthreads();

        if (kc == 3) {
#pragma unroll
            for (int nt = 0; nt < 4; nt++) {
                int cbase = jt * 128 + wn * 32 + nt * 8 + 2 * (l & 3);
                float2 en = __ldg((const float2*)&g_enorm[cbase]);
#pragma unroll
                for (int mt = 0; mt < 4; mt++) {
                    float d0 = fmaf(-2.0f, acc[mt][nt][0], en.x);
                    float d1 = fmaf(-2.0f, acc[mt][nt][1], en.y);
                    float d2 = fmaf(-2.0f, acc[mt][nt][2], en.x);
                    float d3 = fmaf(-2.0f, acc[mt][nt][3], en.y);
                    t4_insert(sv[mt * 2],     sj[mt * 2],     d0, cbase);
                    t4_insert(sv[mt * 2],     sj[mt * 2],     d1, cbase + 1);
                    t4_insert(sv[mt * 2 + 1], sj[mt * 2 + 1], d2, cbase);
                    t4_insert(sv[mt * 2 + 1], sj[mt * 2 + 1], d3, cbase + 1);
                }
            }
        }
    }

    // cross-lane merge (4 lanes per row), stash per-warp top-4 in smem
    __syncthreads();
#pragma unroll
    for (int mt = 0; mt < 4; mt++) {
#pragma unroll
        for (int h = 0; h < 2; h++) {
            int s = mt * 2 + h;
#pragma unroll
            for (int o = 1; o <= 2; o <<= 1) {
                float wv[4]; int wj[4];
#pragma unroll
                for (int e = 0; e < 4; e++) {
                    wv[e] = __shfl_xor_sync(0xffffffffu, sv[s][e], o);
                    wj[e] = __shfl_xor_sync(0xffffffffu, sj[s][e], o);
                }
                t4_merge(sv[s], sj[s], wv, wj);
            }
            if ((l & 3) == 0) {
                int rl = wm * 64 + mt * 16 + h * 8 + (l >> 2);
                float4* dst = (float4*)(smem + SM_RED) + (rl * 4 + wn) * 2;
                dst[0] = make_float4(sv[s][0], sv[s][1], sv[s][2], sv[s][3]);
                dst[1] = make_float4(__int_as_float(sj[s][0]), __int_as_float(sj[s][1]),
                                     __int_as_float(sj[s][2]), __int_as_float(sj[s][3]));
            }
        }
    }
    __syncthreads();

    // merge the 4 n-warps per row; write final top-4
    if (tid < 128) {
        const float4* src = (const float4*)(smem + SM_RED) + tid * 8;
        float v[4]; int j[4];
        float4 a = src[0], b = src[1];
        v[0] = a.x; v[1] = a.y; v[2] = a.z; v[3] = a.w;
        j[0] = __float_as_int(b.x); j[1] = __float_as_int(b.y);
        j[2] = __float_as_int(b.z); j[3] = __float_as_int(b.w);
#pragma unroll
        for (int w = 1; w < 4; w++) {
            float4 c = src[w * 2], d = src[w * 2 + 1];
            float wv[4] = {c.x, c.y, c.z, c.w};
            int   wj[4] = {__float_as_int(d.x), __float_as_int(d.y),
                           __float_as_int(d.z), __float_as_int(d.w)};
            t4_merge(v, j, wv, wj);
        }
        int row = row0 + tid;
        *(int4*)&g_arg4[4 * row] = make_int4(j[0], j[1], j[2], j[3]);
    }
}

// ---------------------------------------------------------------------------
// D: exact fp32 rescore of top-4 (coalesced via g_eT), then gather quantize,
//    diff, segment sums. One warp per row.
// ---------------------------------------------------------------------------
__global__ __launch_bounds__(256) void k_gather(
    const float* __restrict__ z, float* __restrict__ out)
{
    __shared__ float warpsum[8];
    const int warp = threadIdx.x >> 5, lane = threadIdx.x & 31;
    const int r = blockIdx.x * 8 + warp;
    const int4 cand = *(const int4*)&g_arg4[4 * r];
    const int cj[4] = {cand.x, cand.y, cand.z, cand.w};

    float zv[8];
#pragma unroll
    for (int it = 0; it < 8; it++) zv[it] = z[(size_t)r * DIMS + lane + it * 32];

    float dot[4] = {0.0f, 0.0f, 0.0f, 0.0f};
#pragma unroll
    for (int c = 0; c < 4; c++) {
        const float* e = g_eT + (size_t)cj[c] * DIMS;
#pragma unroll
        for (int it = 0; it < 8; it++)
            dot[c] = fmaf(zv[it], e[lane + it * 32], dot[c]);
    }
#pragma unroll
    for (int c = 0; c < 4; c++)
#pragma unroll
        for (int o = 16; o; o >>= 1) dot[c] += __shfl_xor_sync(0xffffffffu, dot[c], o);

    int bj = cj[0];
    float bd = fmaf(-2.0f, dot[0], g_enorm[cj[0]]);
#pragma unroll
    for (int c = 1; c < 4; c++) {
        float d = fmaf(-2.0f, dot[c], g_enorm[cj[c]]);
        if (d < bd || (d == bd && cj[c] < bj)) { bd = d; bj = cj[c]; }
    }

    const float* eb = g_eT + (size_t)bj * DIMS;
    float ss = 0.0f;
#pragma unroll
    for (int it = 0; it < 8; it++) {
        int d = lane + it * 32;
        float e = eb[d];
        float qd = e - zv[it];
        out[OFF_Q + (size_t)r * DIMS + d] = zv[it] + qd;
        ss = fmaf(qd, qd, ss);
        atomicAdd(&out[OFF_AVG + (size_t)d * NEMB + bj], 0.01f * zv[it]);
    }
    if (lane == 0) {
        atomicAdd(&g_count[bj], 1);
        out[OFF_IND + r] = (float)bj;
    }
#pragma unroll
    for (int o = 16; o; o >>= 1) ss += __shfl_down_sync(0xffffffffu, ss, o);
    if (lane == 0) warpsum[warp] = ss;
    __syncthreads();
    if (threadIdx.x == 0) {
        float t = 0.0f;
#pragma unroll
        for (int w = 0; w < 8; w++) t += warpsum[w];
        atomicAdd(&out[OFF_DIFF], t);
    }
}

// ---------------------------------------------------------------------------
// E: new_cluster_size + global n reduction
// ---------------------------------------------------------------------------
__global__ void k_ncs(const float* __restrict__ cs, float* __restrict__ out) {
    __shared__ float sh[256];
    int j = blockIdx.x * 256 + threadIdx.x;
    float v = cs[j] * 0.99f + 0.01f * (float)g_count[j];
    out[OFF_NCS + j] = v;
    sh[threadIdx.x] = v;
    __syncthreads();
    for (int s = 128; s; s >>= 1) {
        if (threadIdx.x < s) sh[threadIdx.x] += sh[threadIdx.x + s];
        __syncthreads();
    }
    if (threadIdx.x == 0) atomicAdd(&g_n, sh[0]);
}

// ---------------------------------------------------------------------------
// F: new_embedding = avg / smoothed; finalize diff mean
// ---------------------------------------------------------------------------
__global__ void k_final(float* __restrict__ out) {
    int i = blockIdx.x * blockDim.x + threadIdx.x;
    if (i == 0) out[OFF_DIFF] *= (1.0f / 4194304.0f);
    if (i >= DIMS * NEMB) return;
    float n = g_n;
    int j = i & (NEMB - 1);
    float ncs = out[OFF_NCS + j];
    float smoothed = (ncs + 1e-5f) / (n + (float)NEMB * 1e-5f) * n;
    out[OFF_EMB + i] = out[OFF_AVG + i] / smoothed;
}

// ---------------------------------------------------------------------------
extern "C" void kernel_launch(void* const* d_in, const int* in_sizes, int n_in,
                              void* d_out, int out_size) {
    const float* z    = (const float*)d_in[0];   // [16,32,32,256]
    const float* E    = (const float*)d_in[1];   // [256, 8192]
    const float* cs   = (const float*)d_in[2];   // [8192]
    const float* eavg = (const float*)d_in[3];   // [256, 8192]
    float* out = (float*)d_out;

    static int cfg_done = 0;
    if (!cfg_done) {
        cudaFuncSetAttribute(k_argmin_mma,
                             cudaFuncAttributeMaxDynamicSharedMemorySize, SMEM_TOTAL);
        cfg_done = 1;
    }

    k_init   <<<(DIMS * NEMB + 255) / 256, 256>>>(eavg, out);
    k_conv_z <<<NROWS * DIMS / 256, 256>>>(z);
    {
        dim3 g(NEMB / 32, DIMS / 32), b(32, 8);
        k_prep_e<<<g, b>>>(E);
    }
    k_argmin_mma<<<NROWS / 128, 256, SMEM_TOTAL>>>();
    k_gather <<<NROWS / 8, 256>>>(z, out);
    k_ncs    <<<NEMB / 256, 256>>>(cs, out);
    k_final  <<<(DIMS * NEMB + 255) / 256, 256>>>(out);
}

// round 7
// speedup vs baseline: 3.8628x; 2.1488x over previous
#include <cuda_runtime.h>
#include <cuda_bf16.h>
#include <math_constants.h>
#include <stdint.h>

#define NROWS 16384
#define DIMS  256
#define NEMB  8192

// Output layout (float32, reference return order, flattened+concatenated)
#define OFF_Q    0
#define OFF_DIFF 4194304
#define OFF_IND  4194305
#define OFF_EMB  4210689
#define OFF_NCS  6307841
#define OFF_AVG  6316033

// Scratch (no cudaMalloc allowed)
__device__ float          g_enorm[NEMB];
__device__ int            g_arg4[4 * NROWS];       // top-4 candidates per row
__device__ int            g_count[NEMB];
__device__ float          g_n;
__device__ __nv_bfloat16  g_zhi[NROWS * DIMS];     // [row][k] bf16
__device__ __nv_bfloat16  g_ehi[NEMB * DIMS];      // [code][k] bf16 (transposed)
__device__ float          g_eT[NEMB * DIMS];       // [code][k] fp32 (transposed)

// ---------------------------------------------------------------------------
// PTX helpers — baseline sm_80+ features only (target is compute_103, no 'a').
// ---------------------------------------------------------------------------
__device__ __forceinline__ uint32_t smem_u32(const void* p) {
    uint32_t a;
    asm("{ .reg .u64 t; cvta.to.shared.u64 t, %1; cvt.u32.u64 %0, t; }" : "=r"(a) : "l"(p));
    return a;
}
__device__ __forceinline__ void cp_async16(uint32_t s, const void* g) {
    asm volatile("cp.async.ca.shared.global [%0], [%1], 16;" :: "r"(s), "l"(g));
}
#define CP_COMMIT() asm volatile("cp.async.commit_group;")
#define CP_WAIT0()  asm volatile("cp.async.wait_group 0;")
#define CP_WAIT1()  asm volatile("cp.async.wait_group 1;")

__device__ __forceinline__ void ldsm_x4(uint32_t* r, uint32_t a) {
    asm volatile("ldmatrix.sync.aligned.m8n8.x4.shared.b16 {%0,%1,%2,%3}, [%4];"
                 : "=r"(r[0]), "=r"(r[1]), "=r"(r[2]), "=r"(r[3]) : "r"(a));
}
__device__ __forceinline__ void mma16816(float* d, const uint32_t* a, const uint32_t* b) {
    asm volatile("mma.sync.aligned.m16n8k16.row.col.f32.bf16.bf16.f32 "
                 "{%0,%1,%2,%3}, {%4,%5,%6,%7}, {%8,%9}, {%0,%1,%2,%3};"
                 : "+f"(d[0]), "+f"(d[1]), "+f"(d[2]), "+f"(d[3])
                 : "r"(a[0]), "r"(a[1]), "r"(a[2]), "r"(a[3]), "r"(b[0]), "r"(b[1]));
}

// sorted top-4 insert (ascending); common case = 1 compare
__device__ __forceinline__ void t4_insert(float (&v)[4], int (&j)[4], float d, int c) {
    if (d < v[3]) {
        if (d < v[1]) {
            v[3] = v[2]; j[3] = j[2]; v[2] = v[1]; j[2] = j[1];
            if (d < v[0]) { v[1] = v[0]; j[1] = j[0]; v[0] = d; j[0] = c; }
            else          { v[1] = d; j[1] = c; }
        } else {
            if (d < v[2]) { v[3] = v[2]; j[3] = j[2]; v[2] = d; j[2] = c; }
            else          { v[3] = d; j[3] = c; }
        }
    }
}

// merge sorted-4 'w' into sorted-4 'v' keeping smallest 4
__device__ __forceinline__ void t4_merge(float (&v)[4], int (&j)[4],
                                         const float (&w)[4], const int (&iw)[4]) {
    float rv[4]; int rj[4];
    int a = 0, b = 0;
#pragma unroll
    for (int o = 0; o < 4; o++) {
        bool t = (w[b] < v[a]);
        rv[o] = t ? w[b] : v[a];
        rj[o] = t ? iw[b] : j[a];
        if (t) b = (b < 3) ? b + 1 : 3; else a = (a < 3) ? a + 1 : 3;
    }
#pragma unroll
    for (int o = 0; o < 4; o++) { v[o] = rv[o]; j[o] = rj[o]; }
}

// ---------------------------------------------------------------------------
// A: init — zero counters/enorm/diff/n; seed new_embedding_avg with 0.99*avg
// ---------------------------------------------------------------------------
__global__ void k_init(const float* __restrict__ eavg, float* __restrict__ out) {
    int i = blockIdx.x * blockDim.x + threadIdx.x;
    if (i < DIMS * NEMB) out[OFF_AVG + i] = 0.99f * eavg[i];
    if (i < NEMB) { g_count[i] = 0; g_enorm[i] = 0.0f; }
    if (i == 0) { g_n = 0.0f; out[OFF_DIFF] = 0.0f; }
}

// ---------------------------------------------------------------------------
// B: convert z to bf16
// ---------------------------------------------------------------------------
__global__ void k_conv_z(const float* __restrict__ z) {
    int i = blockIdx.x * blockDim.x + threadIdx.x;
    g_zhi[i] = __float2bfloat16(z[i]);
}

// ---------------------------------------------------------------------------
// B2: fused E prep: transpose to [j][k] (fp32 + bf16) and accumulate enorm.
// ---------------------------------------------------------------------------
__global__ void k_prep_e(const float* __restrict__ E) {
    __shared__ float t[32][33];
    int j0 = blockIdx.x * 32, k0 = blockIdx.y * 32;
    int tx = threadIdx.x, ty = threadIdx.y;
#pragma unroll
    for (int s = 0; s < 32; s += 8)
        t[ty + s][tx] = E[(size_t)(k0 + ty + s) * NEMB + j0 + tx];
    __syncthreads();
#pragma unroll
    for (int s = 0; s < 32; s += 8) {
        float x = t[tx][ty + s];
        size_t o = (size_t)(j0 + ty + s) * DIMS + k0 + tx;
        g_eT[o]  = x;
        g_ehi[o] = __float2bfloat16(x);
        float p = x * x;
#pragma unroll
        for (int w = 16; w; w >>= 1) p += __shfl_xor_sync(0xffffffffu, p, w);
        if (tx == 0) atomicAdd(&g_enorm[j0 + ty + s], p);
    }
}

// ---------------------------------------------------------------------------
// C: single-bf16 mma.sync GEMM + smem-persistent per-row top-4.
//    CTA 128 rows; 64 epochs of full jt tiles (128 codes x K=256).
//    A resident (64KB), B double-buffered (2x64KB). Rows of 512B; chunk c
//    (16B, c=0..31) stored at r*512 + (c>>3)*128 + (((c&7)^(r&7))<<4).
// ---------------------------------------------------------------------------
#define SM_A     0
#define SM_B     65536
#define SM_T4    196608     // persistent top-4: 128 rows x 32B
#define SM_RED   200704     // per-warp tile top-4: 128 rows x 5-pad x 32B
#define SMEM_TOTAL 221184

#define PLANE_ADDR(r, c) ((r) * 512 + (((c) >> 3) << 7) + ((((c) & 7) ^ ((r) & 7)) << 4))

__global__ __launch_bounds__(256, 1) void k_argmin_mma() {
    extern __shared__ char smem[];
    const uint32_t sb = smem_u32(smem);
    const int tid = threadIdx.x, wid = tid >> 5, l = tid & 31;
    const int wm = wid >> 2, wn = wid & 3;
    const int row0 = blockIdx.x * 128;

    // stage resident A: 4096 x 16B
#pragma unroll
    for (int t = 0; t < 16; t++) {
        int i = tid + t * 256;
        int r = i >> 5, c = i & 31;
        cp_async16(sb + SM_A + PLANE_ADDR(r, c),
                   g_zhi + (size_t)(row0 + r) * DIMS + c * 8);
    }
    CP_COMMIT();

    auto stageB = [&](int jt) {
        const int buf = jt & 1;
#pragma unroll
        for (int t = 0; t < 16; t++) {
            int i = tid + t * 256;
            int r = i >> 5, c = i & 31;
            cp_async16(sb + SM_B + buf * 65536 + PLANE_ADDR(r, c),
                       g_ehi + (size_t)(jt * 128 + r) * DIMS + c * 8);
        }
        CP_COMMIT();
    };
    stageB(0);

    // init persistent top-4
    if (tid < 128) {
        float4* t4 = (float4*)(smem + SM_T4) + tid * 2;
        t4[0] = make_float4(CUDART_INF_F, CUDART_INF_F, CUDART_INF_F, CUDART_INF_F);
        t4[1] = make_float4(0.0f, 0.0f, 0.0f, 0.0f);
    }

    // fragment lane addressing (fixed parts)
    const int arow = wm * 64 + (l & 15);            // + mt*16
    const int acd  = l >> 4;                         // chunk delta
    const int brow = wn * 32 + ((l >> 4) << 3) + (l & 7);   // + p*16
    const int bcd  = (l >> 3) & 1;

    for (int jt = 0; jt < 64; jt++) {
        const int buf = jt & 1;
        if (jt + 1 < 64) { stageB(jt + 1); CP_WAIT1(); } else { CP_WAIT0(); }
        __syncthreads();

        float acc[4][4][4];
#pragma unroll
        for (int mt = 0; mt < 4; mt++)
#pragma unroll
            for (int nt = 0; nt < 4; nt++)
#pragma unroll
                for (int e = 0; e < 4; e++) acc[mt][nt][e] = 0.0f;

#pragma unroll 4
        for (int t16 = 0; t16 < 16; t16++) {
            const int kb = 2 * t16;
            uint32_t bfr[4][2];
#pragma unroll
            for (int p = 0; p < 2; p++) {
                int r = brow + p * 16, c = kb + bcd;
                uint32_t q[4];
                ldsm_x4(q, sb + SM_B + buf * 65536 + PLANE_ADDR(r, c));
                bfr[2 * p][0] = q[0]; bfr[2 * p][1] = q[1];
                bfr[2 * p + 1][0] = q[2]; bfr[2 * p + 1][1] = q[3];
            }
#pragma unroll
            for (int mt = 0; mt < 4; mt++) {
                int r = arow + mt * 16, c = kb + acd;
                uint32_t afr[4];
                ldsm_x4(afr, sb + SM_A + PLANE_ADDR(r, c));
#pragma unroll
                for (int nt = 0; nt < 4; nt++)
                    mma16816(acc[mt][nt], afr, bfr[nt]);
            }
        }
        __syncthreads();

        // epilogue: distances -> transient top-4 -> quad merge -> SM_RED
        {
            float2 en[4];
#pragma unroll
            for (int nt = 0; nt < 4; nt++)
                en[nt] = __ldg((const float2*)&g_enorm[jt * 128 + wn * 32 + nt * 8 + 2 * (l & 3)]);
#pragma unroll
            for (int mt = 0; mt < 4; mt++) {
#pragma unroll
                for (int h = 0; h < 2; h++) {
                    float v[4] = {CUDART_INF_F, CUDART_INF_F, CUDART_INF_F, CUDART_INF_F};
                    int   id[4] = {0, 0, 0, 0};
#pragma unroll
                    for (int nt = 0; nt < 4; nt++) {
                        int cb = jt * 128 + wn * 32 + nt * 8 + 2 * (l & 3);
                        float d0 = fmaf(-2.0f, acc[mt][nt][h * 2],     en[nt].x);
                        float d1 = fmaf(-2.0f, acc[mt][nt][h * 2 + 1], en[nt].y);
                        t4_insert(v, id, d0, cb);
                        t4_insert(v, id, d1, cb + 1);
                    }
#pragma unroll
                    for (int o = 1; o <= 2; o <<= 1) {
                        float wv[4]; int wj[4];
#pragma unroll
                        for (int e = 0; e < 4; e++) {
                            wv[e] = __shfl_xor_sync(0xffffffffu, v[e], o);
                            wj[e] = __shfl_xor_sync(0xffffffffu, id[e], o);
                        }
                        t4_merge(v, id, wv, wj);
                    }
                    if ((l & 3) == 0) {
                        int rl = wm * 64 + mt * 16 + h * 8 + (l >> 2);
                        float4* dst = (float4*)(smem + SM_RED) + (rl * 5 + wn) * 2;
                        dst[0] = make_float4(v[0], v[1], v[2], v[3]);
                        dst[1] = make_float4(__int_as_float(id[0]), __int_as_float(id[1]),
                                             __int_as_float(id[2]), __int_as_float(id[3]));
                    }
                }
            }
        }
        __syncthreads();

        // 128 threads merge the 4 warp lists into the persistent per-row top-4
        if (tid < 128) {
            float4* t4 = (float4*)(smem + SM_T4) + tid * 2;
            float4 pa = t4[0], pb = t4[1];
            float v[4] = {pa.x, pa.y, pa.z, pa.w};
            int   id[4] = {__float_as_int(pb.x), __float_as_int(pb.y),
                           __float_as_int(pb.z), __float_as_int(pb.w)};
#pragma unroll
            for (int w = 0; w < 4; w++) {
                const float4* src = (const float4*)(smem + SM_RED) + (tid * 5 + w) * 2;
                float4 c = src[0], d = src[1];
                float wv[4] = {c.x, c.y, c.z, c.w};
                int   wj[4] = {__float_as_int(d.x), __float_as_int(d.y),
                               __float_as_int(d.z), __float_as_int(d.w)};
                t4_merge(v, id, wv, wj);
            }
            t4[0] = make_float4(v[0], v[1], v[2], v[3]);
            t4[1] = make_float4(__int_as_float(id[0]), __int_as_float(id[1]),
                                __int_as_float(id[2]), __int_as_float(id[3]));
            if (jt == 63)
                *(int4*)&g_arg4[4 * (row0 + tid)] = make_int4(id[0], id[1], id[2], id[3]);
        }
    }
}

// ---------------------------------------------------------------------------
// D: exact fp32 rescore of top-4 (coalesced via g_eT), then gather quantize,
//    diff, segment sums. One warp per row.
// ---------------------------------------------------------------------------
__global__ __launch_bounds__(256) void k_gather(
    const float* __restrict__ z, float* __restrict__ out)
{
    __shared__ float warpsum[8];
    const int warp = threadIdx.x >> 5, lane = threadIdx.x & 31;
    const int r = blockIdx.x * 8 + warp;
    const int4 cand = *(const int4*)&g_arg4[4 * r];
    const int cj[4] = {cand.x, cand.y, cand.z, cand.w};

    float zv[8];
#pragma unroll
    for (int it = 0; it < 8; it++) zv[it] = z[(size_t)r * DIMS + lane + it * 32];

    float dot[4] = {0.0f, 0.0f, 0.0f, 0.0f};
#pragma unroll
    for (int c = 0; c < 4; c++) {
        const float* e = g_eT + (size_t)cj[c] * DIMS;
#pragma unroll
        for (int it = 0; it < 8; it++)
            dot[c] = fmaf(zv[it], e[lane + it * 32], dot[c]);
    }
#pragma unroll
    for (int c = 0; c < 4; c++)
#pragma unroll
        for (int o = 16; o; o >>= 1) dot[c] += __shfl_xor_sync(0xffffffffu, dot[c], o);

    int bj = cj[0];
    float bd = fmaf(-2.0f, dot[0], g_enorm[cj[0]]);
#pragma unroll
    for (int c = 1; c < 4; c++) {
        float d = fmaf(-2.0f, dot[c], g_enorm[cj[c]]);
        if (d < bd || (d == bd && cj[c] < bj)) { bd = d; bj = cj[c]; }
    }

    const float* eb = g_eT + (size_t)bj * DIMS;
    float ss = 0.0f;
#pragma unroll
    for (int it = 0; it < 8; it++) {
        int d = lane + it * 32;
        float e = eb[d];
        float qd = e - zv[it];
        out[OFF_Q + (size_t)r * DIMS + d] = zv[it] + qd;
        ss = fmaf(qd, qd, ss);
        atomicAdd(&out[OFF_AVG + (size_t)d * NEMB + bj], 0.01f * zv[it]);
    }
    if (lane == 0) {
        atomicAdd(&g_count[bj], 1);
        out[OFF_IND + r] = (float)bj;
    }
#pragma unroll
    for (int o = 16; o; o >>= 1) ss += __shfl_down_sync(0xffffffffu, ss, o);
    if (lane == 0) warpsum[warp] = ss;
    __syncthreads();
    if (threadIdx.x == 0) {
        float t = 0.0f;
#pragma unroll
        for (int w = 0; w < 8; w++) t += warpsum[w];
        atomicAdd(&out[OFF_DIFF], t);
    }
}

// ---------------------------------------------------------------------------
// E: new_cluster_size + global n reduction
// ---------------------------------------------------------------------------
__global__ void k_ncs(const float* __restrict__ cs, float* __restrict__ out) {
    __shared__ float sh[256];
    int j = blockIdx.x * 256 + threadIdx.x;
    float v = cs[j] * 0.99f + 0.01f * (float)g_count[j];
    out[OFF_NCS + j] = v;
    sh[threadIdx.x] = v;
    __syncthreads();
    for (int s = 128; s; s >>= 1) {
        if (threadIdx.x < s) sh[threadIdx.x] += sh[threadIdx.x + s];
        __syncthreads();
    }
    if (threadIdx.x == 0) atomicAdd(&g_n, sh[0]);
}

// ---------------------------------------------------------------------------
// F: new_embedding = avg / smoothed; finalize diff mean
// ---------------------------------------------------------------------------
__global__ void k_final(float* __restrict__ out) {
    int i = blockIdx.x * blockDim.x + threadIdx.x;
    if (i == 0) out[OFF_DIFF] *= (1.0f / 4194304.0f);
    if (i >= DIMS * NEMB) return;
    float n = g_n;
    int j = i & (NEMB - 1);
    float ncs = out[OFF_NCS + j];
    float smoothed = (ncs + 1e-5f) / (n + (float)NEMB * 1e-5f) * n;
    out[OFF_EMB + i] = out[OFF_AVG + i] / smoothed;
}

// ---------------------------------------------------------------------------
extern "C" void kernel_launch(void* const* d_in, const int* in_sizes, int n_in,
                              void* d_out, int out_size) {
    const float* z    = (const float*)d_in[0];   // [16,32,32,256]
    const float* E    = (const float*)d_in[1];   // [256, 8192]
    const float* cs   = (const float*)d_in[2];   // [8192]
    const float* eavg = (const float*)d_in[3];   // [256, 8192]
    float* out = (float*)d_out;

    static int cfg_done = 0;
    if (!cfg_done) {
        cudaFuncSetAttribute(k_argmin_mma,
                             cudaFuncAttributeMaxDynamicSharedMemorySize, SMEM_TOTAL);
        cfg_done = 1;
    }

    k_init   <<<(DIMS * NEMB + 255) / 256, 256>>>(eavg, out);
    k_conv_z <<<NROWS * DIMS / 256, 256>>>(z);
    {
        dim3 g(NEMB / 32, DIMS / 32), b(32, 8);
        k_prep_e<<<g, b>>>(E);
    }
    k_argmin_mma<<<NROWS / 128, 256, SMEM_TOTAL>>>();
    k_gather <<<NROWS / 8, 256>>>(z, out);
    k_ncs    <<<NEMB / 256, 256>>>(cs, out);
    k_final  <<<(DIMS * NEMB + 255) / 256, 256>>>(out);
}

// round 9
// speedup vs baseline: 7.6180x; 1.9721x over previous
#include <cuda_runtime.h>
#include <cuda_bf16.h>
#include <math_constants.h>
#include <stdint.h>

#define NROWS 16384
#define DIMS  256
#define NEMB  8192

// Output layout (float32, reference return order, flattened+concatenated)
#define OFF_Q    0
#define OFF_DIFF 4194304
#define OFF_IND  4194305
#define OFF_EMB  4210689
#define OFF_NCS  6307841
#define OFF_AVG  6316033

// Scratch (no cudaMalloc allowed)
__device__ float          g_enorm[NEMB];
__device__ int            g_arg4[4 * NROWS];       // top-4 candidates per row
__device__ int            g_count[NEMB];
__device__ float          g_n;
__device__ __nv_bfloat16  g_zhi[NROWS * DIMS];     // [row][k] bf16
__device__ __nv_bfloat16  g_ehi[NEMB * DIMS];      // [code][k] bf16 (transposed)
__device__ float          g_eT[NEMB * DIMS];       // [code][k] fp32 (transposed)

// ---------------------------------------------------------------------------
// PTX helpers — baseline sm_80+ features only (target is compute_103, no 'a').
// ---------------------------------------------------------------------------
__device__ __forceinline__ uint32_t smem_u32(const void* p) {
    uint32_t a;
    asm("{ .reg .u64 t; cvta.to.shared.u64 t, %1; cvt.u32.u64 %0, t; }" : "=r"(a) : "l"(p));
    return a;
}
__device__ __forceinline__ void cp_async16(uint32_t s, const void* g) {
    asm volatile("cp.async.ca.shared.global [%0], [%1], 16;" :: "r"(s), "l"(g));
}
#define CP_COMMIT() asm volatile("cp.async.commit_group;")
#define CP_WAIT0()  asm volatile("cp.async.wait_group 0;")
#define CP_WAIT1()  asm volatile("cp.async.wait_group 1;")

__device__ __forceinline__ void ldsm_x4(uint32_t* r, uint32_t a) {
    asm volatile("ldmatrix.sync.aligned.m8n8.x4.shared.b16 {%0,%1,%2,%3}, [%4];"
                 : "=r"(r[0]), "=r"(r[1]), "=r"(r[2]), "=r"(r[3]) : "r"(a));
}
__device__ __forceinline__ void mma16816(float* d, const uint32_t* a, const uint32_t* b) {
    asm volatile("mma.sync.aligned.m16n8k16.row.col.f32.bf16.bf16.f32 "
                 "{%0,%1,%2,%3}, {%4,%5,%6,%7}, {%8,%9}, {%0,%1,%2,%3};"
                 : "+f"(d[0]), "+f"(d[1]), "+f"(d[2]), "+f"(d[3])
                 : "r"(a[0]), "r"(a[1]), "r"(a[2]), "r"(a[3]), "r"(b[0]), "r"(b[1]));
}

// sorted top-2 insert (ascending)
__device__ __forceinline__ void t2_insert(float& v0, int& j0, float& v1, int& j1,
                                          float d, int c) {
    if (d < v1) {
        if (d < v0) { v1 = v0; j1 = j0; v0 = d; j0 = c; }
        else        { v1 = d; j1 = c; }
    }
}

// sorted top-4 insert (ascending); common case = 1 compare
__device__ __forceinline__ void t4_insert(float (&v)[4], int (&j)[4], float d, int c) {
    if (d < v[3]) {
        if (d < v[1]) {
            v[3] = v[2]; j[3] = j[2]; v[2] = v[1]; j[2] = j[1];
            if (d < v[0]) { v[1] = v[0]; j[1] = j[0]; v[0] = d; j[0] = c; }
            else          { v[1] = d; j[1] = c; }
        } else {
            if (d < v[2]) { v[3] = v[2]; j[3] = j[2]; v[2] = d; j[2] = c; }
            else          { v[3] = d; j[3] = c; }
        }
    }
}

// ---------------------------------------------------------------------------
// A: init — zero counters/enorm/diff/n; seed new_embedding_avg with 0.99*avg
// ---------------------------------------------------------------------------
__global__ void k_init(const float* __restrict__ eavg, float* __restrict__ out) {
    int i = blockIdx.x * blockDim.x + threadIdx.x;
    if (i < DIMS * NEMB) out[OFF_AVG + i] = 0.99f * eavg[i];
    if (i < NEMB) { g_count[i] = 0; g_enorm[i] = 0.0f; }
    if (i == 0) { g_n = 0.0f; out[OFF_DIFF] = 0.0f; }
}

// ---------------------------------------------------------------------------
// B: convert z to bf16
// ---------------------------------------------------------------------------
__global__ void k_conv_z(const float* __restrict__ z) {
    int i = blockIdx.x * blockDim.x + threadIdx.x;
    g_zhi[i] = __float2bfloat16(z[i]);
}

// ---------------------------------------------------------------------------
// B2: fused E prep: transpose to [j][k] (fp32 + bf16) and accumulate enorm.
// ---------------------------------------------------------------------------
__global__ void k_prep_e(const float* __restrict__ E) {
    __shared__ float t[32][33];
    int j0 = blockIdx.x * 32, k0 = blockIdx.y * 32;
    int tx = threadIdx.x, ty = threadIdx.y;
#pragma unroll
    for (int s = 0; s < 32; s += 8)
        t[ty + s][tx] = E[(size_t)(k0 + ty + s) * NEMB + j0 + tx];
    __syncthreads();
#pragma unroll
    for (int s = 0; s < 32; s += 8) {
        float x = t[tx][ty + s];
        size_t o = (size_t)(j0 + ty + s) * DIMS + k0 + tx;
        g_eT[o]  = x;
        g_ehi[o] = __float2bfloat16(x);
        float p = x * x;
#pragma unroll
        for (int w = 16; w; w >>= 1) p += __shfl_xor_sync(0xffffffffu, p, w);
        if (tx == 0) atomicAdd(&g_enorm[j0 + ty + s], p);
    }
}

// ---------------------------------------------------------------------------
// C: single-bf16 mma.sync GEMM + per-tile top-2 -> register-persistent top-4.
//    512 threads, 16 warps (4m x 4n), warp tile 32x32; 64 jt epochs.
//    A resident (64KB), B double-buffered (2x64KB). Rows of 512B; chunk c
//    (16B, c=0..31) stored at r*512 + (c>>3)*128 + (((c&7)^(r&7))<<4).
// ---------------------------------------------------------------------------
#define SM_A     0
#define SM_B     65536
#define SM_RED   196608     // per-warp tile top-2: 128 rows x 5-pad x 16B = 10240
#define SMEM_TOTAL 206848

#define PLANE_ADDR(r, c) ((r) * 512 + (((c) >> 3) << 7) + ((((c) & 7) ^ ((r) & 7)) << 4))

__global__ __launch_bounds__(512, 1) void k_argmin_mma() {
    extern __shared__ char smem[];
    const uint32_t sb = smem_u32(smem);
    const int tid = threadIdx.x, wid = tid >> 5, l = tid & 31;
    const int wm = wid >> 2, wn = wid & 3;
    const int row0 = blockIdx.x * 128;

    // stage resident A: 4096 x 16B
#pragma unroll
    for (int t = 0; t < 8; t++) {
        int i = tid + t * 512;
        int r = i >> 5, c = i & 31;
        cp_async16(sb + SM_A + PLANE_ADDR(r, c),
                   g_zhi + (size_t)(row0 + r) * DIMS + c * 8);
    }
    CP_COMMIT();

    auto stageB = [&](int jt) {
        const int buf = jt & 1;
#pragma unroll
        for (int t = 0; t < 8; t++) {
            int i = tid + t * 512;
            int r = i >> 5, c = i & 31;
            cp_async16(sb + SM_B + buf * 65536 + PLANE_ADDR(r, c),
                       g_ehi + (size_t)(jt * 128 + r) * DIMS + c * 8);
        }
        CP_COMMIT();
    };
    stageB(0);

    // persistent per-row top-4, in registers of threads 0..127 (row = tid)
    float pv[4] = {CUDART_INF_F, CUDART_INF_F, CUDART_INF_F, CUDART_INF_F};
    int   pj[4] = {0, 0, 0, 0};

    // fragment lane addressing (fixed parts)
    const int arow = wm * 32 + (l & 15);                      // + mt*16
    const int acd  = l >> 4;
    const int brow = wn * 32 + ((l >> 4) << 3) + (l & 7);     // + p*16
    const int bcd  = (l >> 3) & 1;

    for (int jt = 0; jt < 64; jt++) {
        const int buf = jt & 1;
        if (jt + 1 < 64) { stageB(jt + 1); CP_WAIT1(); } else { CP_WAIT0(); }
        __syncthreads();

        float acc[2][4][4];
#pragma unroll
        for (int mt = 0; mt < 2; mt++)
#pragma unroll
            for (int nt = 0; nt < 4; nt++)
#pragma unroll
                for (int e = 0; e < 4; e++) acc[mt][nt][e] = 0.0f;

#pragma unroll 4
        for (int t16 = 0; t16 < 16; t16++) {
            const int kb = 2 * t16;
            uint32_t bfr[4][2];
#pragma unroll
            for (int p = 0; p < 2; p++) {
                int r = brow + p * 16, c = kb + bcd;
                uint32_t q[4];
                ldsm_x4(q, sb + SM_B + buf * 65536 + PLANE_ADDR(r, c));
                bfr[2 * p][0] = q[0]; bfr[2 * p][1] = q[1];
                bfr[2 * p + 1][0] = q[2]; bfr[2 * p + 1][1] = q[3];
            }
#pragma unroll
            for (int mt = 0; mt < 2; mt++) {
                int r = arow + mt * 16, c = kb + acd;
                uint32_t afr[4];
                ldsm_x4(afr, sb + SM_A + PLANE_ADDR(r, c));
#pragma unroll
                for (int nt = 0; nt < 4; nt++)
                    mma16816(acc[mt][nt], afr, bfr[nt]);
            }
        }
        // no sync needed here: epilogue reads only registers + gmem enorm

        // epilogue: distances -> per-row-slot top-2 -> quad merge -> SM_RED
        {
            const int cb0 = jt * 128 + wn * 32 + 2 * (l & 3);
            float2 en[4];
#pragma unroll
            for (int nt = 0; nt < 4; nt++)
                en[nt] = __ldg((const float2*)&g_enorm[cb0 + nt * 8]);
#pragma unroll
            for (int mt = 0; mt < 2; mt++) {
#pragma unroll
                for (int h = 0; h < 2; h++) {
                    float v0 = CUDART_INF_F, v1 = CUDART_INF_F;
                    int   j0 = 0, j1 = 0;
#pragma unroll
                    for (int nt = 0; nt < 4; nt++) {
                        int cb = cb0 + nt * 8;
                        float d0 = fmaf(-2.0f, acc[mt][nt][h * 2],     en[nt].x);
                        float d1 = fmaf(-2.0f, acc[mt][nt][h * 2 + 1], en[nt].y);
                        t2_insert(v0, j0, v1, j1, d0, cb);
                        t2_insert(v0, j0, v1, j1, d1, cb + 1);
                    }
#pragma unroll
                    for (int o = 1; o <= 2; o <<= 1) {
                        float w0 = __shfl_xor_sync(0xffffffffu, v0, o);
                        int   i0 = __shfl_xor_sync(0xffffffffu, j0, o);
                        float w1 = __shfl_xor_sync(0xffffffffu, v1, o);
                        int   i1 = __shfl_xor_sync(0xffffffffu, j1, o);
                        if (w0 < v0) {
                            float nv1 = (v0 < w1) ? v0 : w1;
                            int   nj1 = (v0 < w1) ? j0 : i1;
                            v1 = nv1; j1 = nj1; v0 = w0; j0 = i0;
                        } else if (w0 < v1) { v1 = w0; j1 = i0; }
                    }
                    if ((l & 3) == 0) {
                        int rl = wm * 32 + mt * 16 + h * 8 + (l >> 2);
                        ((float4*)(smem + SM_RED))[rl * 5 + wn] =
                            make_float4(v0, v1, __int_as_float(j0), __int_as_float(j1));
                    }
                }
            }
        }
        __syncthreads();

        // threads 0..127 merge the 4 warp top-2 lists into register top-4
        if (tid < 128) {
            const float4* src = (const float4*)(smem + SM_RED) + tid * 5;
#pragma unroll
            for (int w = 0; w < 4; w++) {
                float4 b = src[w];
                t4_insert(pv, pj, b.x, __float_as_int(b.z));
                t4_insert(pv, pj, b.y, __float_as_int(b.w));
            }
        }
        // next epoch's first __syncthreads orders SM_RED reuse
    }

    if (tid < 128)
        *(int4*)&g_arg4[4 * (row0 + tid)] = make_int4(pj[0], pj[1], pj[2], pj[3]);
}

// ---------------------------------------------------------------------------
// D: exact fp32 rescore of top-4 (coalesced via g_eT), then gather quantize,
//    diff, segment sums. One warp per row.
// ---------------------------------------------------------------------------
__global__ __launch_bounds__(256) void k_gather(
    const float* __restrict__ z, float* __restrict__ out)
{
    __shared__ float warpsum[8];
    const int warp = threadIdx.x >> 5, lane = threadIdx.x & 31;
    const int r = blockIdx.x * 8 + warp;
    const int4 cand = *(const int4*)&g_arg4[4 * r];
    const int cj[4] = {cand.x, cand.y, cand.z, cand.w};

    float zv[8];
#pragma unroll
    for (int it = 0; it < 8; it++) zv[it] = z[(size_t)r * DIMS + lane + it * 32];

    float dot[4] = {0.0f, 0.0f, 0.0f, 0.0f};
#pragma unroll
    for (int c = 0; c < 4; c++) {
        const float* e = g_eT + (size_t)cj[c] * DIMS;
#pragma unroll
        for (int it = 0; it < 8; it++)
            dot[c] = fmaf(zv[it], e[lane + it * 32], dot[c]);
    }
#pragma unroll
    for (int c = 0; c < 4; c++)
#pragma unroll
        for (int o = 16; o; o >>= 1) dot[c] += __shfl_xor_sync(0xffffffffu, dot[c], o);

    int bj = cj[0];
    float bd = fmaf(-2.0f, dot[0], g_enorm[cj[0]]);
#pragma unroll
    for (int c = 1; c < 4; c++) {
        float d = fmaf(-2.0f, dot[c], g_enorm[cj[c]]);
        if (d < bd || (d == bd && cj[c] < bj)) { bd = d; bj = cj[c]; }
    }

    const float* eb = g_eT + (size_t)bj * DIMS;
    float ss = 0.0f;
#pragma unroll
    for (int it = 0; it < 8; it++) {
        int d = lane + it * 32;
        float e = eb[d];
        float qd = e - zv[it];
        out[OFF_Q + (size_t)r * DIMS + d] = zv[it] + qd;
        ss = fmaf(qd, qd, ss);
        atomicAdd(&out[OFF_AVG + (size_t)d * NEMB + bj], 0.01f * zv[it]);
    }
    if (lane == 0) {
        atomicAdd(&g_count[bj], 1);
        out[OFF_IND + r] = (float)bj;
    }
#pragma unroll
    for (int o = 16; o; o >>= 1) ss += __shfl_down_sync(0xffffffffu, ss, o);
    if (lane == 0) warpsum[warp] = ss;
    __syncthreads();
    if (threadIdx.x == 0) {
        float t = 0.0f;
#pragma unroll
        for (int w = 0; w < 8; w++) t += warpsum[w];
        atomicAdd(&out[OFF_DIFF], t);
    }
}

// ---------------------------------------------------------------------------
// E: new_cluster_size + global n reduction
// ---------------------------------------------------------------------------
__global__ void k_ncs(const float* __restrict__ cs, float* __restrict__ out) {
    __shared__ float sh[256];
    int j = blockIdx.x * 256 + threadIdx.x;
    float v = cs[j] * 0.99f + 0.01f * (float)g_count[j];
    out[OFF_NCS + j] = v;
    sh[threadIdx.x] = v;
    __syncthreads();
    for (int s = 128; s; s >>= 1) {
        if (threadIdx.x < s) sh[threadIdx.x] += sh[threadIdx.x + s];
        __syncthreads();
    }
    if (threadIdx.x == 0) atomicAdd(&g_n, sh[0]);
}

// ---------------------------------------------------------------------------
// F: new_embedding = avg / smoothed; finalize diff mean
// ---------------------------------------------------------------------------
__global__ void k_final(float* __restrict__ out) {
    int i = blockIdx.x * blockDim.x + threadIdx.x;
    if (i == 0) out[OFF_DIFF] *= (1.0f / 4194304.0f);
    if (i >= DIMS * NEMB) return;
    float n = g_n;
    int j = i & (NEMB - 1);
    float ncs = out[OFF_NCS + j];
    float smoothed = (ncs + 1e-5f) / (n + (float)NEMB * 1e-5f) * n;
    out[OFF_EMB + i] = out[OFF_AVG + i] / smoothed;
}

// ---------------------------------------------------------------------------
extern "C" void kernel_launch(void* const* d_in, const int* in_sizes, int n_in,
                              void* d_out, int out_size) {
    const float* z    = (const float*)d_in[0];   // [16,32,32,256]
    const float* E    = (const float*)d_in[1];   // [256, 8192]
    const float* cs   = (const float*)d_in[2];   // [8192]
    const float* eavg = (const float*)d_in[3];   // [256, 8192]
    float* out = (float*)d_out;

    static int cfg_done = 0;
    if (!cfg_done) {
        cudaFuncSetAttribute(k_argmin_mma,
                             cudaFuncAttributeMaxDynamicSharedMemorySize, SMEM_TOTAL);
        cfg_done = 1;
    }

    k_init   <<<(DIMS * NEMB + 255) / 256, 256>>>(eavg, out);
    k_conv_z <<<NROWS * DIMS / 256, 256>>>(z);
    {
        dim3 g(NEMB / 32, DIMS / 32), b(32, 8);
        k_prep_e<<<g, b>>>(E);
    }
    k_argmin_mma<<<NROWS / 128, 512, SMEM_TOTAL>>>();
    k_gather <<<NROWS / 8, 256>>>(z, out);
    k_ncs    <<<NEMB / 256, 256>>>(cs, out);
    k_final  <<<(DIMS * NEMB + 255) / 256, 256>>>(out);
}

// round 11
// speedup vs baseline: 9.0344x; 1.1859x over previous
#include <cuda_runtime.h>
#include <cuda_bf16.h>
#include <math_constants.h>
#include <stdint.h>

#define NROWS 16384
#define DIMS  256
#define NEMB  8192

// Output layout (float32, reference return order, flattened+concatenated)
#define OFF_Q    0
#define OFF_DIFF 4194304
#define OFF_IND  4194305
#define OFF_EMB  4210689
#define OFF_NCS  6307841
#define OFF_AVG  6316033

// Scratch (no cudaMalloc allowed)
__device__ float          g_enorm[NEMB];
__device__ int            g_arg4[4 * NROWS];       // top-4 candidates per row
__device__ int            g_count[NEMB];
__device__ float          g_n;
__device__ __nv_bfloat16  g_zhi[NROWS * DIMS];     // [row][k] bf16
__device__ __nv_bfloat16  g_ehi[NEMB * DIMS];      // [code][k] bf16 (transposed)
__device__ float          g_eT[NEMB * DIMS];       // [code][k] fp32 (transposed)

// ---------------------------------------------------------------------------
// PTX helpers — baseline sm_80+ features only (target is compute_103, no 'a').
// ---------------------------------------------------------------------------
__device__ __forceinline__ uint32_t smem_u32(const void* p) {
    uint32_t a;
    asm("{ .reg .u64 t; cvta.to.shared.u64 t, %1; cvt.u32.u64 %0, t; }" : "=r"(a) : "l"(p));
    return a;
}
__device__ __forceinline__ void cp_async16(uint32_t s, const void* g) {
    asm volatile("cp.async.ca.shared.global [%0], [%1], 16;" :: "r"(s), "l"(g));
}
#define CP_COMMIT() asm volatile("cp.async.commit_group;")
#define CP_WAIT0()  asm volatile("cp.async.wait_group 0;")
#define CP_WAIT1()  asm volatile("cp.async.wait_group 1;")

__device__ __forceinline__ void ldsm_x4(uint32_t* r, uint32_t a) {
    asm volatile("ldmatrix.sync.aligned.m8n8.x4.shared.b16 {%0,%1,%2,%3}, [%4];"
                 : "=r"(r[0]), "=r"(r[1]), "=r"(r[2]), "=r"(r[3]) : "r"(a));
}
__device__ __forceinline__ void mma16816(float* d, const uint32_t* a, const uint32_t* b) {
    asm volatile("mma.sync.aligned.m16n8k16.row.col.f32.bf16.bf16.f32 "
                 "{%0,%1,%2,%3}, {%4,%5,%6,%7}, {%8,%9}, {%0,%1,%2,%3};"
                 : "+f"(d[0]), "+f"(d[1]), "+f"(d[2]), "+f"(d[3])
                 : "r"(a[0]), "r"(a[1]), "r"(a[2]), "r"(a[3]), "r"(b[0]), "r"(b[1]));
}

// pack positive float distance with 7-bit local code in low mantissa bits
__device__ __forceinline__ float pack7(float d, uint32_t code) {
    return __uint_as_float((__float_as_uint(d) & 0xFFFFFF80u) | code);
}

// merge two ascending pairs (a0<=a1),(b0<=b1) -> smallest two (branch-free)
__device__ __forceinline__ void p2_merge(float& a0, float& a1, float b0, float b1) {
    float lo = fminf(a0, b0);
    a1 = fminf(fmaxf(a0, b0), fminf(a1, b1));
    a0 = lo;
}

// sorted top-4 insert (ascending); common case = 1 compare
__device__ __forceinline__ void t4_insert(float (&v)[4], int (&j)[4], float d, int c) {
    if (d < v[3]) {
        if (d < v[1]) {
            v[3] = v[2]; j[3] = j[2]; v[2] = v[1]; j[2] = j[1];
            if (d < v[0]) { v[1] = v[0]; j[1] = j[0]; v[0] = d; j[0] = c; }
            else          { v[1] = d; j[1] = c; }
        } else {
            if (d < v[2]) { v[3] = v[2]; j[3] = j[2]; v[2] = d; j[2] = c; }
            else          { v[3] = d; j[3] = c; }
        }
    }
}

// ---------------------------------------------------------------------------
// A: init — zero counters/enorm/diff/n; seed new_embedding_avg with 0.99*avg
// ---------------------------------------------------------------------------
__global__ void k_init(const float* __restrict__ eavg, float* __restrict__ out) {
    int i = blockIdx.x * blockDim.x + threadIdx.x;
    if (i < DIMS * NEMB) out[OFF_AVG + i] = 0.99f * eavg[i];
    if (i < NEMB) { g_count[i] = 0; g_enorm[i] = 0.0f; }
    if (i == 0) { g_n = 0.0f; out[OFF_DIFF] = 0.0f; }
}

// ---------------------------------------------------------------------------
// B: convert z to bf16
// ---------------------------------------------------------------------------
__global__ void k_conv_z(const float* __restrict__ z) {
    int i = blockIdx.x * blockDim.x + threadIdx.x;
    g_zhi[i] = __float2bfloat16(z[i]);
}

// ---------------------------------------------------------------------------
// B2: fused E prep: transpose to [j][k] (fp32 + bf16) and accumulate enorm.
// ---------------------------------------------------------------------------
__global__ void k_prep_e(const float* __restrict__ E) {
    __shared__ float t[32][33];
    int j0 = blockIdx.x * 32, k0 = blockIdx.y * 32;
    int tx = threadIdx.x, ty = threadIdx.y;
#pragma unroll
    for (int s = 0; s < 32; s += 8)
        t[ty + s][tx] = E[(size_t)(k0 + ty + s) * NEMB + j0 + tx];
    __syncthreads();
#pragma unroll
    for (int s = 0; s < 32; s += 8) {
        float x = t[tx][ty + s];
        size_t o = (size_t)(j0 + ty + s) * DIMS + k0 + tx;
        g_eT[o]  = x;
        g_ehi[o] = __float2bfloat16(x);
        float p = x * x;
#pragma unroll
        for (int w = 16; w; w >>= 1) p += __shfl_xor_sync(0xffffffffu, p, w);
        if (tx == 0) atomicAdd(&g_enorm[j0 + ty + s], p);
    }
}

// ---------------------------------------------------------------------------
// C: single-bf16 mma.sync GEMM + packed min-2 epilogue -> register top-4.
//    512 threads, 16 warps (4m x 4n), warp tile 32x32; 64 jt epochs.
//    A resident (64KB), B double-buffered (2x64KB). Rows of 512B; chunk c
//    (16B, c=0..31) stored at r*512 + (c>>3)*128 + (((c&7)^(r&7))<<4).
//    Epilogue packs (dist+512) with 7-bit local code in low mantissa bits
//    (pack error <= 0.008); branch-free min/2nd-min tournament; tile top-2
//    inserted into per-row register top-4 (two-deep redundancy so a single
//    within-tile noise flip cannot drop the true argmin); exact rescore after.
// ---------------------------------------------------------------------------
#define SM_A     0
#define SM_B     65536
#define SM_RED   196608     // per-warp tile (min,min2): 128 rows x 5-pad x 8B
#define SMEM_TOTAL 201728

#define PLANE_ADDR(r, c) ((r) * 512 + (((c) >> 3) << 7) + ((((c) & 7) ^ ((r) & 7)) << 4))

__global__ __launch_bounds__(512, 1) void k_argmin_mma() {
    extern __shared__ char smem[];
    const uint32_t sb = smem_u32(smem);
    const int tid = threadIdx.x, wid = tid >> 5, l = tid & 31;
    const int wm = wid >> 2, wn = wid & 3;
    const int row0 = blockIdx.x * 128;

    // stage resident A: 4096 x 16B
#pragma unroll
    for (int t = 0; t < 8; t++) {
        int i = tid + t * 512;
        int r = i >> 5, c = i & 31;
        cp_async16(sb + SM_A + PLANE_ADDR(r, c),
                   g_zhi + (size_t)(row0 + r) * DIMS + c * 8);
    }
    CP_COMMIT();

    auto stageB = [&](int jt) {
        const int buf = jt & 1;
#pragma unroll
        for (int t = 0; t < 8; t++) {
            int i = tid + t * 512;
            int r = i >> 5, c = i & 31;
            cp_async16(sb + SM_B + buf * 65536 + PLANE_ADDR(r, c),
                       g_ehi + (size_t)(jt * 128 + r) * DIMS + c * 8);
        }
        CP_COMMIT();
    };
    stageB(0);

    // persistent per-row top-4, in registers of threads 0..127 (row = tid)
    float pv[4] = {CUDART_INF_F, CUDART_INF_F, CUDART_INF_F, CUDART_INF_F};
    int   pj[4] = {0, 0, 0, 0};

    // fragment lane addressing (fixed parts)
    const int arow = wm * 32 + (l & 15);                      // + mt*16
    const int acd  = l >> 4;
    const int brow = wn * 32 + ((l >> 4) << 3) + (l & 7);     // + p*16
    const int bcd  = (l >> 3) & 1;
    const int lc0  = wn * 32 + 2 * (l & 3);                   // local code base

    for (int jt = 0; jt < 64; jt++) {
        const int buf = jt & 1;
        if (jt + 1 < 64) { stageB(jt + 1); CP_WAIT1(); } else { CP_WAIT0(); }
        __syncthreads();

        float acc[2][4][4];
#pragma unroll
        for (int mt = 0; mt < 2; mt++)
#pragma unroll
            for (int nt = 0; nt < 4; nt++)
#pragma unroll
                for (int e = 0; e < 4; e++) acc[mt][nt][e] = 0.0f;

#pragma unroll 8
        for (int t16 = 0; t16 < 16; t16++) {
            const int kb = 2 * t16;
            uint32_t bfr[4][2];
#pragma unroll
            for (int p = 0; p < 2; p++) {
                int r = brow + p * 16, c = kb + bcd;
                uint32_t q[4];
                ldsm_x4(q, sb + SM_B + buf * 65536 + PLANE_ADDR(r, c));
                bfr[2 * p][0] = q[0]; bfr[2 * p][1] = q[1];
                bfr[2 * p + 1][0] = q[2]; bfr[2 * p + 1][1] = q[3];
            }
#pragma unroll
            for (int mt = 0; mt < 2; mt++) {
                int r = arow + mt * 16, c = kb + acd;
                uint32_t afr[4];
                ldsm_x4(afr, sb + SM_A + PLANE_ADDR(r, c));
#pragma unroll
                for (int nt = 0; nt < 4; nt++)
                    mma16816(acc[mt][nt], afr, bfr[nt]);
            }
        }
        // no sync needed here: epilogue reads only registers + gmem enorm

        // epilogue: packed distances -> branch-free min2 tournament -> SM_RED
        {
            float enx[4], eny[4];
#pragma unroll
            for (int nt = 0; nt < 4; nt++) {
                float2 en = __ldg((const float2*)&g_enorm[jt * 128 + lc0 + nt * 8]);
                enx[nt] = en.x + 512.0f;
                eny[nt] = en.y + 512.0f;
            }
#pragma unroll
            for (int mt = 0; mt < 2; mt++) {
#pragma unroll
                for (int h = 0; h < 2; h++) {
                    float p[8];
#pragma unroll
                    for (int nt = 0; nt < 4; nt++) {
                        uint32_t lc = lc0 + nt * 8;
                        p[2 * nt]     = pack7(fmaf(-2.0f, acc[mt][nt][h * 2],     enx[nt]), lc);
                        p[2 * nt + 1] = pack7(fmaf(-2.0f, acc[mt][nt][h * 2 + 1], eny[nt]), lc + 1);
                    }
                    float l0 = fminf(p[0], p[1]), h0 = fmaxf(p[0], p[1]);
                    float l1 = fminf(p[2], p[3]), h1 = fmaxf(p[2], p[3]);
                    float l2 = fminf(p[4], p[5]), h2 = fmaxf(p[4], p[5]);
                    float l3 = fminf(p[6], p[7]), h3 = fmaxf(p[6], p[7]);
                    p2_merge(l0, h0, l1, h1);
                    p2_merge(l2, h2, l3, h3);
                    p2_merge(l0, h0, l2, h2);
#pragma unroll
                    for (int o = 1; o <= 2; o <<= 1) {
                        float fl = __shfl_xor_sync(0xffffffffu, l0, o);
                        float fh = __shfl_xor_sync(0xffffffffu, h0, o);
                        p2_merge(l0, h0, fl, fh);
                    }
                    if ((l & 3) == 0) {
                        int rl = wm * 32 + mt * 16 + h * 8 + (l >> 2);
                        ((float2*)(smem + SM_RED))[rl * 5 + wn] = make_float2(l0, h0);
                    }
                }
            }
        }
        __syncthreads();

        // threads 0..127: merge the 4 warp (min,min2) pairs -> tile top-2
        if (tid < 128) {
            const float2* src = (const float2*)(smem + SM_RED) + tid * 5;
            float2 a = src[0], b = src[1], c = src[2], d = src[3];
            p2_merge(a.x, a.y, b.x, b.y);
            p2_merge(c.x, c.y, d.x, d.y);
            p2_merge(a.x, a.y, c.x, c.y);
            t4_insert(pv, pj, a.x, jt * 128 + (__float_as_int(a.x) & 0x7F));
            t4_insert(pv, pj, a.y, jt * 128 + (__float_as_int(a.y) & 0x7F));
        }
        // next epoch's first __syncthreads orders SM_RED reuse
    }

    if (tid < 128)
        *(int4*)&g_arg4[4 * (row0 + tid)] = make_int4(pj[0], pj[1], pj[2], pj[3]);
}

// ---------------------------------------------------------------------------
// D: exact fp32 rescore of top-4 (coalesced via g_eT), then gather quantize,
//    diff, segment sums. One warp per row.
// ---------------------------------------------------------------------------
__global__ __launch_bounds__(256) void k_gather(
    const float* __restrict__ z, float* __restrict__ out)
{
    __shared__ float warpsum[8];
    const int warp = threadIdx.x >> 5, lane = threadIdx.x & 31;
    const int r = blockIdx.x * 8 + warp;
    const int4 cand = *(const int4*)&g_arg4[4 * r];
    const int cj[4] = {cand.x, cand.y, cand.z, cand.w};

    float zv[8];
#pragma unroll
    for (int it = 0; it < 8; it++) zv[it] = z[(size_t)r * DIMS + lane + it * 32];

    float dot[4] = {0.0f, 0.0f, 0.0f, 0.0f};
#pragma unroll
    for (int c = 0; c < 4; c++) {
        const float* e = g_eT + (size_t)cj[c] * DIMS;
#pragma unroll
        for (int it = 0; it < 8; it++)
            dot[c] = fmaf(zv[it], e[lane + it * 32], dot[c]);
    }
#pragma unroll
    for (int c = 0; c < 4; c++)
#pragma unroll
        for (int o = 16; o; o >>= 1) dot[c] += __shfl_xor_sync(0xffffffffu, dot[c], o);

    int bj = cj[0];
    float bd = fmaf(-2.0f, dot[0], g_enorm[cj[0]]);
#pragma unroll
    for (int c = 1; c < 4; c++) {
        float d = fmaf(-2.0f, dot[c], g_enorm[cj[c]]);
        if (d < bd || (d == bd && cj[c] < bj)) { bd = d; bj = cj[c]; }
    }

    const float* eb = g_eT + (size_t)bj * DIMS;
    float ss = 0.0f;
#pragma unroll
    for (int it = 0; it < 8; it++) {
        int d = lane + it * 32;
        float e = eb[d];
        float qd = e - zv[it];
        out[OFF_Q + (size_t)r * DIMS + d] = zv[it] + qd;
        ss = fmaf(qd, qd, ss);
        atomicAdd(&out[OFF_AVG + (size_t)d * NEMB + bj], 0.01f * zv[it]);
    }
    if (lane == 0) {
        atomicAdd(&g_count[bj], 1);
        out[OFF_IND + r] = (float)bj;
    }
#pragma unroll
    for (int o = 16; o; o >>= 1) ss += __shfl_down_sync(0xffffffffu, ss, o);
    if (lane == 0) warpsum[warp] = ss;
    __syncthreads();
    if (threadIdx.x == 0) {
        float t = 0.0f;
#pragma unroll
        for (int w = 0; w < 8; w++) t += warpsum[w];
        atomicAdd(&out[OFF_DIFF], t);
    }
}

// ---------------------------------------------------------------------------
// E: new_cluster_size + global n reduction
// ---------------------------------------------------------------------------
__global__ void k_ncs(const float* __restrict__ cs, float* __restrict__ out) {
    __shared__ float sh[256];
    int j = blockIdx.x * 256 + threadIdx.x;
    float v = cs[j] * 0.99f + 0.01f * (float)g_count[j];
    out[OFF_NCS + j] = v;
    sh[threadIdx.x] = v;
    __syncthreads();
    for (int s = 128; s; s >>= 1) {
        if (threadIdx.x < s) sh[threadIdx.x] += sh[threadIdx.x + s];
        __syncthreads();
    }
    if (threadIdx.x == 0) atomicAdd(&g_n, sh[0]);
}

// ---------------------------------------------------------------------------
// F: new_embedding = avg / smoothed; finalize diff mean
// ---------------------------------------------------------------------------
__global__ void k_final(float* __restrict__ out) {
    int i = blockIdx.x * blockDim.x + threadIdx.x;
    if (i == 0) out[OFF_DIFF] *= (1.0f / 4194304.0f);
    if (i >= DIMS * NEMB) return;
    float n = g_n;
    int j = i & (NEMB - 1);
    float ncs = out[OFF_NCS + j];
    float smoothed = (ncs + 1e-5f) / (n + (float)NEMB * 1e-5f) * n;
    out[OFF_EMB + i] = out[OFF_AVG + i] / smoothed;
}

// ---------------------------------------------------------------------------
extern "C" void kernel_launch(void* const* d_in, const int* in_sizes, int n_in,
                              void* d_out, int out_size) {
    const float* z    = (const float*)d_in[0];   // [16,32,32,256]
    const float* E    = (const float*)d_in[1];   // [256, 8192]
    const float* cs   = (const float*)d_in[2];   // [8192]
    const float* eavg = (const float*)d_in[3];   // [256, 8192]
    float* out = (float*)d_out;

    static int cfg_done = 0;
    if (!cfg_done) {
        cudaFuncSetAttribute(k_argmin_mma,
                             cudaFuncAttributeMaxDynamicSharedMemorySize, SMEM_TOTAL);
        cfg_done = 1;
    }

    k_init   <<<(DIMS * NEMB + 255) / 256, 256>>>(eavg, out);
    k_conv_z <<<NROWS * DIMS / 256, 256>>>(z);
    {
        dim3 g(NEMB / 32, DIMS / 32), b(32, 8);
        k_prep_e<<<g, b>>>(E);
    }
    k_argmin_mma<<<NROWS / 128, 512, SMEM_TOTAL>>>();
    k_gather <<<NROWS / 8, 256>>>(z, out);
    k_ncs    <<<NEMB / 256, 256>>>(cs, out);
    k_final  <<<(DIMS * NEMB + 255) / 256, 256>>>(out);
}

// round 12
// speedup vs baseline: 9.6741x; 1.0708x over previous
#include <cuda_runtime.h>
#include <cuda_bf16.h>
#include <math_constants.h>
#include <stdint.h>

#define NROWS 16384
#define DIMS  256
#define NEMB  8192

// Output layout (float32, reference return order, flattened+concatenated)
#define OFF_Q    0
#define OFF_DIFF 4194304
#define OFF_IND  4194305
#define OFF_EMB  4210689
#define OFF_NCS  6307841
#define OFF_AVG  6316033

// Scratch (no cudaMalloc allowed)
__device__ float          g_enorm[NEMB];
__device__ int            g_count[NEMB];
__device__ float          g_n;
__device__ __nv_bfloat16  g_zhi[NROWS * DIMS];     // [row][k] bf16
__device__ __nv_bfloat16  g_ehi[NEMB * DIMS];      // [code][k] bf16 (transposed)
__device__ float          g_eT[NEMB * DIMS];       // [code][k] fp32 (transposed)

// ---------------------------------------------------------------------------
// PTX helpers — baseline sm_80+ features only (target is compute_103, no 'a').
// ---------------------------------------------------------------------------
__device__ __forceinline__ uint32_t smem_u32(const void* p) {
    uint32_t a;
    asm("{ .reg .u64 t; cvta.to.shared.u64 t, %1; cvt.u32.u64 %0, t; }" : "=r"(a) : "l"(p));
    return a;
}
__device__ __forceinline__ void cp_async16(uint32_t s, const void* g) {
    asm volatile("cp.async.ca.shared.global [%0], [%1], 16;" :: "r"(s), "l"(g));
}
#define CP_COMMIT() asm volatile("cp.async.commit_group;")
#define CP_WAIT0()  asm volatile("cp.async.wait_group 0;")
#define CP_WAIT1()  asm volatile("cp.async.wait_group 1;")

__device__ __forceinline__ void ldsm_x4(uint32_t* r, uint32_t a) {
    asm volatile("ldmatrix.sync.aligned.m8n8.x4.shared.b16 {%0,%1,%2,%3}, [%4];"
                 : "=r"(r[0]), "=r"(r[1]), "=r"(r[2]), "=r"(r[3]) : "r"(a));
}
__device__ __forceinline__ void mma16816(float* d, const uint32_t* a, const uint32_t* b) {
    asm volatile("mma.sync.aligned.m16n8k16.row.col.f32.bf16.bf16.f32 "
                 "{%0,%1,%2,%3}, {%4,%5,%6,%7}, {%8,%9}, {%0,%1,%2,%3};"
                 : "+f"(d[0]), "+f"(d[1]), "+f"(d[2]), "+f"(d[3])
                 : "r"(a[0]), "r"(a[1]), "r"(a[2]), "r"(a[3]), "r"(b[0]), "r"(b[1]));
}

// pack positive float distance with 7-bit local code in low mantissa bits
__device__ __forceinline__ float pack7(float d, uint32_t code) {
    return __uint_as_float((__float_as_uint(d) & 0xFFFFFF80u) | code);
}

// merge two ascending pairs (a0<=a1),(b0<=b1) -> smallest two (branch-free)
__device__ __forceinline__ void p2_merge(float& a0, float& a1, float b0, float b1) {
    float lo = fminf(a0, b0);
    a1 = fminf(fmaxf(a0, b0), fminf(a1, b1));
    a0 = lo;
}

// sorted top-4 insert (ascending); common case = 1 compare
__device__ __forceinline__ void t4_insert(float (&v)[4], int (&j)[4], float d, int c) {
    if (d < v[3]) {
        if (d < v[1]) {
            v[3] = v[2]; j[3] = j[2]; v[2] = v[1]; j[2] = j[1];
            if (d < v[0]) { v[1] = v[0]; j[1] = j[0]; v[0] = d; j[0] = c; }
            else          { v[1] = d; j[1] = c; }
        } else {
            if (d < v[2]) { v[3] = v[2]; j[3] = j[2]; v[2] = d; j[2] = c; }
            else          { v[3] = d; j[3] = c; }
        }
    }
}

// ---------------------------------------------------------------------------
// A: init — zero counters/enorm/diff/n; seed new_embedding_avg with 0.99*avg
// ---------------------------------------------------------------------------
__global__ void k_init(const float* __restrict__ eavg, float* __restrict__ out) {
    int i = blockIdx.x * blockDim.x + threadIdx.x;
    if (i < DIMS * NEMB) out[OFF_AVG + i] = 0.99f * eavg[i];
    if (i < NEMB) { g_count[i] = 0; g_enorm[i] = 0.0f; }
    if (i == 0) { g_n = 0.0f; out[OFF_DIFF] = 0.0f; }
}

// ---------------------------------------------------------------------------
// B: convert z to bf16
// ---------------------------------------------------------------------------
__global__ void k_conv_z(const float* __restrict__ z) {
    int i = blockIdx.x * blockDim.x + threadIdx.x;
    g_zhi[i] = __float2bfloat16(z[i]);
}

// ---------------------------------------------------------------------------
// B2: fused E prep: transpose to [j][k] (fp32 + bf16) and accumulate enorm.
// ---------------------------------------------------------------------------
__global__ void k_prep_e(const float* __restrict__ E) {
    __shared__ float t[32][33];
    int j0 = blockIdx.x * 32, k0 = blockIdx.y * 32;
    int tx = threadIdx.x, ty = threadIdx.y;
#pragma unroll
    for (int s = 0; s < 32; s += 8)
        t[ty + s][tx] = E[(size_t)(k0 + ty + s) * NEMB + j0 + tx];
    __syncthreads();
#pragma unroll
    for (int s = 0; s < 32; s += 8) {
        float x = t[tx][ty + s];
        size_t o = (size_t)(j0 + ty + s) * DIMS + k0 + tx;
        g_eT[o]  = x;
        g_ehi[o] = __float2bfloat16(x);
        float p = x * x;
#pragma unroll
        for (int w = 16; w; w >>= 1) p += __shfl_xor_sync(0xffffffffu, p, w);
        if (tx == 0) atomicAdd(&g_enorm[j0 + ty + s], p);
    }
}

// ---------------------------------------------------------------------------
// C: single-bf16 mma.sync GEMM + packed min-2 epilogue -> register top-4,
//    then FUSED exact-rescore gather tail.
//    512 threads, 16 warps (4m x 4n), warp tile 32x32; 64 jt epochs, ONE
//    barrier per epoch (merge-previous with double-buffered SM_RED).
//    LDSM addresses strength-reduced: 4 precomputed XOR offsets; +8192
//    immediates cover mt/p.
// ---------------------------------------------------------------------------
#define SM_A     0
#define SM_B     65536
#define SM_RED   196608     // 2 buffers x (128 rows x 5-pad x 8B) = 2 x 5120
#define SMEM_TOTAL 206848

#define PLANE_ADDR(r, c) ((r) * 512 + (((c) >> 3) << 7) + ((((c) & 7) ^ ((r) & 7)) << 4))

__global__ __launch_bounds__(512, 1) void k_argmin_mma(
    const float* __restrict__ z, float* __restrict__ out)
{
    extern __shared__ char smem[];
    const uint32_t sb = smem_u32(smem);
    const int tid = threadIdx.x, wid = tid >> 5, l = tid & 31;
    const int wm = wid >> 2, wn = wid & 3;
    const int row0 = blockIdx.x * 128;

    // stage resident A: 4096 x 16B
#pragma unroll
    for (int t = 0; t < 8; t++) {
        int i = tid + t * 512;
        int r = i >> 5, c = i & 31;
        cp_async16(sb + SM_A + PLANE_ADDR(r, c),
                   g_zhi + (size_t)(row0 + r) * DIMS + c * 8);
    }
    CP_COMMIT();

    auto stageB = [&](int jt) {
        const int buf = jt & 1;
#pragma unroll
        for (int t = 0; t < 8; t++) {
            int i = tid + t * 512;
            int r = i >> 5, c = i & 31;
            cp_async16(sb + SM_B + buf * 65536 + PLANE_ADDR(r, c),
                       g_ehi + (size_t)(jt * 128 + r) * DIMS + c * 8);
        }
        CP_COMMIT();
    };
    stageB(0);

    // persistent per-row top-4, in registers of threads 0..127 (row = tid)
    float pv[4] = {CUDART_INF_F, CUDART_INF_F, CUDART_INF_F, CUDART_INF_F};
    int   pj[4] = {0, 0, 0, 0};

    // fragment lane addressing
    const int arow = wm * 32 + (l & 15);                      // + mt*16
    const int acd  = l >> 4;
    const int brow = wn * 32 + ((l >> 4) << 3) + (l & 7);     // + p*16
    const int bcd  = (l >> 3) & 1;
    const int lc0  = wn * 32 + 2 * (l & 3);                   // local code base

    // strength-reduced LDSM offsets: for c = 2*t16 + cd (cd<=1),
    // c>>3 == t16>>2 (exact) and (c&7) = 2*(t16&3)+cd.
    uint32_t aoff[4], boff[4];
#pragma unroll
    for (int j = 0; j < 4; j++) {
        aoff[j] = (uint32_t)(((2 * j + acd) ^ (arow & 7)) << 4);
        boff[j] = (uint32_t)(((2 * j + bcd) ^ (brow & 7)) << 4);
    }
    const uint32_t abase  = sb + SM_A + arow * 512;
    const uint32_t bbase0 = sb + SM_B + brow * 512;

    const float2* RED0 = (const float2*)(smem + SM_RED);
    const float2* RED1 = (const float2*)(smem + SM_RED + 5120);

    for (int jt = 0; jt < 64; jt++) {
        const int buf = jt & 1;
        if (jt + 1 < 64) { stageB(jt + 1); CP_WAIT1(); } else { CP_WAIT0(); }
        __syncthreads();

        // merge PREVIOUS epoch's warp lists (warps 0-3 only; overlaps MMA of
        // warps 4-15). Hazards ordered by the single per-epoch barrier.
        if (jt > 0 && tid < 128) {
            const float2* src = ((jt & 1) ? RED0 : RED1) + tid * 5;
            float2 a = src[0], b = src[1], c = src[2], d = src[3];
            p2_merge(a.x, a.y, b.x, b.y);
            p2_merge(c.x, c.y, d.x, d.y);
            p2_merge(a.x, a.y, c.x, c.y);
            int cb = (jt - 1) * 128;
            t4_insert(pv, pj, a.x, cb + (__float_as_int(a.x) & 0x7F));
            t4_insert(pv, pj, a.y, cb + (__float_as_int(a.y) & 0x7F));
        }

        float acc[2][4][4];
#pragma unroll
        for (int mt = 0; mt < 2; mt++)
#pragma unroll
            for (int nt = 0; nt < 4; nt++)
#pragma unroll
                for (int e = 0; e < 4; e++) acc[mt][nt][e] = 0.0f;

        const uint32_t bbase = bbase0 + buf * 65536;
#pragma unroll
        for (int t16 = 0; t16 < 16; t16++) {
            const uint32_t g = (uint32_t)((t16 >> 2) << 7);
            uint32_t ba = bbase + g + boff[t16 & 3];
            uint32_t q0[4], q1[4];
            ldsm_x4(q0, ba);
            ldsm_x4(q1, ba + 8192);
            uint32_t aa = abase + g + aoff[t16 & 3];
            uint32_t a0[4], a1[4];
            ldsm_x4(a0, aa);
            ldsm_x4(a1, aa + 8192);
            mma16816(acc[0][0], a0, q0);
            mma16816(acc[0][1], a0, q0 + 2);
            mma16816(acc[0][2], a0, q1);
            mma16816(acc[0][3], a0, q1 + 2);
            mma16816(acc[1][0], a1, q0);
            mma16816(acc[1][1], a1, q0 + 2);
            mma16816(acc[1][2], a1, q1);
            mma16816(acc[1][3], a1, q1 + 2);
        }

        // epilogue: packed distances -> branch-free min2 tournament -> RED[buf]
        {
            float enx[4], eny[4];
#pragma unroll
            for (int nt = 0; nt < 4; nt++) {
                float2 en = __ldg((const float2*)&g_enorm[jt * 128 + lc0 + nt * 8]);
                enx[nt] = en.x + 512.0f;
                eny[nt] = en.y + 512.0f;
            }
#pragma unroll
            for (int mt = 0; mt < 2; mt++) {
#pragma unroll
                for (int h = 0; h < 2; h++) {
                    float p[8];
#pragma unroll
                    for (int nt = 0; nt < 4; nt++) {
                        uint32_t lc = lc0 + nt * 8;
                        p[2 * nt]     = pack7(fmaf(-2.0f, acc[mt][nt][h * 2],     enx[nt]), lc);
                        p[2 * nt + 1] = pack7(fmaf(-2.0f, acc[mt][nt][h * 2 + 1], eny[nt]), lc + 1);
                    }
                    float l0 = fminf(p[0], p[1]), h0 = fmaxf(p[0], p[1]);
                    float l1 = fminf(p[2], p[3]), h1 = fmaxf(p[2], p[3]);
                    float l2 = fminf(p[4], p[5]), h2 = fmaxf(p[4], p[5]);
                    float l3 = fminf(p[6], p[7]), h3 = fmaxf(p[6], p[7]);
                    p2_merge(l0, h0, l1, h1);
                    p2_merge(l2, h2, l3, h3);
                    p2_merge(l0, h0, l2, h2);
#pragma unroll
                    for (int o = 1; o <= 2; o <<= 1) {
                        float fl = __shfl_xor_sync(0xffffffffu, l0, o);
                        float fh = __shfl_xor_sync(0xffffffffu, h0, o);
                        p2_merge(l0, h0, fl, fh);
                    }
                    if ((l & 3) == 0) {
                        int rl = wm * 32 + mt * 16 + h * 8 + (l >> 2);
                        ((float2*)(smem + SM_RED + buf * 5120))[rl * 5 + wn] =
                            make_float2(l0, h0);
                    }
                }
            }
        }
    }

    __syncthreads();
    // final merge (jt=63, buffer 1) and hand candidates to all warps via smem
    if (tid < 128) {
        const float2* src = RED1 + tid * 5;
        float2 a = src[0], b = src[1], c = src[2], d = src[3];
        p2_merge(a.x, a.y, b.x, b.y);
        p2_merge(c.x, c.y, d.x, d.y);
        p2_merge(a.x, a.y, c.x, c.y);
        t4_insert(pv, pj, a.x, 63 * 128 + (__float_as_int(a.x) & 0x7F));
        t4_insert(pv, pj, a.y, 63 * 128 + (__float_as_int(a.y) & 0x7F));
        ((int4*)(smem + SM_RED))[tid] = make_int4(pj[0], pj[1], pj[2], pj[3]);
    }
    __syncthreads();

    // ---- fused gather: 16 warps x 8 rows; exact fp32 rescore + outputs ----
    float ssacc = 0.0f;
#pragma unroll 1
    for (int rr = 0; rr < 8; rr++) {
        const int rl = wid * 8 + rr;
        const int r  = row0 + rl;
        const int4 cand = ((const int4*)(smem + SM_RED))[rl];
        const int cj[4] = {cand.x, cand.y, cand.z, cand.w};

        float zv[8];
#pragma unroll
        for (int it = 0; it < 8; it++) zv[it] = z[(size_t)r * DIMS + l + it * 32];

        float dot[4] = {0.0f, 0.0f, 0.0f, 0.0f};
#pragma unroll
        for (int c = 0; c < 4; c++) {
            const float* e = g_eT + (size_t)cj[c] * DIMS;
#pragma unroll
            for (int it = 0; it < 8; it++)
                dot[c] = fmaf(zv[it], e[l + it * 32], dot[c]);
        }
#pragma unroll
        for (int c = 0; c < 4; c++)
#pragma unroll
            for (int o = 16; o; o >>= 1) dot[c] += __shfl_xor_sync(0xffffffffu, dot[c], o);

        int bj = cj[0];
        float bd = fmaf(-2.0f, dot[0], g_enorm[cj[0]]);
#pragma unroll
        for (int c = 1; c < 4; c++) {
            float d = fmaf(-2.0f, dot[c], g_enorm[cj[c]]);
            if (d < bd || (d == bd && cj[c] < bj)) { bd = d; bj = cj[c]; }
        }

        const float* eb = g_eT + (size_t)bj * DIMS;
        float ss = 0.0f;
#pragma unroll
        for (int it = 0; it < 8; it++) {
            int d = l + it * 32;
            float e = eb[d];
            float qd = e - zv[it];
            out[OFF_Q + (size_t)r * DIMS + d] = zv[it] + qd;
            ss = fmaf(qd, qd, ss);
            atomicAdd(&out[OFF_AVG + (size_t)d * NEMB + bj], 0.01f * zv[it]);
        }
        if (l == 0) {
            atomicAdd(&g_count[bj], 1);
            out[OFF_IND + r] = (float)bj;
        }
#pragma unroll
        for (int o = 16; o; o >>= 1) ss += __shfl_down_sync(0xffffffffu, ss, o);
        if (l == 0) ssacc += ss;
    }
    if (l == 0) atomicAdd(&out[OFF_DIFF], ssacc);
}

// ---------------------------------------------------------------------------
// E: new_cluster_size + global n reduction
// ---------------------------------------------------------------------------
__global__ void k_ncs(const float* __restrict__ cs, float* __restrict__ out) {
    __shared__ float sh[256];
    int j = blockIdx.x * 256 + threadIdx.x;
    float v = cs[j] * 0.99f + 0.01f * (float)g_count[j];
    out[OFF_NCS + j] = v;
    sh[threadIdx.x] = v;
    __syncthreads();
    for (int s = 128; s; s >>= 1) {
        if (threadIdx.x < s) sh[threadIdx.x] += sh[threadIdx.x + s];
        __syncthreads();
    }
    if (threadIdx.x == 0) atomicAdd(&g_n, sh[0]);
}

// ---------------------------------------------------------------------------
// F: new_embedding = avg / smoothed; finalize diff mean
// ---------------------------------------------------------------------------
__global__ void k_final(float* __restrict__ out) {
    int i = blockIdx.x * blockDim.x + threadIdx.x;
    if (i == 0) out[OFF_DIFF] *= (1.0f / 4194304.0f);
    if (i >= DIMS * NEMB) return;
    float n = g_n;
    int j = i & (NEMB - 1);
    float ncs = out[OFF_NCS + j];
    float smoothed = (ncs + 1e-5f) / (n + (float)NEMB * 1e-5f) * n;
    out[OFF_EMB + i] = out[OFF_AVG + i] / smoothed;
}

// ---------------------------------------------------------------------------
extern "C" void kernel_launch(void* const* d_in, const int* in_sizes, int n_in,
                              void* d_out, int out_size) {
    const float* z    = (const float*)d_in[0];   // [16,32,32,256]
    const float* E    = (const float*)d_in[1];   // [256, 8192]
    const float* cs   = (const float*)d_in[2];   // [8192]
    const float* eavg = (const float*)d_in[3];   // [256, 8192]
    float* out = (float*)d_out;

    static int cfg_done = 0;
    if (!cfg_done) {
        cudaFuncSetAttribute(k_argmin_mma,
                             cudaFuncAttributeMaxDynamicSharedMemorySize, SMEM_TOTAL);
        cfg_done = 1;
    }

    k_init   <<<(DIMS * NEMB + 255) / 256, 256>>>(eavg, out);
    k_conv_z <<<NROWS * DIMS / 256, 256>>>(z);
    {
        dim3 g(NEMB / 32, DIMS / 32), b(32, 8);
        k_prep_e<<<g, b>>>(E);
    }
    k_argmin_mma<<<NROWS / 128, 512, SMEM_TOTAL>>>(z, out);
    k_ncs    <<<NEMB / 256, 256>>>(cs, out);
    k_final  <<<(DIMS * NEMB + 255) / 256, 256>>>(out);
}

// round 13
// speedup vs baseline: 9.7497x; 1.0078x over previous
#include <cuda_runtime.h>
#include <cuda_bf16.h>
#include <math_constants.h>
#include <stdint.h>

#define NROWS 16384
#define DIMS  256
#define NEMB  8192

// Output layout (float32, reference return order, flattened+concatenated)
#define OFF_Q    0
#define OFF_DIFF 4194304
#define OFF_IND  4194305
#define OFF_EMB  4210689
#define OFF_NCS  6307841
#define OFF_AVG  6316033

// Scratch (no cudaMalloc allowed)
__device__ float          g_enorm[NEMB];
__device__ int            g_count[NEMB];
__device__ float          g_n;
__device__ __nv_bfloat16  g_zhi[NROWS * DIMS];     // [row][k] bf16
__device__ __nv_bfloat16  g_ehi[NEMB * DIMS];      // [code][k] bf16 (transposed)
__device__ float          g_eT[NEMB * DIMS];       // [code][k] fp32 (transposed)

// ---------------------------------------------------------------------------
// PTX helpers — baseline sm_80+ features only (target is compute_103, no 'a').
// ---------------------------------------------------------------------------
__device__ __forceinline__ uint32_t smem_u32(const void* p) {
    uint32_t a;
    asm("{ .reg .u64 t; cvta.to.shared.u64 t, %1; cvt.u32.u64 %0, t; }" : "=r"(a) : "l"(p));
    return a;
}
__device__ __forceinline__ void cp_async16(uint32_t s, const void* g) {
    asm volatile("cp.async.ca.shared.global [%0], [%1], 16;" :: "r"(s), "l"(g));
}
#define CP_COMMIT() asm volatile("cp.async.commit_group;")
#define CP_WAIT0()  asm volatile("cp.async.wait_group 0;")
#define CP_WAIT1()  asm volatile("cp.async.wait_group 1;")

__device__ __forceinline__ void bar_sync(int id) {
    asm volatile("bar.sync %0, 256;" :: "r"(id) : "memory");
}

__device__ __forceinline__ void ldsm_x4(uint32_t* r, uint32_t a) {
    asm volatile("ldmatrix.sync.aligned.m8n8.x4.shared.b16 {%0,%1,%2,%3}, [%4];"
                 : "=r"(r[0]), "=r"(r[1]), "=r"(r[2]), "=r"(r[3]) : "r"(a));
}
__device__ __forceinline__ void mma16816(float* d, const uint32_t* a, const uint32_t* b) {
    asm volatile("mma.sync.aligned.m16n8k16.row.col.f32.bf16.bf16.f32 "
                 "{%0,%1,%2,%3}, {%4,%5,%6,%7}, {%8,%9}, {%0,%1,%2,%3};"
                 : "+f"(d[0]), "+f"(d[1]), "+f"(d[2]), "+f"(d[3])
                 : "r"(a[0]), "r"(a[1]), "r"(a[2]), "r"(a[3]), "r"(b[0]), "r"(b[1]));
}

// pack positive float distance with 7-bit local code in low mantissa bits
__device__ __forceinline__ float pack7(float d, uint32_t code) {
    return __uint_as_float((__float_as_uint(d) & 0xFFFFFF80u) | code);
}

// merge two ascending pairs (a0<=a1),(b0<=b1) -> smallest two (branch-free)
__device__ __forceinline__ void p2_merge(float& a0, float& a1, float b0, float b1) {
    float lo = fminf(a0, b0);
    a1 = fminf(fmaxf(a0, b0), fminf(a1, b1));
    a0 = lo;
}

// sorted top-4 insert (ascending); common case = 1 compare
__device__ __forceinline__ void t4_insert(float (&v)[4], int (&j)[4], float d, int c) {
    if (d < v[3]) {
        if (d < v[1]) {
            v[3] = v[2]; j[3] = j[2]; v[2] = v[1]; j[2] = j[1];
            if (d < v[0]) { v[1] = v[0]; j[1] = j[0]; v[0] = d; j[0] = c; }
            else          { v[1] = d; j[1] = c; }
        } else {
            if (d < v[2]) { v[3] = v[2]; j[3] = j[2]; v[2] = d; j[2] = c; }
            else          { v[3] = d; j[3] = c; }
        }
    }
}

// ---------------------------------------------------------------------------
// A: init — zero counters/enorm/diff/n; seed new_embedding_avg with 0.99*avg
// ---------------------------------------------------------------------------
__global__ void k_init(const float* __restrict__ eavg, float* __restrict__ out) {
    int i = blockIdx.x * blockDim.x + threadIdx.x;
    if (i < DIMS * NEMB) out[OFF_AVG + i] = 0.99f * eavg[i];
    if (i < NEMB) { g_count[i] = 0; g_enorm[i] = 0.0f; }
    if (i == 0) { g_n = 0.0f; out[OFF_DIFF] = 0.0f; }
}

// ---------------------------------------------------------------------------
// B: convert z to bf16
// ---------------------------------------------------------------------------
__global__ void k_conv_z(const float* __restrict__ z) {
    int i = blockIdx.x * blockDim.x + threadIdx.x;
    g_zhi[i] = __float2bfloat16(z[i]);
}

// ---------------------------------------------------------------------------
// B2: fused E prep: transpose to [j][k] (fp32 + bf16) and accumulate enorm.
// ---------------------------------------------------------------------------
__global__ void k_prep_e(const float* __restrict__ E) {
    __shared__ float t[32][33];
    int j0 = blockIdx.x * 32, k0 = blockIdx.y * 32;
    int tx = threadIdx.x, ty = threadIdx.y;
#pragma unroll
    for (int s = 0; s < 32; s += 8)
        t[ty + s][tx] = E[(size_t)(k0 + ty + s) * NEMB + j0 + tx];
    __syncthreads();
#pragma unroll
    for (int s = 0; s < 32; s += 8) {
        float x = t[tx][ty + s];
        size_t o = (size_t)(j0 + ty + s) * DIMS + k0 + tx;
        g_eT[o]  = x;
        g_ehi[o] = __float2bfloat16(x);
        float p = x * x;
#pragma unroll
        for (int w = 16; w; w >>= 1) p += __shfl_xor_sync(0xffffffffu, p, w);
        if (tx == 0) atomicAdd(&g_enorm[j0 + ty + s], p);
    }
}

// ---------------------------------------------------------------------------
// C: split-barrier halves. 512 threads; warps 0-7 = half 0 (even 64-code
//    tiles), warps 8-15 = half 1 (odd tiles). Each half: own double-buffered
//    B (2x32KB), own SM_RED, own named barrier. Shared read-only A (64KB).
//    Warp tile 32x32 (mt=2, nt=4) exactly as R12. Per-tile packed min-2 ->
//    per-half register top-4 -> cross-half union -> global top-4 -> fused
//    exact fp32 rescore + gather tail.
// ---------------------------------------------------------------------------
#define SM_A     0
#define SM_B     65536       // + (half*2+buf)*32768
#define SM_RED   196608      // + (half*2+buf)*3072 ; entry rl*3+wn (float2)
#define SM_CAND  208896      // 256 x float4 (half1 pv/pj), then final int4
#define SMEM_TOTAL 212992

#define PLANE_ADDR(r, c) ((r) * 512 + (((c) >> 3) << 7) + ((((c) & 7) ^ ((r) & 7)) << 4))

__global__ __launch_bounds__(512, 1) void k_argmin_mma(
    const float* __restrict__ z, float* __restrict__ out)
{
    extern __shared__ char smem[];
    const uint32_t sb = smem_u32(smem);
    const int tid = threadIdx.x, wid = tid >> 5, l = tid & 31;
    const int half = wid >> 3, hw = wid & 7, htid = tid & 255;
    const int wm = hw >> 1, wn = hw & 1;
    const int row0 = blockIdx.x * 128;

    // stage resident A: 4096 x 16B (all 512 threads; group 0)
#pragma unroll
    for (int t = 0; t < 8; t++) {
        int i = tid + t * 512;
        int r = i >> 5, c = i & 31;
        cp_async16(sb + SM_A + PLANE_ADDR(r, c),
                   g_zhi + (size_t)(row0 + r) * DIMS + c * 8);
    }
    CP_COMMIT();

    // each half stages its own 64-row B tiles (tile index = 2*q + half)
    auto stageB = [&](int q) {
        const uint32_t base = sb + SM_B + (uint32_t)(half * 2 + (q & 1)) * 32768;
        const int tile = 2 * q + half;
#pragma unroll
        for (int t = 0; t < 8; t++) {
            int i = htid + t * 256;
            int r = i >> 5, c = i & 31;
            cp_async16(base + PLANE_ADDR(r, c),
                       g_ehi + (size_t)(tile * 64 + r) * DIMS + c * 8);
        }
        CP_COMMIT();
    };
    stageB(0);
    CP_WAIT1();          // A complete for this thread
    __syncthreads();     // A complete CTA-wide (both halves read all of A)

    // persistent per-row top-4 (threads htid<128 of each half, row = htid)
    float pv[4] = {CUDART_INF_F, CUDART_INF_F, CUDART_INF_F, CUDART_INF_F};
    int   pj[4] = {0, 0, 0, 0};

    // fragment lane addressing
    const int arow = wm * 32 + (l & 15);
    const int acd  = l >> 4;
    const int brow = wn * 32 + ((l >> 4) << 3) + (l & 7);
    const int bcd  = (l >> 3) & 1;
    const int lc0  = wn * 32 + 2 * (l & 3);

    uint32_t aoff[4], boff[4];
#pragma unroll
    for (int j = 0; j < 4; j++) {
        aoff[j] = (uint32_t)(((2 * j + acd) ^ (arow & 7)) << 4);
        boff[j] = (uint32_t)(((2 * j + bcd) ^ (brow & 7)) << 4);
    }
    const uint32_t abase  = sb + SM_A + arow * 512;
    const uint32_t bbase0 = sb + SM_B + (uint32_t)(half * 2) * 32768 + brow * 512;
    const uint32_t redb   = sb + SM_RED + (uint32_t)(half * 2) * 3072;

    for (int q = 0; q < 64; q++) {
        const int buf = q & 1;
        if (q + 1 < 64) { stageB(q + 1); CP_WAIT1(); } else { CP_WAIT0(); }
        bar_sync(half + 1);

        // merge previous tile's 2 warp lists (overlaps other warps' MMA)
        if (q > 0 && htid < 128) {
            const float2* src = (const float2*)(smem + (redb - sb) + ((q - 1) & 1) * 3072)
                                + htid * 3;
            float2 a = src[0], b = src[1];
            p2_merge(a.x, a.y, b.x, b.y);
            int cb = (2 * (q - 1) + half) * 64;
            t4_insert(pv, pj, a.x, cb + (__float_as_int(a.x) & 0x7F));
            t4_insert(pv, pj, a.y, cb + (__float_as_int(a.y) & 0x7F));
        }

        float acc[2][4][4];
#pragma unroll
        for (int mt = 0; mt < 2; mt++)
#pragma unroll
            for (int nt = 0; nt < 4; nt++)
#pragma unroll
                for (int e = 0; e < 4; e++) acc[mt][nt][e] = 0.0f;

        const uint32_t bbase = bbase0 + (uint32_t)buf * 32768;
#pragma unroll
        for (int t16 = 0; t16 < 16; t16++) {
            const uint32_t g = (uint32_t)((t16 >> 2) << 7);
            uint32_t ba = bbase + g + boff[t16 & 3];
            uint32_t q0[4], q1[4];
            ldsm_x4(q0, ba);
            ldsm_x4(q1, ba + 8192);
            uint32_t aa = abase + g + aoff[t16 & 3];
            uint32_t a0[4], a1[4];
            ldsm_x4(a0, aa);
            ldsm_x4(a1, aa + 8192);
            mma16816(acc[0][0], a0, q0);
            mma16816(acc[0][1], a0, q0 + 2);
            mma16816(acc[0][2], a0, q1);
            mma16816(acc[0][3], a0, q1 + 2);
            mma16816(acc[1][0], a1, q0);
            mma16816(acc[1][1], a1, q0 + 2);
            mma16816(acc[1][2], a1, q1);
            mma16816(acc[1][3], a1, q1 + 2);
        }

        // epilogue: packed distances -> branch-free min2 tournament -> RED[buf]
        {
            const int tile = 2 * q + half;
            float enx[4], eny[4];
#pragma unroll
            for (int nt = 0; nt < 4; nt++) {
                float2 en = __ldg((const float2*)&g_enorm[tile * 64 + lc0 + nt * 8]);
                enx[nt] = en.x + 512.0f;
                eny[nt] = en.y + 512.0f;
            }
#pragma unroll
            for (int mt = 0; mt < 2; mt++) {
#pragma unroll
                for (int h = 0; h < 2; h++) {
                    float p[8];
#pragma unroll
                    for (int nt = 0; nt < 4; nt++) {
                        uint32_t lc = lc0 + nt * 8;
                        p[2 * nt]     = pack7(fmaf(-2.0f, acc[mt][nt][h * 2],     enx[nt]), lc);
                        p[2 * nt + 1] = pack7(fmaf(-2.0f, acc[mt][nt][h * 2 + 1], eny[nt]), lc + 1);
                    }
                    float l0 = fminf(p[0], p[1]), h0 = fmaxf(p[0], p[1]);
                    float l1 = fminf(p[2], p[3]), h1 = fmaxf(p[2], p[3]);
                    float l2 = fminf(p[4], p[5]), h2 = fmaxf(p[4], p[5]);
                    float l3 = fminf(p[6], p[7]), h3 = fmaxf(p[6], p[7]);
                    p2_merge(l0, h0, l1, h1);
                    p2_merge(l2, h2, l3, h3);
                    p2_merge(l0, h0, l2, h2);
#pragma unroll
                    for (int o = 1; o <= 2; o <<= 1) {
                        float fl = __shfl_xor_sync(0xffffffffu, l0, o);
                        float fh = __shfl_xor_sync(0xffffffffu, h0, o);
                        p2_merge(l0, h0, fl, fh);
                    }
                    if ((l & 3) == 0) {
                        int rl = wm * 32 + mt * 16 + h * 8 + (l >> 2);
                        ((float2*)(smem + (redb - sb) + buf * 3072))[rl * 3 + wn] =
                            make_float2(l0, h0);
                    }
                }
            }
        }
    }

    bar_sync(half + 1);
    // merge last tile (q=63, buf=1)
    if (htid < 128) {
        const float2* src = (const float2*)(smem + (redb - sb) + 3072) + htid * 3;
        float2 a = src[0], b = src[1];
        p2_merge(a.x, a.y, b.x, b.y);
        int cb = (2 * 63 + half) * 64;
        t4_insert(pv, pj, a.x, cb + (__float_as_int(a.x) & 0x7F));
        t4_insert(pv, pj, a.y, cb + (__float_as_int(a.y) & 0x7F));
    }
    // half 1 publishes its top-4 (values + codes)
    if (half == 1 && htid < 128) {
        float4* cnd = (float4*)(smem + SM_CAND);
        cnd[htid]       = make_float4(pv[0], pv[1], pv[2], pv[3]);
        cnd[128 + htid] = make_float4(__int_as_float(pj[0]), __int_as_float(pj[1]),
                                      __int_as_float(pj[2]), __int_as_float(pj[3]));
    }
    __syncthreads();
    // half 0's first 128 threads union-merge -> global top-4 -> final cand
    if (tid < 128) {
        const float4* cnd = (const float4*)(smem + SM_CAND);
        float4 f = cnd[tid], ii = cnd[128 + tid];
        t4_insert(pv, pj, f.x, __float_as_int(ii.x));
        t4_insert(pv, pj, f.y, __float_as_int(ii.y));
        t4_insert(pv, pj, f.z, __float_as_int(ii.z));
        t4_insert(pv, pj, f.w, __float_as_int(ii.w));
        ((int4*)(smem + SM_CAND))[tid] = make_int4(pj[0], pj[1], pj[2], pj[3]);
    }
    __syncthreads();

    // ---- fused gather: 16 warps x 8 rows; exact fp32 rescore + outputs ----
    float ssacc = 0.0f;
#pragma unroll 1
    for (int rr = 0; rr < 8; rr++) {
        const int rl = wid * 8 + rr;
        const int r  = row0 + rl;
        const int4 cand = ((const int4*)(smem + SM_CAND))[rl];
        const int cj[4] = {cand.x, cand.y, cand.z, cand.w};

        float zv[8];
#pragma unroll
        for (int it = 0; it < 8; it++) zv[it] = z[(size_t)r * DIMS + l + it * 32];

        float dot[4] = {0.0f, 0.0f, 0.0f, 0.0f};
#pragma unroll
        for (int c = 0; c < 4; c++) {
            const float* e = g_eT + (size_t)cj[c] * DIMS;
#pragma unroll
            for (int it = 0; it < 8; it++)
                dot[c] = fmaf(zv[it], e[l + it * 32], dot[c]);
        }
#pragma unroll
        for (int c = 0; c < 4; c++)
#pragma unroll
            for (int o = 16; o; o >>= 1) dot[c] += __shfl_xor_sync(0xffffffffu, dot[c], o);

        int bj = cj[0];
        float bd = fmaf(-2.0f, dot[0], g_enorm[cj[0]]);
#pragma unroll
        for (int c = 1; c < 4; c++) {
            float d = fmaf(-2.0f, dot[c], g_enorm[cj[c]]);
            if (d < bd || (d == bd && cj[c] < bj)) { bd = d; bj = cj[c]; }
        }

        const float* eb = g_eT + (size_t)bj * DIMS;
        float ss = 0.0f;
#pragma unroll
        for (int it = 0; it < 8; it++) {
            int d = l + it * 32;
            float e = eb[d];
            float qd = e - zv[it];
            out[OFF_Q + (size_t)r * DIMS + d] = zv[it] + qd;
            ss = fmaf(qd, qd, ss);
            atomicAdd(&out[OFF_AVG + (size_t)d * NEMB + bj], 0.01f * zv[it]);
        }
        if (l == 0) {
            atomicAdd(&g_count[bj], 1);
            out[OFF_IND + r] = (float)bj;
        }
#pragma unroll
        for (int o = 16; o; o >>= 1) ss += __shfl_down_sync(0xffffffffu, ss, o);
        if (l == 0) ssacc += ss;
    }
    if (l == 0) atomicAdd(&out[OFF_DIFF], ssacc);
}

// ---------------------------------------------------------------------------
// E: new_cluster_size + global n reduction
// ---------------------------------------------------------------------------
__global__ void k_ncs(const float* __restrict__ cs, float* __restrict__ out) {
    __shared__ float sh[256];
    int j = blockIdx.x * 256 + threadIdx.x;
    float v = cs[j] * 0.99f + 0.01f * (float)g_count[j];
    out[OFF_NCS + j] = v;
    sh[threadIdx.x] = v;
    __syncthreads();
    for (int s = 128; s; s >>= 1) {
        if (threadIdx.x < s) sh[threadIdx.x] += sh[threadIdx.x + s];
        __syncthreads();
    }
    if (threadIdx.x == 0) atomicAdd(&g_n, sh[0]);
}

// ---------------------------------------------------------------------------
// F: new_embedding = avg / smoothed; finalize diff mean
// ---------------------------------------------------------------------------
__global__ void k_final(float* __restrict__ out) {
    int i = blockIdx.x * blockDim.x + threadIdx.x;
    if (i == 0) out[OFF_DIFF] *= (1.0f / 4194304.0f);
    if (i >= DIMS * NEMB) return;
    float n = g_n;
    int j = i & (NEMB - 1);
    float ncs = out[OFF_NCS + j];
    float smoothed = (ncs + 1e-5f) / (n + (float)NEMB * 1e-5f) * n;
    out[OFF_EMB + i] = out[OFF_AVG + i] / smoothed;
}

// ---------------------------------------------------------------------------
extern "C" void kernel_launch(void* const* d_in, const int* in_sizes, int n_in,
                              void* d_out, int out_size) {
    const float* z    = (const float*)d_in[0];   // [16,32,32,256]
    const float* E    = (const float*)d_in[1];   // [256, 8192]
    const float* cs   = (const float*)d_in[2];   // [8192]
    const float* eavg = (const float*)d_in[3];   // [256, 8192]
    float* out = (float*)d_out;

    static int cfg_done = 0;
    if (!cfg_done) {
        cudaFuncSetAttribute(k_argmin_mma,
                             cudaFuncAttributeMaxDynamicSharedMemorySize, SMEM_TOTAL);
        cfg_done = 1;
    }

    k_init   <<<(DIMS * NEMB + 255) / 256, 256>>>(eavg, out);
    k_conv_z <<<NROWS * DIMS / 256, 256>>>(z);
    {
        dim3 g(NEMB / 32, DIMS / 32), b(32, 8);
        k_prep_e<<<g, b>>>(E);
    }
    k_argmin_mma<<<NROWS / 128, 512, SMEM_TOTAL>>>(z, out);
    k_ncs    <<<NEMB / 256, 256>>>(cs, out);
    k_final  <<<(DIMS * NEMB + 255) / 256, 256>>>(out);
}

// round 14
// speedup vs baseline: 10.7167x; 1.0992x over previous
#include <cuda_runtime.h>
#include <cuda_bf16.h>
#include <math_constants.h>
#include <stdint.h>

#define NROWS 16384
#define DIMS  256
#define NEMB  8192

// Output layout (float32, reference return order, flattened+concatenated)
#define OFF_Q    0
#define OFF_DIFF 4194304
#define OFF_IND  4194305
#define OFF_EMB  4210689
#define OFF_NCS  6307841
#define OFF_AVG  6316033

// swizzled plane layout: row r (0..127 for A, 0..63 for B), 16B chunk c (0..31)
#define PLANE_ADDR(r, c) ((r) * 512 + (((c) >> 3) << 7) + ((((c) & 7) ^ ((r) & 7)) << 4))

// Scratch (no cudaMalloc allowed). g_zhi/g_ehi hold PRE-SWIZZLED tile layouts
// so cp.async.bulk can stage them linearly.
__device__ float g_enorm[NEMB];
__device__ int   g_count[NEMB];
__device__ float g_n;
__device__ __align__(128) __nv_bfloat16 g_zhi[NROWS * DIMS];  // [blk128][plane 64KB]
__device__ __align__(128) __nv_bfloat16 g_ehi[NEMB * DIMS];   // [tile64][plane 32KB]
__device__ float g_eT[NEMB * DIMS];                            // [code][k] fp32 linear

// ---------------------------------------------------------------------------
// PTX helpers — baseline sm_80/sm_90 features only (target compute_103, no 'a').
// ---------------------------------------------------------------------------
__device__ __forceinline__ uint32_t smem_u32(const void* p) {
    uint32_t a;
    asm("{ .reg .u64 t; cvta.to.shared.u64 t, %1; cvt.u32.u64 %0, t; }" : "=r"(a) : "l"(p));
    return a;
}
__device__ __forceinline__ void bar_sync(int id) {
    asm volatile("bar.sync %0, 256;" :: "r"(id) : "memory");
}
__device__ __forceinline__ void mbar_init(uint32_t a, uint32_t cnt) {
    asm volatile("mbarrier.init.shared.b64 [%0], %1;" :: "r"(a), "r"(cnt) : "memory");
}
__device__ __forceinline__ void mbar_expect_tx(uint32_t a, uint32_t bytes) {
    asm volatile("mbarrier.arrive.expect_tx.shared.b64 _, [%0], %1;"
                 :: "r"(a), "r"(bytes) : "memory");
}
__device__ __forceinline__ void bulk_g2s(uint32_t dst, const void* src,
                                         uint32_t bytes, uint32_t mbar) {
    asm volatile("cp.async.bulk.shared::cta.global.mbarrier::complete_tx::bytes "
                 "[%0], [%1], %2, [%3];"
                 :: "r"(dst), "l"(src), "r"(bytes), "r"(mbar) : "memory");
}
#define MBAR_WAIT(a, p) do {                                                     \
    uint32_t _m = (a), _p = (p), _d;                                             \
    asm volatile("{\n\t.reg .pred q;\n\t"                                        \
        "mbarrier.try_wait.parity.acquire.cta.shared::cta.b64 q, [%1], %2;\n\t"  \
        "selp.b32 %0, 1, 0, q;\n\t}" : "=r"(_d) : "r"(_m), "r"(_p) : "memory");  \
    if (!_d) {                                                                   \
        asm volatile("{\n\t.reg .pred Q;\n\tWL_%=:\n\t"                          \
            "mbarrier.try_wait.parity.acquire.cta.shared::cta.b64 Q, [%0], %1, 0x989680;\n\t" \
            "@Q bra.uni WD_%=;\n\tbra.uni WL_%=;\n\tWD_%=:\n\t}"                 \
            :: "r"(_m), "r"(_p) : "memory");                                     \
    }                                                                            \
} while (0)

__device__ __forceinline__ void ldsm_x4(uint32_t* r, uint32_t a) {
    asm volatile("ldmatrix.sync.aligned.m8n8.x4.shared.b16 {%0,%1,%2,%3}, [%4];"
                 : "=r"(r[0]), "=r"(r[1]), "=r"(r[2]), "=r"(r[3]) : "r"(a));
}
__device__ __forceinline__ void mma16816(float* d, const uint32_t* a, const uint32_t* b) {
    asm volatile("mma.sync.aligned.m16n8k16.row.col.f32.bf16.bf16.f32 "
                 "{%0,%1,%2,%3}, {%4,%5,%6,%7}, {%8,%9}, {%0,%1,%2,%3};"
                 : "+f"(d[0]), "+f"(d[1]), "+f"(d[2]), "+f"(d[3])
                 : "r"(a[0]), "r"(a[1]), "r"(a[2]), "r"(a[3]), "r"(b[0]), "r"(b[1]));
}

// pack positive float distance with 7-bit local code in low mantissa bits
__device__ __forceinline__ float pack7(float d, uint32_t code) {
    return __uint_as_float((__float_as_uint(d) & 0xFFFFFF80u) | code);
}

// merge two ascending pairs (a0<=a1),(b0<=b1) -> smallest two (branch-free)
__device__ __forceinline__ void p2_merge(float& a0, float& a1, float b0, float b1) {
    float lo = fminf(a0, b0);
    a1 = fminf(fmaxf(a0, b0), fminf(a1, b1));
    a0 = lo;
}

// sorted top-4 insert (ascending); common case = 1 compare
__device__ __forceinline__ void t4_insert(float (&v)[4], int (&j)[4], float d, int c) {
    if (d < v[3]) {
        if (d < v[1]) {
            v[3] = v[2]; j[3] = j[2]; v[2] = v[1]; j[2] = j[1];
            if (d < v[0]) { v[1] = v[0]; j[1] = j[0]; v[0] = d; j[0] = c; }
            else          { v[1] = d; j[1] = c; }
        } else {
            if (d < v[2]) { v[3] = v[2]; j[3] = j[2]; v[2] = d; j[2] = c; }
            else          { v[3] = d; j[3] = c; }
        }
    }
}

// ---------------------------------------------------------------------------
// A: init — zero counters/enorm/diff/n; seed new_embedding_avg with 0.99*avg
// ---------------------------------------------------------------------------
__global__ void k_init(const float* __restrict__ eavg, float* __restrict__ out) {
    int i = blockIdx.x * blockDim.x + threadIdx.x;
    if (i < DIMS * NEMB) out[OFF_AVG + i] = 0.99f * eavg[i];
    if (i < NEMB) { g_count[i] = 0; g_enorm[i] = 0.0f; }
    if (i == 0) { g_n = 0.0f; out[OFF_DIFF] = 0.0f; }
}

// ---------------------------------------------------------------------------
// B: convert z to bf16, writing the pre-swizzled 128-row plane layout
// ---------------------------------------------------------------------------
__global__ void k_conv_z(const float* __restrict__ z) {
    int i = blockIdx.x * blockDim.x + threadIdx.x;
    int row = i >> 8, k = i & 255;
    int blk = row >> 7, r = row & 127, c = k >> 3;
    uint32_t off = (uint32_t)blk * 65536 + PLANE_ADDR(r, c) + (k & 7) * 2;
    *(__nv_bfloat16*)((char*)g_zhi + off) = __float2bfloat16(z[i]);
}

// ---------------------------------------------------------------------------
// B2: fused E prep: transpose to [j][k]; bf16 goes to pre-swizzled 64-row
//     tiles; fp32 stays linear; accumulate enorm.
// ---------------------------------------------------------------------------
__global__ void k_prep_e(const float* __restrict__ E) {
    __shared__ float t[32][33];
    int j0 = blockIdx.x * 32, k0 = blockIdx.y * 32;
    int tx = threadIdx.x, ty = threadIdx.y;
#pragma unroll
    for (int s = 0; s < 32; s += 8)
        t[ty + s][tx] = E[(size_t)(k0 + ty + s) * NEMB + j0 + tx];
    __syncthreads();
#pragma unroll
    for (int s = 0; s < 32; s += 8) {
        float x = t[tx][ty + s];
        int j = j0 + ty + s, k = k0 + tx;
        g_eT[(size_t)j * DIMS + k] = x;
        uint32_t off = (uint32_t)(j >> 6) * 32768 + PLANE_ADDR(j & 63, k >> 3) + (k & 7) * 2;
        *(__nv_bfloat16*)((char*)g_ehi + off) = __float2bfloat16(x);
        float p = x * x;
#pragma unroll
        for (int w = 16; w; w >>= 1) p += __shfl_xor_sync(0xffffffffu, p, w);
        if (tx == 0) atomicAdd(&g_enorm[j], p);
    }
}

// ---------------------------------------------------------------------------
// C: split-barrier halves, cp.async.bulk staging (one UBLKCP per tile).
//    512 threads; warps 0-7 = half 0 (even 64-code tiles), 8-15 = half 1.
//    Warp tile 32x32 (mt=2, nt=4). Packed min-2 -> per-half top-4 ->
//    cross-half union -> fused exact fp32 rescore + gather tail.
// ---------------------------------------------------------------------------
#define SM_A     0
#define SM_B     65536       // + (half*2+buf)*32768
#define SM_RED   196608      // + half*2*3072 + buf*3072 ; entry rl*3+wn (float2)
#define SM_CAND  208896      // 256 x float4 (half1 pv/pj), then final int4
#define SM_MBAR  212992      // A @ +0; B @ +8 + (half*2+buf)*8
#define SMEM_TOTAL 213504

__global__ __launch_bounds__(512, 1) void k_argmin_mma(
    const float* __restrict__ z, float* __restrict__ out)
{
    extern __shared__ char smem[];
    const uint32_t sb = smem_u32(smem);
    const int tid = threadIdx.x, wid = tid >> 5, l = tid & 31;
    const int half = wid >> 3, hw = wid & 7, htid = tid & 255;
    const int wm = hw >> 1, wn = hw & 1;
    const int row0 = blockIdx.x * 128;

    if (tid == 0) {
        mbar_init(sb + SM_MBAR, 1);
#pragma unroll
        for (int b = 0; b < 4; b++) mbar_init(sb + SM_MBAR + 8 + b * 8, 1);
    }
    __syncthreads();

    // stage A (64KB, this CTA's 128-row block) and B tile 0 of each half
    if (tid == 0) {
        mbar_expect_tx(sb + SM_MBAR, 65536);
        bulk_g2s(sb + SM_A, (const char*)g_zhi + (size_t)blockIdx.x * 65536,
                 65536, sb + SM_MBAR);
    }
    if (htid == 0) {
        uint32_t mb = sb + SM_MBAR + 8 + (uint32_t)(half * 2) * 8;
        mbar_expect_tx(mb, 32768);
        bulk_g2s(sb + SM_B + (uint32_t)(half * 2) * 32768,
                 (const char*)g_ehi + (size_t)half * 32768, 32768, mb);
    }

    // persistent per-row top-4 (threads htid<128 of each half, row = htid)
    float pv[4] = {CUDART_INF_F, CUDART_INF_F, CUDART_INF_F, CUDART_INF_F};
    int   pj[4] = {0, 0, 0, 0};

    // fragment lane addressing
    const int arow = wm * 32 + (l & 15);
    const int acd  = l >> 4;
    const int brow = wn * 32 + ((l >> 4) << 3) + (l & 7);
    const int bcd  = (l >> 3) & 1;
    const int lc0  = wn * 32 + 2 * (l & 3);

    uint32_t aoff[4], boff[4];
#pragma unroll
    for (int j = 0; j < 4; j++) {
        aoff[j] = (uint32_t)(((2 * j + acd) ^ (arow & 7)) << 4);
        boff[j] = (uint32_t)(((2 * j + bcd) ^ (brow & 7)) << 4);
    }
    const uint32_t abase  = sb + SM_A + arow * 512;
    const uint32_t bbase0 = sb + SM_B + (uint32_t)(half * 2) * 32768 + brow * 512;
    const uint32_t redb   = sb + SM_RED + (uint32_t)(half * 2) * 3072;

    MBAR_WAIT(sb + SM_MBAR, 0);   // A resident

    for (int q = 0; q < 64; q++) {
        const int buf = q & 1;
        bar_sync(half + 1);   // all half-warps done with epoch q-1 (reads+RED)

        // prefetch next tile (single bulk op; buffer free per the barrier)
        if (q + 1 < 64 && htid == 0) {
            const int nb = (q + 1) & 1;
            uint32_t mb = sb + SM_MBAR + 8 + (uint32_t)(half * 2 + nb) * 8;
            mbar_expect_tx(mb, 32768);
            bulk_g2s(sb + SM_B + (uint32_t)(half * 2 + nb) * 32768,
                     (const char*)g_ehi + (size_t)(2 * (q + 1) + half) * 32768,
                     32768, mb);
        }

        // merge previous tile's 2 warp lists (overlaps other warps' progress)
        if (q > 0 && htid < 128) {
            const float2* src = (const float2*)(smem + (redb - sb) + ((q - 1) & 1) * 3072)
                                + htid * 3;
            float2 a = src[0], b = src[1];
            p2_merge(a.x, a.y, b.x, b.y);
            int cb = (2 * (q - 1) + half) * 64;
            t4_insert(pv, pj, a.x, cb + (__float_as_int(a.x) & 0x7F));
            t4_insert(pv, pj, a.y, cb + (__float_as_int(a.y) & 0x7F));
        }

        // wait for this epoch's B tile
        MBAR_WAIT(sb + SM_MBAR + 8 + (uint32_t)(half * 2 + buf) * 8, (q >> 1) & 1);

        float acc[2][4][4];
#pragma unroll
        for (int mt = 0; mt < 2; mt++)
#pragma unroll
            for (int nt = 0; nt < 4; nt++)
#pragma unroll
                for (int e = 0; e < 4; e++) acc[mt][nt][e] = 0.0f;

        const uint32_t bbase = bbase0 + (uint32_t)buf * 32768;
#pragma unroll
        for (int t16 = 0; t16 < 16; t16++) {
            const uint32_t g = (uint32_t)((t16 >> 2) << 7);
            uint32_t ba = bbase + g + boff[t16 & 3];
            uint32_t q0[4], q1[4];
            ldsm_x4(q0, ba);
            ldsm_x4(q1, ba + 8192);
            uint32_t aa = abase + g + aoff[t16 & 3];
            uint32_t a0[4], a1[4];
            ldsm_x4(a0, aa);
            ldsm_x4(a1, aa + 8192);
            mma16816(acc[0][0], a0, q0);
            mma16816(acc[0][1], a0, q0 + 2);
            mma16816(acc[0][2], a0, q1);
            mma16816(acc[0][3], a0, q1 + 2);
            mma16816(acc[1][0], a1, q0);
            mma16816(acc[1][1], a1, q0 + 2);
            mma16816(acc[1][2], a1, q1);
            mma16816(acc[1][3], a1, q1 + 2);
        }

        // epilogue: packed distances -> branch-free min2 tournament -> RED[buf]
        {
            const int tile = 2 * q + half;
            float enx[4], eny[4];
#pragma unroll
            for (int nt = 0; nt < 4; nt++) {
                float2 en = __ldg((const float2*)&g_enorm[tile * 64 + lc0 + nt * 8]);
                enx[nt] = en.x + 512.0f;
                eny[nt] = en.y + 512.0f;
            }
#pragma unroll
            for (int mt = 0; mt < 2; mt++) {
#pragma unroll
                for (int h = 0; h < 2; h++) {
                    float p[8];
#pragma unroll
                    for (int nt = 0; nt < 4; nt++) {
                        uint32_t lc = lc0 + nt * 8;
                        p[2 * nt]     = pack7(fmaf(-2.0f, acc[mt][nt][h * 2],     enx[nt]), lc);
                        p[2 * nt + 1] = pack7(fmaf(-2.0f, acc[mt][nt][h * 2 + 1], eny[nt]), lc + 1);
                    }
                    float l0 = fminf(p[0], p[1]), h0 = fmaxf(p[0], p[1]);
                    float l1 = fminf(p[2], p[3]), h1 = fmaxf(p[2], p[3]);
                    float l2 = fminf(p[4], p[5]), h2 = fmaxf(p[4], p[5]);
                    float l3 = fminf(p[6], p[7]), h3 = fmaxf(p[6], p[7]);
                    p2_merge(l0, h0, l1, h1);
                    p2_merge(l2, h2, l3, h3);
                    p2_merge(l0, h0, l2, h2);
#pragma unroll
                    for (int o = 1; o <= 2; o <<= 1) {
                        float fl = __shfl_xor_sync(0xffffffffu, l0, o);
                        float fh = __shfl_xor_sync(0xffffffffu, h0, o);
                        p2_merge(l0, h0, fl, fh);
                    }
                    if ((l & 3) == 0) {
                        int rl = wm * 32 + mt * 16 + h * 8 + (l >> 2);
                        ((float2*)(smem + (redb - sb) + buf * 3072))[rl * 3 + wn] =
                            make_float2(l0, h0);
                    }
                }
            }
        }
    }

    bar_sync(half + 1);
    // merge last tile (q=63, buf=1)
    if (htid < 128) {
        const float2* src = (const float2*)(smem + (redb - sb) + 3072) + htid * 3;
        float2 a = src[0], b = src[1];
        p2_merge(a.x, a.y, b.x, b.y);
        int cb = (2 * 63 + half) * 64;
        t4_insert(pv, pj, a.x, cb + (__float_as_int(a.x) & 0x7F));
        t4_insert(pv, pj, a.y, cb + (__float_as_int(a.y) & 0x7F));
    }
    // half 1 publishes its top-4 (values + codes)
    if (half == 1 && htid < 128) {
        float4* cnd = (float4*)(smem + SM_CAND);
        cnd[htid]       = make_float4(pv[0], pv[1], pv[2], pv[3]);
        cnd[128 + htid] = make_float4(__int_as_float(pj[0]), __int_as_float(pj[1]),
                                      __int_as_float(pj[2]), __int_as_float(pj[3]));
    }
    __syncthreads();
    // half 0's first 128 threads union-merge -> global top-4 -> final cand
    if (tid < 128) {
        const float4* cnd = (const float4*)(smem + SM_CAND);
        float4 f = cnd[tid], ii = cnd[128 + tid];
        t4_insert(pv, pj, f.x, __float_as_int(ii.x));
        t4_insert(pv, pj, f.y, __float_as_int(ii.y));
        t4_insert(pv, pj, f.z, __float_as_int(ii.z));
        t4_insert(pv, pj, f.w, __float_as_int(ii.w));
        ((int4*)(smem + SM_CAND))[tid] = make_int4(pj[0], pj[1], pj[2], pj[3]);
    }
    __syncthreads();

    // ---- fused gather: 16 warps x 8 rows; exact fp32 rescore + outputs ----
    float ssacc = 0.0f;
#pragma unroll 1
    for (int rr = 0; rr < 8; rr++) {
        const int rl = wid * 8 + rr;
        const int r  = row0 + rl;
        const int4 cand = ((const int4*)(smem + SM_CAND))[rl];
        const int cj[4] = {cand.x, cand.y, cand.z, cand.w};

        float zv[8];
#pragma unroll
        for (int it = 0; it < 8; it++) zv[it] = z[(size_t)r * DIMS + l + it * 32];

        float dot[4] = {0.0f, 0.0f, 0.0f, 0.0f};
#pragma unroll
        for (int c = 0; c < 4; c++) {
            const float* e = g_eT + (size_t)cj[c] * DIMS;
#pragma unroll
            for (int it = 0; it < 8; it++)
                dot[c] = fmaf(zv[it], e[l + it * 32], dot[c]);
        }
#pragma unroll
        for (int c = 0; c < 4; c++)
#pragma unroll
            for (int o = 16; o; o >>= 1) dot[c] += __shfl_xor_sync(0xffffffffu, dot[c], o);

        int bj = cj[0];
        float bd = fmaf(-2.0f, dot[0], g_enorm[cj[0]]);
#pragma unroll
        for (int c = 1; c < 4; c++) {
            float d = fmaf(-2.0f, dot[c], g_enorm[cj[c]]);
            if (d < bd || (d == bd && cj[c] < bj)) { bd = d; bj = cj[c]; }
        }

        const float* eb = g_eT + (size_t)bj * DIMS;
        float ss = 0.0f;
#pragma unroll
        for (int it = 0; it < 8; it++) {
            int d = l + it * 32;
            float e = eb[d];
            float qd = e - zv[it];
            out[OFF_Q + (size_t)r * DIMS + d] = zv[it] + qd;
            ss = fmaf(qd, qd, ss);
            atomicAdd(&out[OFF_AVG + (size_t)d * NEMB + bj], 0.01f * zv[it]);
        }
        if (l == 0) {
            atomicAdd(&g_count[bj], 1);
            out[OFF_IND + r] = (float)bj;
        }
#pragma unroll
        for (int o = 16; o; o >>= 1) ss += __shfl_down_sync(0xffffffffu, ss, o);
        if (l == 0) ssacc += ss;
    }
    if (l == 0) atomicAdd(&out[OFF_DIFF], ssacc);
}

// ---------------------------------------------------------------------------
// E: new_cluster_size + global n reduction
// ---------------------------------------------------------------------------
__global__ void k_ncs(const float* __restrict__ cs, float* __restrict__ out) {
    __shared__ float sh[256];
    int j = blockIdx.x * 256 + threadIdx.x;
    float v = cs[j] * 0.99f + 0.01f * (float)g_count[j];
    out[OFF_NCS + j] = v;
    sh[threadIdx.x] = v;
    __syncthreads();
    for (int s = 128; s; s >>= 1) {
        if (threadIdx.x < s) sh[threadIdx.x] += sh[threadIdx.x + s];
        __syncthreads();
    }
    if (threadIdx.x == 0) atomicAdd(&g_n, sh[0]);
}

// ---------------------------------------------------------------------------
// F: new_embedding = avg / smoothed; finalize diff mean
// ---------------------------------------------------------------------------
__global__ void k_final(float* __restrict__ out) {
    int i = blockIdx.x * blockDim.x + threadIdx.x;
    if (i == 0) out[OFF_DIFF] *= (1.0f / 4194304.0f);
    if (i >= DIMS * NEMB) return;
    float n = g_n;
    int j = i & (NEMB - 1);
    float ncs = out[OFF_NCS + j];
    float smoothed = (ncs + 1e-5f) / (n + (float)NEMB * 1e-5f) * n;
    out[OFF_EMB + i] = out[OFF_AVG + i] / smoothed;
}

// ---------------------------------------------------------------------------
extern "C" void kernel_launch(void* const* d_in, const int* in_sizes, int n_in,
                              void* d_out, int out_size) {
    const float* z    = (const float*)d_in[0];   // [16,32,32,256]
    const float* E    = (const float*)d_in[1];   // [256, 8192]
    const float* cs   = (const float*)d_in[2];   // [8192]
    const float* eavg = (const float*)d_in[3];   // [256, 8192]
    float* out = (float*)d_out;

    static int cfg_done = 0;
    if (!cfg_done) {
        cudaFuncSetAttribute(k_argmin_mma,
                             cudaFuncAttributeMaxDynamicSharedMemorySize, SMEM_TOTAL);
        cfg_done = 1;
    }

    k_init   <<<(DIMS * NEMB + 255) / 256, 256>>>(eavg, out);
    k_conv_z <<<NROWS * DIMS / 256, 256>>>(z);
    {
        dim3 g(NEMB / 32, DIMS / 32), b(32, 8);
        k_prep_e<<<g, b>>>(E);
    }
    k_argmin_mma<<<NROWS / 128, 512, SMEM_TOTAL>>>(z, out);
    k_ncs    <<<NEMB / 256, 256>>>(cs, out);
    k_final  <<<(DIMS * NEMB + 255) / 256, 256>>>(out);
}

// round 15
// speedup vs baseline: 10.9665x; 1.0233x over previous
#include <cuda_runtime.h>
#include <cuda_bf16.h>
#include <math_constants.h>
#include <stdint.h>

#define NROWS 16384
#define DIMS  256
#define NEMB  8192

// Output layout (float32, reference return order, flattened+concatenated)
#define OFF_Q    0
#define OFF_DIFF 4194304
#define OFF_IND  4194305
#define OFF_EMB  4210689
#define OFF_NCS  6307841
#define OFF_AVG  6316033

// swizzled plane layout: row r (0..127 for A, 0..63 for B), 16B chunk c (0..31)
#define PLANE_ADDR(r, c) ((r) * 512 + (((c) >> 3) << 7) + ((((c) & 7) ^ ((r) & 7)) << 4))

// Scratch (no cudaMalloc allowed). g_zhi/g_ehi hold PRE-SWIZZLED tile layouts
// so cp.async.bulk can stage them linearly. g_enorm carries a uniform +512
// offset (argmin/rescore invariant) so the epilogue skips the bias add.
__device__ float g_enorm[NEMB];
__device__ int   g_count[NEMB];
__device__ float g_n;
__device__ __align__(128) __nv_bfloat16 g_zhi[NROWS * DIMS];  // [blk128][plane 64KB]
__device__ __align__(128) __nv_bfloat16 g_ehi[NEMB * DIMS];   // [tile64][plane 32KB]
__device__ float g_eT[NEMB * DIMS];                            // [code][k] fp32 linear

// ---------------------------------------------------------------------------
// PTX helpers — baseline sm_80/sm_90 features only (target compute_103, no 'a').
// ---------------------------------------------------------------------------
__device__ __forceinline__ uint32_t smem_u32(const void* p) {
    uint32_t a;
    asm("{ .reg .u64 t; cvta.to.shared.u64 t, %1; cvt.u32.u64 %0, t; }" : "=r"(a) : "l"(p));
    return a;
}
__device__ __forceinline__ void bar_sync(int id) {
    asm volatile("bar.sync %0, 256;" :: "r"(id) : "memory");
}
__device__ __forceinline__ void mbar_init(uint32_t a, uint32_t cnt) {
    asm volatile("mbarrier.init.shared.b64 [%0], %1;" :: "r"(a), "r"(cnt) : "memory");
}
__device__ __forceinline__ void mbar_expect_tx(uint32_t a, uint32_t bytes) {
    asm volatile("mbarrier.arrive.expect_tx.shared.b64 _, [%0], %1;"
                 :: "r"(a), "r"(bytes) : "memory");
}
__device__ __forceinline__ void bulk_g2s(uint32_t dst, const void* src,
                                         uint32_t bytes, uint32_t mbar) {
    asm volatile("cp.async.bulk.shared::cta.global.mbarrier::complete_tx::bytes "
                 "[%0], [%1], %2, [%3];"
                 :: "r"(dst), "l"(src), "r"(bytes), "r"(mbar) : "memory");
}
#define MBAR_WAIT(a, p) do {                                                     \
    uint32_t _m = (a), _p = (p), _d;                                             \
    asm volatile("{\n\t.reg .pred q;\n\t"                                        \
        "mbarrier.try_wait.parity.acquire.cta.shared::cta.b64 q, [%1], %2;\n\t"  \
        "selp.b32 %0, 1, 0, q;\n\t}" : "=r"(_d) : "r"(_m), "r"(_p) : "memory");  \
    if (!_d) {                                                                   \
        asm volatile("{\n\t.reg .pred Q;\n\tWL_%=:\n\t"                          \
            "mbarrier.try_wait.parity.acquire.cta.shared::cta.b64 Q, [%0], %1, 0x989680;\n\t" \
            "@Q bra.uni WD_%=;\n\tbra.uni WL_%=;\n\tWD_%=:\n\t}"                 \
            :: "r"(_m), "r"(_p) : "memory");                                     \
    }                                                                            \
} while (0)

__device__ __forceinline__ void ldsm_x4(uint32_t* r, uint32_t a) {
    asm volatile("ldmatrix.sync.aligned.m8n8.x4.shared.b16 {%0,%1,%2,%3}, [%4];"
                 : "=r"(r[0]), "=r"(r[1]), "=r"(r[2]), "=r"(r[3]) : "r"(a));
}
__device__ __forceinline__ void mma16816(float* d, const uint32_t* a, const uint32_t* b) {
    asm volatile("mma.sync.aligned.m16n8k16.row.col.f32.bf16.bf16.f32 "
                 "{%0,%1,%2,%3}, {%4,%5,%6,%7}, {%8,%9}, {%0,%1,%2,%3};"
                 : "+f"(d[0]), "+f"(d[1]), "+f"(d[2]), "+f"(d[3])
                 : "r"(a[0]), "r"(a[1]), "r"(a[2]), "r"(a[3]), "r"(b[0]), "r"(b[1]));
}

// pack positive float distance with 7-bit local code in low mantissa bits
__device__ __forceinline__ float pack7(float d, uint32_t code) {
    return __uint_as_float((__float_as_uint(d) & 0xFFFFFF80u) | code);
}

// merge two ascending pairs (a0<=a1),(b0<=b1) -> smallest two (branch-free)
__device__ __forceinline__ void p2_merge(float& a0, float& a1, float b0, float b1) {
    float lo = fminf(a0, b0);
    a1 = fminf(fmaxf(a0, b0), fminf(a1, b1));
    a0 = lo;
}

// sorted top-4 insert (ascending); common case = 1 compare
__device__ __forceinline__ void t4_insert(float (&v)[4], int (&j)[4], float d, int c) {
    if (d < v[3]) {
        if (d < v[1]) {
            v[3] = v[2]; j[3] = j[2]; v[2] = v[1]; j[2] = j[1];
            if (d < v[0]) { v[1] = v[0]; j[1] = j[0]; v[0] = d; j[0] = c; }
            else          { v[1] = d; j[1] = c; }
        } else {
            if (d < v[2]) { v[3] = v[2]; j[3] = j[2]; v[2] = d; j[2] = c; }
            else          { v[3] = d; j[3] = c; }
        }
    }
}

// ---------------------------------------------------------------------------
// A: fused init + z conversion. Grid covers NROWS*DIMS (4.19M).
//    - all i: convert z[i] to bf16 in pre-swizzled plane layout
//    - i < DIMS*NEMB: seed new_embedding_avg with 0.99*avg
//    - i < NEMB: zero count; enorm = 512 (uniform distance offset)
// ---------------------------------------------------------------------------
__global__ void k_init_conv(const float* __restrict__ z,
                            const float* __restrict__ eavg,
                            float* __restrict__ out) {
    int i = blockIdx.x * blockDim.x + threadIdx.x;
    {
        int row = i >> 8, k = i & 255;
        int blk = row >> 7, r = row & 127, c = k >> 3;
        uint32_t off = (uint32_t)blk * 65536 + PLANE_ADDR(r, c) + (k & 7) * 2;
        *(__nv_bfloat16*)((char*)g_zhi + off) = __float2bfloat16(z[i]);
    }
    if (i < DIMS * NEMB) out[OFF_AVG + i] = 0.99f * eavg[i];
    if (i < NEMB) { g_count[i] = 0; g_enorm[i] = 512.0f; }
    if (i == 0) { g_n = 0.0f; out[OFF_DIFF] = 0.0f; }
}

// ---------------------------------------------------------------------------
// B2: fused E prep: transpose to [j][k]; bf16 goes to pre-swizzled 64-row
//     tiles; fp32 stays linear; accumulate enorm (on top of the +512 seed).
// ---------------------------------------------------------------------------
__global__ void k_prep_e(const float* __restrict__ E) {
    __shared__ float t[32][33];
    int j0 = blockIdx.x * 32, k0 = blockIdx.y * 32;
    int tx = threadIdx.x, ty = threadIdx.y;
#pragma unroll
    for (int s = 0; s < 32; s += 8)
        t[ty + s][tx] = E[(size_t)(k0 + ty + s) * NEMB + j0 + tx];
    __syncthreads();
#pragma unroll
    for (int s = 0; s < 32; s += 8) {
        float x = t[tx][ty + s];
        int j = j0 + ty + s, k = k0 + tx;
        g_eT[(size_t)j * DIMS + k] = x;
        uint32_t off = (uint32_t)(j >> 6) * 32768 + PLANE_ADDR(j & 63, k >> 3) + (k & 7) * 2;
        *(__nv_bfloat16*)((char*)g_ehi + off) = __float2bfloat16(x);
        float p = x * x;
#pragma unroll
        for (int w = 16; w; w >>= 1) p += __shfl_xor_sync(0xffffffffu, p, w);
        if (tx == 0) atomicAdd(&g_enorm[j], p);
    }
}

// ---------------------------------------------------------------------------
// C: split-barrier halves, cp.async.bulk staging, packed min-2 epilogue with
//    single shfl round (pair-granular RED), register top-4, fused gather tail.
// ---------------------------------------------------------------------------
#define SM_A     0
#define SM_B     65536       // + (half*2+buf)*32768
#define SM_RED   196608      // + (half*2+buf)*5120 ; entry rl*5 + wn*2 + pr (float2)
#define SM_CAND  217088      // 256 x float4 (half1 pv/pj), then final int4
#define SM_MBAR  221184      // A @ +0; B @ +8 + (half*2+buf)*8
#define SMEM_TOTAL 221696

__global__ __launch_bounds__(512, 1) void k_argmin_mma(
    const float* __restrict__ z, float* __restrict__ out)
{
    extern __shared__ char smem[];
    const uint32_t sb = smem_u32(smem);
    const int tid = threadIdx.x, wid = tid >> 5, l = tid & 31;
    const int half = wid >> 3, hw = wid & 7, htid = tid & 255;
    const int wm = hw >> 1, wn = hw & 1;
    const int row0 = blockIdx.x * 128;

    if (tid == 0) {
        mbar_init(sb + SM_MBAR, 1);
#pragma unroll
        for (int b = 0; b < 4; b++) mbar_init(sb + SM_MBAR + 8 + b * 8, 1);
    }
    __syncthreads();

    // stage A (64KB, this CTA's 128-row block) and B tile 0 of each half
    if (tid == 0) {
        mbar_expect_tx(sb + SM_MBAR, 65536);
        bulk_g2s(sb + SM_A, (const char*)g_zhi + (size_t)blockIdx.x * 65536,
                 65536, sb + SM_MBAR);
    }
    if (htid == 0) {
        uint32_t mb = sb + SM_MBAR + 8 + (uint32_t)(half * 2) * 8;
        mbar_expect_tx(mb, 32768);
        bulk_g2s(sb + SM_B + (uint32_t)(half * 2) * 32768,
                 (const char*)g_ehi + (size_t)half * 32768, 32768, mb);
    }

    // persistent per-row top-4 (threads htid<128 of each half, row = htid)
    float pv[4] = {CUDART_INF_F, CUDART_INF_F, CUDART_INF_F, CUDART_INF_F};
    int   pj[4] = {0, 0, 0, 0};

    // fragment lane addressing
    const int arow = wm * 32 + (l & 15);
    const int acd  = l >> 4;
    const int brow = wn * 32 + ((l >> 4) << 3) + (l & 7);
    const int bcd  = (l >> 3) & 1;
    const int lc0  = wn * 32 + 2 * (l & 3);

    uint32_t aoff[4], boff[4];
#pragma unroll
    for (int j = 0; j < 4; j++) {
        aoff[j] = (uint32_t)(((2 * j + acd) ^ (arow & 7)) << 4);
        boff[j] = (uint32_t)(((2 * j + bcd) ^ (brow & 7)) << 4);
    }
    const uint32_t abase  = sb + SM_A + arow * 512;
    const uint32_t bbase0 = sb + SM_B + (uint32_t)(half * 2) * 32768 + brow * 512;
    const uint32_t redb   = sb + SM_RED + (uint32_t)(half * 2) * 5120;

    MBAR_WAIT(sb + SM_MBAR, 0);   // A resident

    for (int q = 0; q < 64; q++) {
        const int buf = q & 1;
        bar_sync(half + 1);   // all half-warps done with epoch q-1 (reads+RED)

        // prefetch next tile (single bulk op; buffer free per the barrier)
        if (q + 1 < 64 && htid == 0) {
            const int nb = (q + 1) & 1;
            uint32_t mb = sb + SM_MBAR + 8 + (uint32_t)(half * 2 + nb) * 8;
            mbar_expect_tx(mb, 32768);
            bulk_g2s(sb + SM_B + (uint32_t)(half * 2 + nb) * 32768,
                     (const char*)g_ehi + (size_t)(2 * (q + 1) + half) * 32768,
                     32768, mb);
        }

        // merge previous tile's warp pair-lists (overlaps other warps' MMA)
        if (q > 0 && htid < 128) {
            const float2* src = (const float2*)(smem + (redb - sb) + ((q - 1) & 1) * 5120)
                                + htid * 5;
            float2 a = src[0], b = src[1], c = src[2], d = src[3];
            p2_merge(a.x, a.y, b.x, b.y);
            p2_merge(c.x, c.y, d.x, d.y);
            p2_merge(a.x, a.y, c.x, c.y);
            int cb = (2 * (q - 1) + half) * 64;
            t4_insert(pv, pj, a.x, cb + (__float_as_int(a.x) & 0x7F));
            t4_insert(pv, pj, a.y, cb + (__float_as_int(a.y) & 0x7F));
        }

        // wait for this epoch's B tile
        MBAR_WAIT(sb + SM_MBAR + 8 + (uint32_t)(half * 2 + buf) * 8, (q >> 1) & 1);

        float acc[2][4][4];
#pragma unroll
        for (int mt = 0; mt < 2; mt++)
#pragma unroll
            for (int nt = 0; nt < 4; nt++)
#pragma unroll
                for (int e = 0; e < 4; e++) acc[mt][nt][e] = 0.0f;

        const uint32_t bbase = bbase0 + (uint32_t)buf * 32768;
#pragma unroll
        for (int t16 = 0; t16 < 16; t16++) {
            const uint32_t g = (uint32_t)((t16 >> 2) << 7);
            uint32_t ba = bbase + g + boff[t16 & 3];
            uint32_t q0[4], q1[4];
            ldsm_x4(q0, ba);
            ldsm_x4(q1, ba + 8192);
            uint32_t aa = abase + g + aoff[t16 & 3];
            uint32_t a0[4], a1[4];
            ldsm_x4(a0, aa);
            ldsm_x4(a1, aa + 8192);
            mma16816(acc[0][0], a0, q0);
            mma16816(acc[0][1], a0, q0 + 2);
            mma16816(acc[0][2], a0, q1);
            mma16816(acc[0][3], a0, q1 + 2);
            mma16816(acc[1][0], a1, q0);
            mma16816(acc[1][1], a1, q0 + 2);
            mma16816(acc[1][2], a1, q1);
            mma16816(acc[1][3], a1, q1 + 2);
        }

        // epilogue: packed distances -> min2 tournament -> ONE shfl round ->
        // two lanes per quad write their pair to RED[buf]
        {
            const int tile = 2 * q + half;
            float enx[4], eny[4];
#pragma unroll
            for (int nt = 0; nt < 4; nt++) {
                float2 en = __ldg((const float2*)&g_enorm[tile * 64 + lc0 + nt * 8]);
                enx[nt] = en.x;   // +512 pre-folded into g_enorm
                eny[nt] = en.y;
            }
#pragma unroll
            for (int mt = 0; mt < 2; mt++) {
#pragma unroll
                for (int h = 0; h < 2; h++) {
                    float p[8];
#pragma unroll
                    for (int nt = 0; nt < 4; nt++) {
                        uint32_t lc = lc0 + nt * 8;
                        p[2 * nt]     = pack7(fmaf(-2.0f, acc[mt][nt][h * 2],     enx[nt]), lc);
                        p[2 * nt + 1] = pack7(fmaf(-2.0f, acc[mt][nt][h * 2 + 1], eny[nt]), lc + 1);
                    }
                    float l0 = fminf(p[0], p[1]), h0 = fmaxf(p[0], p[1]);
                    float l1 = fminf(p[2], p[3]), h1 = fmaxf(p[2], p[3]);
                    float l2 = fminf(p[4], p[5]), h2 = fmaxf(p[4], p[5]);
                    float l3 = fminf(p[6], p[7]), h3 = fmaxf(p[6], p[7]);
                    p2_merge(l0, h0, l1, h1);
                    p2_merge(l2, h2, l3, h3);
                    p2_merge(l0, h0, l2, h2);
                    // single pair-merge round (lanes x <-> x^1)
                    {
                        float fl = __shfl_xor_sync(0xffffffffu, l0, 1);
                        float fh = __shfl_xor_sync(0xffffffffu, h0, 1);
                        p2_merge(l0, h0, fl, fh);
                    }
                    if ((l & 1) == 0) {
                        int rl = wm * 32 + mt * 16 + h * 8 + (l >> 2);
                        int pr = (l >> 1) & 1;
                        ((float2*)(smem + (redb - sb) + buf * 5120))[rl * 5 + wn * 2 + pr] =
                            make_float2(l0, h0);
                    }
                }
            }
        }
    }

    bar_sync(half + 1);
    // merge last tile (q=63, buf=1)
    if (htid < 128) {
        const float2* src = (const float2*)(smem + (redb - sb) + 5120) + htid * 5;
        float2 a = src[0], b = src[1], c = src[2], d = src[3];
        p2_merge(a.x, a.y, b.x, b.y);
        p2_merge(c.x, c.y, d.x, d.y);
        p2_merge(a.x, a.y, c.x, c.y);
        int cb = (2 * 63 + half) * 64;
        t4_insert(pv, pj, a.x, cb + (__float_as_int(a.x) & 0x7F));
        t4_insert(pv, pj, a.y, cb + (__float_as_int(a.y) & 0x7F));
    }
    // half 1 publishes its top-4 (values + codes)
    if (half == 1 && htid < 128) {
        float4* cnd = (float4*)(smem + SM_CAND);
        cnd[htid]       = make_float4(pv[0], pv[1], pv[2], pv[3]);
        cnd[128 + htid] = make_float4(__int_as_float(pj[0]), __int_as_float(pj[1]),
                                      __int_as_float(pj[2]), __int_as_float(pj[3]));
    }
    __syncthreads();
    // half 0's first 128 threads union-merge -> global top-4 -> final cand
    if (tid < 128) {
        const float4* cnd = (const float4*)(smem + SM_CAND);
        float4 f = cnd[tid], ii = cnd[128 + tid];
        t4_insert(pv, pj, f.x, __float_as_int(ii.x));
        t4_insert(pv, pj, f.y, __float_as_int(ii.y));
        t4_insert(pv, pj, f.z, __float_as_int(ii.z));
        t4_insert(pv, pj, f.w, __float_as_int(ii.w));
        ((int4*)(smem + SM_CAND))[tid] = make_int4(pj[0], pj[1], pj[2], pj[3]);
    }
    __syncthreads();

    // ---- fused gather: 16 warps x 8 rows; exact fp32 rescore + outputs ----
    float ssacc = 0.0f;
#pragma unroll 1
    for (int rr = 0; rr < 8; rr++) {
        const int rl = wid * 8 + rr;
        const int r  = row0 + rl;
        const int4 cand = ((const int4*)(smem + SM_CAND))[rl];
        const int cj[4] = {cand.x, cand.y, cand.z, cand.w};

        float zv[8];
#pragma unroll
        for (int it = 0; it < 8; it++) zv[it] = z[(size_t)r * DIMS + l + it * 32];

        float dot[4] = {0.0f, 0.0f, 0.0f, 0.0f};
#pragma unroll
        for (int c = 0; c < 4; c++) {
            const float* e = g_eT + (size_t)cj[c] * DIMS;
#pragma unroll
            for (int it = 0; it < 8; it++)
                dot[c] = fmaf(zv[it], e[l + it * 32], dot[c]);
        }
#pragma unroll
        for (int c = 0; c < 4; c++)
#pragma unroll
            for (int o = 16; o; o >>= 1) dot[c] += __shfl_xor_sync(0xffffffffu, dot[c], o);

        int bj = cj[0];
        float bd = fmaf(-2.0f, dot[0], g_enorm[cj[0]]);
#pragma unroll
        for (int c = 1; c < 4; c++) {
            float d = fmaf(-2.0f, dot[c], g_enorm[cj[c]]);
            if (d < bd || (d == bd && cj[c] < bj)) { bd = d; bj = cj[c]; }
        }

        const float* eb = g_eT + (size_t)bj * DIMS;
        float ss = 0.0f;
#pragma unroll
        for (int it = 0; it < 8; it++) {
            int d = l + it * 32;
            float e = eb[d];
            float qd = e - zv[it];
            out[OFF_Q + (size_t)r * DIMS + d] = zv[it] + qd;
            ss = fmaf(qd, qd, ss);
            atomicAdd(&out[OFF_AVG + (size_t)d * NEMB + bj], 0.01f * zv[it]);
        }
        if (l == 0) {
            atomicAdd(&g_count[bj], 1);
            out[OFF_IND + r] = (float)bj;
        }
#pragma unroll
        for (int o = 16; o; o >>= 1) ss += __shfl_down_sync(0xffffffffu, ss, o);
        if (l == 0) ssacc += ss;
    }
    if (l == 0) atomicAdd(&out[OFF_DIFF], ssacc);
}

// ---------------------------------------------------------------------------
// E: new_cluster_size + global n reduction
// ---------------------------------------------------------------------------
__global__ void k_ncs(const float* __restrict__ cs, float* __restrict__ out) {
    __shared__ float sh[256];
    int j = blockIdx.x * 256 + threadIdx.x;
    float v = cs[j] * 0.99f + 0.01f * (float)g_count[j];
    out[OFF_NCS + j] = v;
    sh[threadIdx.x] = v;
    __syncthreads();
    for (int s = 128; s; s >>= 1) {
        if (threadIdx.x < s) sh[threadIdx.x] += sh[threadIdx.x + s];
        __syncthreads();
    }
    if (threadIdx.x == 0) atomicAdd(&g_n, sh[0]);
}

// ---------------------------------------------------------------------------
// F: new_embedding = avg / smoothed; finalize diff mean
// ---------------------------------------------------------------------------
__global__ void k_final(float* __restrict__ out) {
    int i = blockIdx.x * blockDim.x + threadIdx.x;
    if (i == 0) out[OFF_DIFF] *= (1.0f / 4194304.0f);
    if (i >= DIMS * NEMB) return;
    float n = g_n;
    int j = i & (NEMB - 1);
    float ncs = out[OFF_NCS + j];
    float smoothed = (ncs + 1e-5f) / (n + (float)NEMB * 1e-5f) * n;
    out[OFF_EMB + i] = out[OFF_AVG + i] / smoothed;
}

// ---------------------------------------------------------------------------
extern "C" void kernel_launch(void* const* d_in, const int* in_sizes, int n_in,
                              void* d_out, int out_size) {
    const float* z    = (const float*)d_in[0];   // [16,32,32,256]
    const float* E    = (const float*)d_in[1];   // [256, 8192]
    const float* cs   = (const float*)d_in[2];   // [8192]
    const float* eavg = (const float*)d_in[3];   // [256, 8192]
    float* out = (float*)d_out;

    static int cfg_done = 0;
    if (!cfg_done) {
        cudaFuncSetAttribute(k_argmin_mma,
                             cudaFuncAttributeMaxDynamicSharedMemorySize, SMEM_TOTAL);
        cfg_done = 1;
    }

    k_init_conv<<<NROWS * DIMS / 256, 256>>>(z, eavg, out);
    {
        dim3 g(NEMB / 32, DIMS / 32), b(32, 8);
        k_prep_e<<<g, b>>>(E);
    }
    k_argmin_mma<<<NROWS / 128, 512, SMEM_TOTAL>>>(z, out);
    k_ncs    <<<NEMB / 256, 256>>>(cs, out);
    k_final  <<<(DIMS * NEMB + 255) / 256, 256>>>(out);
}

// round 16
// speedup vs baseline: 11.5870x; 1.0566x over previous
#include <cuda_runtime.h>
#include <cuda_bf16.h>
#include <math_constants.h>
#include <stdint.h>

#define NROWS 16384
#define DIMS  256
#define NEMB  8192

// Output layout (float32, reference return order, flattened+concatenated)
#define OFF_Q    0
#define OFF_DIFF 4194304
#define OFF_IND  4194305
#define OFF_EMB  4210689
#define OFF_NCS  6307841
#define OFF_AVG  6316033

// swizzled plane layout: row r (0..127 for A, 0..63 for B), 16B chunk c (0..31)
#define PLANE_ADDR(r, c) ((r) * 512 + (((c) >> 3) << 7) + ((((c) & 7) ^ ((r) & 7)) << 4))

// Scratch (no cudaMalloc allowed). g_zhi/g_ehi hold PRE-SWIZZLED tile layouts
// so cp.async.bulk can stage them linearly. g_enorm carries a uniform +512
// offset (argmin/rescore invariant). g_avgT accumulates 0.01*segment-sum in
// TRANSPOSED [code][dim] layout so the scatter can use red.v4.f32.
__device__ float g_enorm[NEMB];
__device__ int   g_count[NEMB];
__device__ float g_n;
__device__ __align__(128) __nv_bfloat16 g_zhi[NROWS * DIMS];  // [blk128][plane 64KB]
__device__ __align__(128) __nv_bfloat16 g_ehi[NEMB * DIMS];   // [tile64][plane 32KB]
__device__ float g_eT[NEMB * DIMS];                            // [code][k] fp32 linear
__device__ __align__(16) float g_avgT[NEMB * DIMS];            // [code][dim] scatter

// ---------------------------------------------------------------------------
// PTX helpers — baseline sm_80/sm_90 features only (target compute_103, no 'a').
// ---------------------------------------------------------------------------
__device__ __forceinline__ uint32_t smem_u32(const void* p) {
    uint32_t a;
    asm("{ .reg .u64 t; cvta.to.shared.u64 t, %1; cvt.u32.u64 %0, t; }" : "=r"(a) : "l"(p));
    return a;
}
__device__ __forceinline__ void bar_sync(int id) {
    asm volatile("bar.sync %0, 256;" :: "r"(id) : "memory");
}
__device__ __forceinline__ void mbar_init(uint32_t a, uint32_t cnt) {
    asm volatile("mbarrier.init.shared.b64 [%0], %1;" :: "r"(a), "r"(cnt) : "memory");
}
__device__ __forceinline__ void mbar_expect_tx(uint32_t a, uint32_t bytes) {
    asm volatile("mbarrier.arrive.expect_tx.shared.b64 _, [%0], %1;"
                 :: "r"(a), "r"(bytes) : "memory");
}
__device__ __forceinline__ void bulk_g2s(uint32_t dst, const void* src,
                                         uint32_t bytes, uint32_t mbar) {
    asm volatile("cp.async.bulk.shared::cta.global.mbarrier::complete_tx::bytes "
                 "[%0], [%1], %2, [%3];"
                 :: "r"(dst), "l"(src), "r"(bytes), "r"(mbar) : "memory");
}
__device__ __forceinline__ void red_add_v4(float* p, float4 v) {
    asm volatile("red.global.add.v4.f32 [%0], {%1, %2, %3, %4};"
                 :: "l"(p), "f"(v.x), "f"(v.y), "f"(v.z), "f"(v.w) : "memory");
}
#define MBAR_WAIT(a, p) do {                                                     \
    uint32_t _m = (a), _p = (p), _d;                                             \
    asm volatile("{\n\t.reg .pred q;\n\t"                                        \
        "mbarrier.try_wait.parity.acquire.cta.shared::cta.b64 q, [%1], %2;\n\t"  \
        "selp.b32 %0, 1, 0, q;\n\t}" : "=r"(_d) : "r"(_m), "r"(_p) : "memory");  \
    if (!_d) {                                                                   \
        asm volatile("{\n\t.reg .pred Q;\n\tWL_%=:\n\t"                          \
            "mbarrier.try_wait.parity.acquire.cta.shared::cta.b64 Q, [%0], %1, 0x989680;\n\t" \
            "@Q bra.uni WD_%=;\n\tbra.uni WL_%=;\n\tWD_%=:\n\t}"                 \
            :: "r"(_m), "r"(_p) : "memory");                                     \
    }                                                                            \
} while (0)

__device__ __forceinline__ void ldsm_x4(uint32_t* r, uint32_t a) {
    asm volatile("ldmatrix.sync.aligned.m8n8.x4.shared.b16 {%0,%1,%2,%3}, [%4];"
                 : "=r"(r[0]), "=r"(r[1]), "=r"(r[2]), "=r"(r[3]) : "r"(a));
}
__device__ __forceinline__ void mma16816(float* d, const uint32_t* a, const uint32_t* b) {
    asm volatile("mma.sync.aligned.m16n8k16.row.col.f32.bf16.bf16.f32 "
                 "{%0,%1,%2,%3}, {%4,%5,%6,%7}, {%8,%9}, {%0,%1,%2,%3};"
                 : "+f"(d[0]), "+f"(d[1]), "+f"(d[2]), "+f"(d[3])
                 : "r"(a[0]), "r"(a[1]), "r"(a[2]), "r"(a[3]), "r"(b[0]), "r"(b[1]));
}

// pack positive float distance with 7-bit local code in low mantissa bits
__device__ __forceinline__ float pack7(float d, uint32_t code) {
    return __uint_as_float((__float_as_uint(d) & 0xFFFFFF80u) | code);
}

// merge two ascending pairs (a0<=a1),(b0<=b1) -> smallest two (branch-free)
__device__ __forceinline__ void p2_merge(float& a0, float& a1, float b0, float b1) {
    float lo = fminf(a0, b0);
    a1 = fminf(fmaxf(a0, b0), fminf(a1, b1));
    a0 = lo;
}

// sorted top-4 insert (ascending); common case = 1 compare
__device__ __forceinline__ void t4_insert(float (&v)[4], int (&j)[4], float d, int c) {
    if (d < v[3]) {
        if (d < v[1]) {
            v[3] = v[2]; j[3] = j[2]; v[2] = v[1]; j[2] = j[1];
            if (d < v[0]) { v[1] = v[0]; j[1] = j[0]; v[0] = d; j[0] = c; }
            else          { v[1] = d; j[1] = c; }
        } else {
            if (d < v[2]) { v[3] = v[2]; j[3] = j[2]; v[2] = d; j[2] = c; }
            else          { v[3] = d; j[3] = c; }
        }
    }
}

// ---------------------------------------------------------------------------
// A: fused init + z conversion. Grid covers NROWS*DIMS (4.19M).
//    - all i: convert z[i] to bf16 in pre-swizzled plane layout
//    - i < DIMS*NEMB: zero g_avgT scatter scratch
//    - i < NEMB: zero count; enorm = 512 (uniform distance offset)
// ---------------------------------------------------------------------------
__global__ void k_init_conv(const float* __restrict__ z, float* __restrict__ out) {
    int i = blockIdx.x * blockDim.x + threadIdx.x;
    {
        int row = i >> 8, k = i & 255;
        int blk = row >> 7, r = row & 127, c = k >> 3;
        uint32_t off = (uint32_t)blk * 65536 + PLANE_ADDR(r, c) + (k & 7) * 2;
        *(__nv_bfloat16*)((char*)g_zhi + off) = __float2bfloat16(z[i]);
    }
    if (i < DIMS * NEMB) g_avgT[i] = 0.0f;
    if (i < NEMB) { g_count[i] = 0; g_enorm[i] = 512.0f; }
    if (i == 0) { g_n = 0.0f; out[OFF_DIFF] = 0.0f; }
}

// ---------------------------------------------------------------------------
// B2: fused E prep: transpose to [j][k]; bf16 goes to pre-swizzled 64-row
//     tiles; fp32 stays linear; accumulate enorm (on top of the +512 seed).
// ---------------------------------------------------------------------------
__global__ void k_prep_e(const float* __restrict__ E) {
    __shared__ float t[32][33];
    int j0 = blockIdx.x * 32, k0 = blockIdx.y * 32;
    int tx = threadIdx.x, ty = threadIdx.y;
#pragma unroll
    for (int s = 0; s < 32; s += 8)
        t[ty + s][tx] = E[(size_t)(k0 + ty + s) * NEMB + j0 + tx];
    __syncthreads();
#pragma unroll
    for (int s = 0; s < 32; s += 8) {
        float x = t[tx][ty + s];
        int j = j0 + ty + s, k = k0 + tx;
        g_eT[(size_t)j * DIMS + k] = x;
        uint32_t off = (uint32_t)(j >> 6) * 32768 + PLANE_ADDR(j & 63, k >> 3) + (k & 7) * 2;
        *(__nv_bfloat16*)((char*)g_ehi + off) = __float2bfloat16(x);
        float p = x * x;
#pragma unroll
        for (int w = 16; w; w >>= 1) p += __shfl_xor_sync(0xffffffffu, p, w);
        if (tx == 0) atomicAdd(&g_enorm[j], p);
    }
}

// ---------------------------------------------------------------------------
// C: split-barrier halves, cp.async.bulk staging, packed min-2 epilogue,
//    register top-4, fused gather with red.v4 scatter into g_avgT.
// ---------------------------------------------------------------------------
#define SM_A     0
#define SM_B     65536       // + (half*2+buf)*32768
#define SM_RED   196608      // + (half*2+buf)*5120 ; entry rl*5 + wn*2 + pr (float2)
#define SM_CAND  217088      // 256 x float4 (half1 pv/pj), then final int4
#define SM_MBAR  221184      // A @ +0; B @ +8 + (half*2+buf)*8
#define SMEM_TOTAL 221696

__global__ __launch_bounds__(512, 1) void k_argmin_mma(
    const float* __restrict__ z, float* __restrict__ out)
{
    extern __shared__ char smem[];
    const uint32_t sb = smem_u32(smem);
    const int tid = threadIdx.x, wid = tid >> 5, l = tid & 31;
    const int half = wid >> 3, hw = wid & 7, htid = tid & 255;
    const int wm = hw >> 1, wn = hw & 1;
    const int row0 = blockIdx.x * 128;

    if (tid == 0) {
        mbar_init(sb + SM_MBAR, 1);
#pragma unroll
        for (int b = 0; b < 4; b++) mbar_init(sb + SM_MBAR + 8 + b * 8, 1);
    }
    __syncthreads();

    // stage A (64KB, this CTA's 128-row block) and B tile 0 of each half
    if (tid == 0) {
        mbar_expect_tx(sb + SM_MBAR, 65536);
        bulk_g2s(sb + SM_A, (const char*)g_zhi + (size_t)blockIdx.x * 65536,
                 65536, sb + SM_MBAR);
    }
    if (htid == 0) {
        uint32_t mb = sb + SM_MBAR + 8 + (uint32_t)(half * 2) * 8;
        mbar_expect_tx(mb, 32768);
        bulk_g2s(sb + SM_B + (uint32_t)(half * 2) * 32768,
                 (const char*)g_ehi + (size_t)half * 32768, 32768, mb);
    }

    // persistent per-row top-4 (threads htid<128 of each half, row = htid)
    float pv[4] = {CUDART_INF_F, CUDART_INF_F, CUDART_INF_F, CUDART_INF_F};
    int   pj[4] = {0, 0, 0, 0};

    // fragment lane addressing
    const int arow = wm * 32 + (l & 15);
    const int acd  = l >> 4;
    const int brow = wn * 32 + ((l >> 4) << 3) + (l & 7);
    const int bcd  = (l >> 3) & 1;
    const int lc0  = wn * 32 + 2 * (l & 3);

    uint32_t aoff[4], boff[4];
#pragma unroll
    for (int j = 0; j < 4; j++) {
        aoff[j] = (uint32_t)(((2 * j + acd) ^ (arow & 7)) << 4);
        boff[j] = (uint32_t)(((2 * j + bcd) ^ (brow & 7)) << 4);
    }
    const uint32_t abase  = sb + SM_A + arow * 512;
    const uint32_t bbase0 = sb + SM_B + (uint32_t)(half * 2) * 32768 + brow * 512;
    const uint32_t redb   = sb + SM_RED + (uint32_t)(half * 2) * 5120;

    MBAR_WAIT(sb + SM_MBAR, 0);   // A resident

    for (int q = 0; q < 64; q++) {
        const int buf = q & 1;
        bar_sync(half + 1);   // all half-warps done with epoch q-1 (reads+RED)

        // prefetch next tile (single bulk op; buffer free per the barrier)
        if (q + 1 < 64 && htid == 0) {
            const int nb = (q + 1) & 1;
            uint32_t mb = sb + SM_MBAR + 8 + (uint32_t)(half * 2 + nb) * 8;
            mbar_expect_tx(mb, 32768);
            bulk_g2s(sb + SM_B + (uint32_t)(half * 2 + nb) * 32768,
                     (const char*)g_ehi + (size_t)(2 * (q + 1) + half) * 32768,
                     32768, mb);
        }

        // merge previous tile's warp pair-lists (overlaps other warps' MMA)
        if (q > 0 && htid < 128) {
            const float2* src = (const float2*)(smem + (redb - sb) + ((q - 1) & 1) * 5120)
                                + htid * 5;
            float2 a = src[0], b = src[1], c = src[2], d = src[3];
            p2_merge(a.x, a.y, b.x, b.y);
            p2_merge(c.x, c.y, d.x, d.y);
            p2_merge(a.x, a.y, c.x, c.y);
            int cb = (2 * (q - 1) + half) * 64;
            t4_insert(pv, pj, a.x, cb + (__float_as_int(a.x) & 0x7F));
            t4_insert(pv, pj, a.y, cb + (__float_as_int(a.y) & 0x7F));
        }

        // wait for this epoch's B tile
        MBAR_WAIT(sb + SM_MBAR + 8 + (uint32_t)(half * 2 + buf) * 8, (q >> 1) & 1);

        float acc[2][4][4];
#pragma unroll
        for (int mt = 0; mt < 2; mt++)
#pragma unroll
            for (int nt = 0; nt < 4; nt++)
#pragma unroll
                for (int e = 0; e < 4; e++) acc[mt][nt][e] = 0.0f;

        const uint32_t bbase = bbase0 + (uint32_t)buf * 32768;
#pragma unroll
        for (int t16 = 0; t16 < 16; t16++) {
            const uint32_t g = (uint32_t)((t16 >> 2) << 7);
            uint32_t ba = bbase + g + boff[t16 & 3];
            uint32_t q0[4], q1[4];
            ldsm_x4(q0, ba);
            ldsm_x4(q1, ba + 8192);
            uint32_t aa = abase + g + aoff[t16 & 3];
            uint32_t a0[4], a1[4];
            ldsm_x4(a0, aa);
            ldsm_x4(a1, aa + 8192);
            mma16816(acc[0][0], a0, q0);
            mma16816(acc[0][1], a0, q0 + 2);
            mma16816(acc[0][2], a0, q1);
            mma16816(acc[0][3], a0, q1 + 2);
            mma16816(acc[1][0], a1, q0);
            mma16816(acc[1][1], a1, q0 + 2);
            mma16816(acc[1][2], a1, q1);
            mma16816(acc[1][3], a1, q1 + 2);
        }

        // epilogue: packed distances -> min2 tournament -> ONE shfl round ->
        // two lanes per quad write their pair to RED[buf]
        {
            const int tile = 2 * q + half;
            float enx[4], eny[4];
#pragma unroll
            for (int nt = 0; nt < 4; nt++) {
                float2 en = __ldg((const float2*)&g_enorm[tile * 64 + lc0 + nt * 8]);
                enx[nt] = en.x;   // +512 pre-folded into g_enorm
                eny[nt] = en.y;
            }
#pragma unroll
            for (int mt = 0; mt < 2; mt++) {
#pragma unroll
                for (int h = 0; h < 2; h++) {
                    float p[8];
#pragma unroll
                    for (int nt = 0; nt < 4; nt++) {
                        uint32_t lc = lc0 + nt * 8;
                        p[2 * nt]     = pack7(fmaf(-2.0f, acc[mt][nt][h * 2],     enx[nt]), lc);
                        p[2 * nt + 1] = pack7(fmaf(-2.0f, acc[mt][nt][h * 2 + 1], eny[nt]), lc + 1);
                    }
                    float l0 = fminf(p[0], p[1]), h0 = fmaxf(p[0], p[1]);
                    float l1 = fminf(p[2], p[3]), h1 = fmaxf(p[2], p[3]);
                    float l2 = fminf(p[4], p[5]), h2 = fmaxf(p[4], p[5]);
                    float l3 = fminf(p[6], p[7]), h3 = fmaxf(p[6], p[7]);
                    p2_merge(l0, h0, l1, h1);
                    p2_merge(l2, h2, l3, h3);
                    p2_merge(l0, h0, l2, h2);
                    {
                        float fl = __shfl_xor_sync(0xffffffffu, l0, 1);
                        float fh = __shfl_xor_sync(0xffffffffu, h0, 1);
                        p2_merge(l0, h0, fl, fh);
                    }
                    if ((l & 1) == 0) {
                        int rl = wm * 32 + mt * 16 + h * 8 + (l >> 2);
                        int pr = (l >> 1) & 1;
                        ((float2*)(smem + (redb - sb) + buf * 5120))[rl * 5 + wn * 2 + pr] =
                            make_float2(l0, h0);
                    }
                }
            }
        }
    }

    bar_sync(half + 1);
    // merge last tile (q=63, buf=1)
    if (htid < 128) {
        const float2* src = (const float2*)(smem + (redb - sb) + 5120) + htid * 5;
        float2 a = src[0], b = src[1], c = src[2], d = src[3];
        p2_merge(a.x, a.y, b.x, b.y);
        p2_merge(c.x, c.y, d.x, d.y);
        p2_merge(a.x, a.y, c.x, c.y);
        int cb = (2 * 63 + half) * 64;
        t4_insert(pv, pj, a.x, cb + (__float_as_int(a.x) & 0x7F));
        t4_insert(pv, pj, a.y, cb + (__float_as_int(a.y) & 0x7F));
    }
    // half 1 publishes its top-4 (values + codes)
    if (half == 1 && htid < 128) {
        float4* cnd = (float4*)(smem + SM_CAND);
        cnd[htid]       = make_float4(pv[0], pv[1], pv[2], pv[3]);
        cnd[128 + htid] = make_float4(__int_as_float(pj[0]), __int_as_float(pj[1]),
                                      __int_as_float(pj[2]), __int_as_float(pj[3]));
    }
    __syncthreads();
    // half 0's first 128 threads union-merge -> global top-4 -> final cand
    if (tid < 128) {
        const float4* cnd = (const float4*)(smem + SM_CAND);
        float4 f = cnd[tid], ii = cnd[128 + tid];
        t4_insert(pv, pj, f.x, __float_as_int(ii.x));
        t4_insert(pv, pj, f.y, __float_as_int(ii.y));
        t4_insert(pv, pj, f.z, __float_as_int(ii.z));
        t4_insert(pv, pj, f.w, __float_as_int(ii.w));
        ((int4*)(smem + SM_CAND))[tid] = make_int4(pj[0], pj[1], pj[2], pj[3]);
    }
    __syncthreads();

    // ---- fused gather: 16 warps x 8 rows; lane owns d in [l*8, l*8+8).
    //      exact fp32 rescore; quantize/diff; red.v4 scatter into g_avgT ----
    float ssacc = 0.0f;
#pragma unroll 1
    for (int rr = 0; rr < 8; rr++) {
        const int rl = wid * 8 + rr;
        const int r  = row0 + rl;
        const int4 cand = ((const int4*)(smem + SM_CAND))[rl];
        const int cj[4] = {cand.x, cand.y, cand.z, cand.w};

        float4 zva = *(const float4*)(z + (size_t)r * DIMS + l * 8);
        float4 zvb = *(const float4*)(z + (size_t)r * DIMS + l * 8 + 4);

        float dot[4];
#pragma unroll
        for (int c = 0; c < 4; c++) {
            const float* e = g_eT + (size_t)cj[c] * DIMS + l * 8;
            float4 ea = *(const float4*)e, eb = *(const float4*)(e + 4);
            float s = zva.x * ea.x;
            s = fmaf(zva.y, ea.y, s); s = fmaf(zva.z, ea.z, s);
            s = fmaf(zva.w, ea.w, s); s = fmaf(zvb.x, eb.x, s);
            s = fmaf(zvb.y, eb.y, s); s = fmaf(zvb.z, eb.z, s);
            s = fmaf(zvb.w, eb.w, s);
            dot[c] = s;
        }
#pragma unroll
        for (int c = 0; c < 4; c++)
#pragma unroll
            for (int o = 16; o; o >>= 1) dot[c] += __shfl_xor_sync(0xffffffffu, dot[c], o);

        int bj = cj[0];
        float bd = fmaf(-2.0f, dot[0], g_enorm[cj[0]]);
#pragma unroll
        for (int c = 1; c < 4; c++) {
            float d = fmaf(-2.0f, dot[c], g_enorm[cj[c]]);
            if (d < bd || (d == bd && cj[c] < bj)) { bd = d; bj = cj[c]; }
        }

        const float* eb = g_eT + (size_t)bj * DIMS + l * 8;
        float4 ea = *(const float4*)eb, eb4 = *(const float4*)(eb + 4);
        // quantize_st == e (z + (e - z)); diff accumulates (e - z)^2
        *(float4*)(out + OFF_Q + (size_t)r * DIMS + l * 8)     = ea;
        *(float4*)(out + OFF_Q + (size_t)r * DIMS + l * 8 + 4) = eb4;
        float ss;
        {
            float d0 = ea.x - zva.x, d1 = ea.y - zva.y, d2 = ea.z - zva.z, d3 = ea.w - zva.w;
            float d4 = eb4.x - zvb.x, d5 = eb4.y - zvb.y, d6 = eb4.z - zvb.z, d7 = eb4.w - zvb.w;
            ss = d0 * d0;
            ss = fmaf(d1, d1, ss); ss = fmaf(d2, d2, ss); ss = fmaf(d3, d3, ss);
            ss = fmaf(d4, d4, ss); ss = fmaf(d5, d5, ss); ss = fmaf(d6, d6, ss);
            ss = fmaf(d7, d7, ss);
        }
        float* avgp = g_avgT + (size_t)bj * DIMS + l * 8;
        red_add_v4(avgp,     make_float4(0.01f * zva.x, 0.01f * zva.y,
                                         0.01f * zva.z, 0.01f * zva.w));
        red_add_v4(avgp + 4, make_float4(0.01f * zvb.x, 0.01f * zvb.y,
                                         0.01f * zvb.z, 0.01f * zvb.w));
        if (l == 0) {
            atomicAdd(&g_count[bj], 1);
            out[OFF_IND + r] = (float)bj;
        }
#pragma unroll
        for (int o = 16; o; o >>= 1) ss += __shfl_down_sync(0xffffffffu, ss, o);
        if (l == 0) ssacc += ss;
    }
    if (l == 0) atomicAdd(&out[OFF_DIFF], ssacc);
}

// ---------------------------------------------------------------------------
// E: new_cluster_size + global n reduction
// ---------------------------------------------------------------------------
__global__ void k_ncs(const float* __restrict__ cs, float* __restrict__ out) {
    __shared__ float sh[256];
    int j = blockIdx.x * 256 + threadIdx.x;
    float v = cs[j] * 0.99f + 0.01f * (float)g_count[j];
    out[OFF_NCS + j] = v;
    sh[threadIdx.x] = v;
    __syncthreads();
    for (int s = 128; s; s >>= 1) {
        if (threadIdx.x < s) sh[threadIdx.x] += sh[threadIdx.x + s];
        __syncthreads();
    }
    if (threadIdx.x == 0) atomicAdd(&g_n, sh[0]);
}

// ---------------------------------------------------------------------------
// F: tiled transpose finalize: AVG[d][j] = 0.99*eavg[d][j] + g_avgT[j][d];
//    EMB = AVG / smoothed(j); finalize diff mean. block (32,8), 32x32 tiles.
// ---------------------------------------------------------------------------
__global__ void k_final(const float* __restrict__ eavg, float* __restrict__ out) {
    __shared__ float t[32][33];
    int j0 = blockIdx.x * 32, d0 = blockIdx.y * 32;
    int tx = threadIdx.x, ty = threadIdx.y;
    if (blockIdx.x == 0 && blockIdx.y == 0 && tx == 0 && ty == 0)
        out[OFF_DIFF] *= (1.0f / 4194304.0f);
    // load avgT[j][d] tile (coalesced in d)
#pragma unroll
    for (int s = 0; s < 32; s += 8)
        t[ty + s][tx] = g_avgT[(size_t)(j0 + ty + s) * DIMS + d0 + tx];
    __syncthreads();
    float n = g_n;
    int j = j0 + tx;
    float ncs = out[OFF_NCS + j];
    float inv_smoothed = (n + (float)NEMB * 1e-5f) / ((ncs + 1e-5f) * n);
#pragma unroll
    for (int s = 0; s < 32; s += 8) {
        int d = d0 + ty + s;
        size_t o = (size_t)d * NEMB + j;
        float avg = fmaf(0.99f, eavg[o], t[tx][ty + s]);
        out[OFF_AVG + o] = avg;
        out[OFF_EMB + o] = avg * inv_smoothed;
    }
}

// ---------------------------------------------------------------------------
extern "C" void kernel_launch(void* const* d_in, const int* in_sizes, int n_in,
                              void* d_out, int out_size) {
    const float* z    = (const float*)d_in[0];   // [16,32,32,256]
    const float* E    = (const float*)d_in[1];   // [256, 8192]
    const float* cs   = (const float*)d_in[2];   // [8192]
    const float* eavg = (const float*)d_in[3];   // [256, 8192]
    float* out = (float*)d_out;

    static int cfg_done = 0;
    if (!cfg_done) {
        cudaFuncSetAttribute(k_argmin_mma,
                             cudaFuncAttributeMaxDynamicSharedMemorySize, SMEM_TOTAL);
        cfg_done = 1;
    }

    k_init_conv<<<NROWS * DIMS / 256, 256>>>(z, out);
    {
        dim3 g(NEMB / 32, DIMS / 32), b(32, 8);
        k_prep_e<<<g, b>>>(E);
    }
    k_argmin_mma<<<NROWS / 128, 512, SMEM_TOTAL>>>(z, out);
    k_ncs<<<NEMB / 256, 256>>>(cs, out);
    {
        dim3 g(NEMB / 32, DIMS / 32), b(32, 8);
        k_final<<<g, b>>>(eavg, out);
    }
}